// round 1
// baseline (speedup 1.0000x reference)
#include <cuda_runtime.h>
#include <math.h>

// ---------------- problem constants ----------------
#define D_EMBED 512
#define N_HEADS 8
#define D_HEADD 64
#define FF_DIM  2048
#define D_CROSS 768
#define BATCH   2
#define SEQ     4096
#define SKV_C   77
#define M_ROWS  (BATCH * SEQ)     // 8192
#define Y_ROWS  (BATCH * SKV_C)   // 154

// ---------------- scratch (static device globals; no allocation) ----------------
__device__ float g_qkv [M_ROWS * 3 * D_EMBED];   // 50 MB
__device__ float g_attn[M_ROWS * D_EMBED];
__device__ float g_proj[M_ROWS * D_EMBED];
__device__ float g_x1  [M_ROWS * D_EMBED];
__device__ float g_x2q [M_ROWS * D_EMBED];       // qc, then reused as x2
__device__ float g_kc  [Y_ROWS * D_EMBED];
__device__ float g_vc  [Y_ROWS * D_EMBED];
__device__ float g_ff  [M_ROWS * FF_DIM];        // 67 MB

__device__ __forceinline__ float gelu_tanh(float x) {
    float x3 = x * x * x;
    return 0.5f * x * (1.0f + tanhf(0.7978845608028654f * (x + 0.044715f * x3)));
}

// ---------------- SGEMM: C[M,N] = A[M,K] @ B[K,N] + bias (+GELU) ----------------
// 128x128 tile, BK=8, 256 threads, 8x8 micro-tile.
template<bool GELU>
__global__ void __launch_bounds__(256, 2)
sgemm_bias(const float* __restrict__ A, const float* __restrict__ B,
           const float* __restrict__ bias, float* __restrict__ C,
           int M, int N, int K)
{
    __shared__ float As[8][128];
    __shared__ float Bs[8][128];

    const int tid = threadIdx.x;
    const int m0 = blockIdx.y * 128;
    const int n0 = blockIdx.x * 128;
    const int tx = tid & 15;        // 0..15 -> N
    const int ty = tid >> 4;        // 0..15 -> M

    float acc[8][8];
#pragma unroll
    for (int i = 0; i < 8; i++)
#pragma unroll
        for (int j = 0; j < 8; j++) acc[i][j] = 0.0f;

    const int a_row = tid >> 1;          // 0..127
    const int a_col = (tid & 1) * 4;     // 0 or 4
    const int b_row = tid >> 5;          // 0..7
    const int b_col = (tid & 31) * 4;    // 0..124

    const bool a_valid = (m0 + a_row) < M;
    const float* Aptr = A + (long)(m0 + a_row) * K + a_col;
    const float* Bptr = B + (long)b_row * N + n0 + b_col;

    for (int k0 = 0; k0 < K; k0 += 8) {
        float4 av = a_valid ? *(const float4*)(Aptr + k0)
                            : make_float4(0.f, 0.f, 0.f, 0.f);
        As[a_col + 0][a_row] = av.x;
        As[a_col + 1][a_row] = av.y;
        As[a_col + 2][a_row] = av.z;
        As[a_col + 3][a_row] = av.w;
        *(float4*)&Bs[b_row][b_col] = *(const float4*)(Bptr + (long)k0 * N);
        __syncthreads();

#pragma unroll
        for (int k = 0; k < 8; k++) {
            float ra[8], rb[8];
            *(float4*)&ra[0] = *(const float4*)&As[k][ty * 8];
            *(float4*)&ra[4] = *(const float4*)&As[k][ty * 8 + 4];
            *(float4*)&rb[0] = *(const float4*)&Bs[k][tx * 8];
            *(float4*)&rb[4] = *(const float4*)&Bs[k][tx * 8 + 4];
#pragma unroll
            for (int i = 0; i < 8; i++)
#pragma unroll
                for (int j = 0; j < 8; j++)
                    acc[i][j] += ra[i] * rb[j];
        }
        __syncthreads();
    }

    // epilogue
    float bv[8];
#pragma unroll
    for (int j = 0; j < 8; j++) bv[j] = bias[n0 + tx * 8 + j];

#pragma unroll
    for (int i = 0; i < 8; i++) {
        int row = m0 + ty * 8 + i;
        if (row < M) {
            float out[8];
#pragma unroll
            for (int j = 0; j < 8; j++) {
                float c = acc[i][j] + bv[j];
                out[j] = GELU ? gelu_tanh(c) : c;
            }
            float* Cp = C + (long)row * N + n0 + tx * 8;
            *(float4*)&Cp[0] = *(float4*)&out[0];
            *(float4*)&Cp[4] = *(float4*)&out[4];
        }
    }
}

// ---------------- Flash attention (fp32, d=64) ----------------
// grid: (Sq/64, N_HEADS, BATCH); block: 128 threads (8x16).
// BM=64 queries, BN=64 keys. Per-thread: 8 query rows x 4 cols.
// Dynamic smem: Qs[64][68] (k-major), KP[64*68] (K k-major, reused as P row-major), Vs[64][68].
#define FLASH_SMEM (3 * 64 * 68 * 4)

__global__ void __launch_bounds__(128)
flash_attn(const float* __restrict__ Q, const float* __restrict__ K,
           const float* __restrict__ V, float* __restrict__ O,
           int ldq, long qbs, int ldk, long kbs, int ldv, long vbs,
           int Skv, float scale)
{
    extern __shared__ float sm[];
    float* Qs = sm;                 // Qs[k*68 + m]
    float* KP = sm + 64 * 68;       // Ks[k*68 + n]  /  Ps[r*68 + c]
    float* Vs = sm + 2 * 64 * 68;   // Vs[n*68 + d]

    const int tid = threadIdx.x;
    const int tx = tid & 15;   // 0..15 : key cols (x4) / d cols (x4)
    const int ty = tid >> 4;   // 0..7  : query rows (x8)
    const int h = blockIdx.y, b = blockIdx.z;
    const int m0 = blockIdx.x * 64;

    const float* q = Q + b * qbs + h * D_HEADD;
    const float* k = K + b * kbs + h * D_HEADD;
    const float* v = V + b * vbs + h * D_HEADD;

    // load Q tile transposed (scaled)
    {
        const int c4 = (tid & 15) * 4;
        const int r0 = tid >> 4;
#pragma unroll
        for (int rr = 0; rr < 64; rr += 8) {
            int r = r0 + rr;
            float4 qv = *(const float4*)(q + (long)(m0 + r) * ldq + c4);
            Qs[(c4 + 0) * 68 + r] = qv.x * scale;
            Qs[(c4 + 1) * 68 + r] = qv.y * scale;
            Qs[(c4 + 2) * 68 + r] = qv.z * scale;
            Qs[(c4 + 3) * 68 + r] = qv.w * scale;
        }
    }

    float m_i[8], l_i[8], o[8][4];
#pragma unroll
    for (int i = 0; i < 8; i++) {
        m_i[i] = -1e30f; l_i[i] = 0.0f;
#pragma unroll
        for (int j = 0; j < 4; j++) o[i][j] = 0.0f;
    }

    const int ntiles = (Skv + 63) >> 6;
    for (int t = 0; t < ntiles; t++) {
        const int n0 = t * 64;
        // load K (transposed) and V (natural) tiles
        {
            const int c4 = (tid & 15) * 4;
            const int r0 = tid >> 4;
#pragma unroll
            for (int rr = 0; rr < 64; rr += 8) {
                int r = r0 + rr;
                float4 kv4, vv4;
                if (n0 + r < Skv) {
                    kv4 = *(const float4*)(k + (long)(n0 + r) * ldk + c4);
                    vv4 = *(const float4*)(v + (long)(n0 + r) * ldv + c4);
                } else {
                    kv4 = make_float4(0.f, 0.f, 0.f, 0.f);
                    vv4 = kv4;
                }
                KP[(c4 + 0) * 68 + r] = kv4.x;
                KP[(c4 + 1) * 68 + r] = kv4.y;
                KP[(c4 + 2) * 68 + r] = kv4.z;
                KP[(c4 + 3) * 68 + r] = kv4.w;
                *(float4*)&Vs[r * 68 + c4] = vv4;
            }
        }
        __syncthreads();

        // scores: s[i][j] = sum_k Qs[k][ty*8+i] * Ks[k][tx*4+j]
        float s[8][4];
#pragma unroll
        for (int i = 0; i < 8; i++)
#pragma unroll
            for (int j = 0; j < 4; j++) s[i][j] = 0.0f;

#pragma unroll 4
        for (int kk = 0; kk < 64; kk++) {
            float qr[8], kr[4];
            *(float4*)&qr[0] = *(const float4*)&Qs[kk * 68 + ty * 8];
            *(float4*)&qr[4] = *(const float4*)&Qs[kk * 68 + ty * 8 + 4];
            *(float4*)&kr[0] = *(const float4*)&KP[kk * 68 + tx * 4];
#pragma unroll
            for (int i = 0; i < 8; i++)
#pragma unroll
                for (int j = 0; j < 4; j++)
                    s[i][j] += qr[i] * kr[j];
        }

        // mask invalid key columns (cross-attn tail)
        if (n0 + 64 > Skv) {
#pragma unroll
            for (int j = 0; j < 4; j++)
                if (n0 + tx * 4 + j >= Skv)
#pragma unroll
                    for (int i = 0; i < 8; i++) s[i][j] = -1e30f;
        }

        // online softmax stats + p (in regs)
        float p[8][4], alpha[8];
#pragma unroll
        for (int i = 0; i < 8; i++) {
            float mt = s[i][0];
#pragma unroll
            for (int j = 1; j < 4; j++) mt = fmaxf(mt, s[i][j]);
#pragma unroll
            for (int off = 8; off >= 1; off >>= 1)
                mt = fmaxf(mt, __shfl_xor_sync(0xffffffffu, mt, off, 16));
            float mnew = fmaxf(m_i[i], mt);
            alpha[i] = __expf(m_i[i] - mnew);
            m_i[i] = mnew;
            float sum = 0.0f;
#pragma unroll
            for (int j = 0; j < 4; j++) {
                p[i][j] = __expf(s[i][j] - mnew);
                sum += p[i][j];
            }
#pragma unroll
            for (int off = 8; off >= 1; off >>= 1)
                sum += __shfl_xor_sync(0xffffffffu, sum, off, 16);
            l_i[i] = l_i[i] * alpha[i] + sum;
#pragma unroll
            for (int j = 0; j < 4; j++) o[i][j] *= alpha[i];
        }

        __syncthreads();  // all done reading K before overwriting with P
#pragma unroll
        for (int i = 0; i < 8; i++)
            *(float4*)&KP[(ty * 8 + i) * 68 + tx * 4] = *(float4*)&p[i][0];
        __syncthreads();

        // O += P @ V
#pragma unroll 4
        for (int j = 0; j < 64; j++) {
            float4 vv = *(const float4*)&Vs[j * 68 + tx * 4];
#pragma unroll
            for (int i = 0; i < 8; i++) {
                float pij = KP[(ty * 8 + i) * 68 + j];
                o[i][0] += pij * vv.x;
                o[i][1] += pij * vv.y;
                o[i][2] += pij * vv.z;
                o[i][3] += pij * vv.w;
            }
        }
        __syncthreads();  // before next tile overwrites KP/Vs
    }

    // normalize + write (output layout: [B*SEQ, 512], head-concat)
#pragma unroll
    for (int i = 0; i < 8; i++) {
        float inv = 1.0f / l_i[i];
        float out4[4];
#pragma unroll
        for (int j = 0; j < 4; j++) out4[j] = o[i][j] * inv;
        long row = (long)b * SEQ + m0 + ty * 8 + i;
        *(float4*)(O + row * D_EMBED + h * D_HEADD + tx * 4) = *(float4*)&out4[0];
    }
}

// ---------------- fused residual add + LayerNorm (C = 512) ----------------
__global__ void __launch_bounds__(128)
add_ln(const float* __restrict__ A, const float* __restrict__ R,
       const float* __restrict__ g, const float* __restrict__ beta,
       float* __restrict__ out)
{
    const long row = blockIdx.x;
    const int tid = threadIdx.x;   // 128, each handles 4 floats
    const float4 a = *(const float4*)(A + row * D_EMBED + tid * 4);
    const float4 r = *(const float4*)(R + row * D_EMBED + tid * 4);
    float v[4] = {a.x + r.x, a.y + r.y, a.z + r.z, a.w + r.w};

    float s = v[0] + v[1] + v[2] + v[3];
    float ss = v[0]*v[0] + v[1]*v[1] + v[2]*v[2] + v[3]*v[3];
#pragma unroll
    for (int off = 16; off >= 1; off >>= 1) {
        s  += __shfl_xor_sync(0xffffffffu, s,  off);
        ss += __shfl_xor_sync(0xffffffffu, ss, off);
    }
    __shared__ float sred[8];
    const int warp = tid >> 5, lane = tid & 31;
    if (lane == 0) { sred[warp] = s; sred[warp + 4] = ss; }
    __syncthreads();
    s  = sred[0] + sred[1] + sred[2] + sred[3];
    ss = sred[4] + sred[5] + sred[6] + sred[7];

    const float mean = s * (1.0f / D_EMBED);
    const float var  = ss * (1.0f / D_EMBED) - mean * mean;
    const float rstd = rsqrtf(var + 1e-5f);

    const float4 gg = *(const float4*)(g + tid * 4);
    const float4 bb = *(const float4*)(beta + tid * 4);
    float4 o;
    o.x = (v[0] - mean) * rstd * gg.x + bb.x;
    o.y = (v[1] - mean) * rstd * gg.y + bb.y;
    o.z = (v[2] - mean) * rstd * gg.z + bb.z;
    o.w = (v[3] - mean) * rstd * gg.w + bb.w;
    *(float4*)(out + row * D_EMBED + tid * 4) = o;
}

// ---------------- host ----------------
extern "C" void kernel_launch(void* const* d_in, const int* in_sizes, int n_in,
                              void* d_out, int out_size)
{
    const float* x        = (const float*)d_in[0];
    const float* y        = (const float*)d_in[1];
    const float* sa_in_w  = (const float*)d_in[2];
    const float* sa_in_b  = (const float*)d_in[3];
    const float* sa_out_w = (const float*)d_in[4];
    const float* sa_out_b = (const float*)d_in[5];
    const float* ca_q_w   = (const float*)d_in[6];
    const float* ca_q_b   = (const float*)d_in[7];
    const float* ca_k_w   = (const float*)d_in[8];
    const float* ca_k_b   = (const float*)d_in[9];
    const float* ca_v_w   = (const float*)d_in[10];
    const float* ca_v_b   = (const float*)d_in[11];
    const float* ca_out_w = (const float*)d_in[12];
    const float* ca_out_b = (const float*)d_in[13];
    const float* ff_w1    = (const float*)d_in[14];
    const float* ff_b1    = (const float*)d_in[15];
    const float* ff_w2    = (const float*)d_in[16];
    const float* ff_b2    = (const float*)d_in[17];
    const float* ln1_g    = (const float*)d_in[18];
    const float* ln1_b    = (const float*)d_in[19];
    const float* ln2_g    = (const float*)d_in[20];
    const float* ln2_b    = (const float*)d_in[21];
    const float* ln3_g    = (const float*)d_in[22];
    const float* ln3_b    = (const float*)d_in[23];
    float* out = (float*)d_out;

    float *qkv, *attn, *proj, *x1, *x2q, *kc, *vc, *ff;
    cudaGetSymbolAddress((void**)&qkv,  g_qkv);
    cudaGetSymbolAddress((void**)&attn, g_attn);
    cudaGetSymbolAddress((void**)&proj, g_proj);
    cudaGetSymbolAddress((void**)&x1,   g_x1);
    cudaGetSymbolAddress((void**)&x2q,  g_x2q);
    cudaGetSymbolAddress((void**)&kc,   g_kc);
    cudaGetSymbolAddress((void**)&vc,   g_vc);
    cudaGetSymbolAddress((void**)&ff,   g_ff);

    cudaFuncSetAttribute(flash_attn, cudaFuncAttributeMaxDynamicSharedMemorySize, FLASH_SMEM);

    // 1. QKV projection: [8192,512] @ [512,1536]
    sgemm_bias<false><<<dim3(1536/128, M_ROWS/128), 256>>>(x, sa_in_w, sa_in_b, qkv,
                                                           M_ROWS, 3*D_EMBED, D_EMBED);
    // 2. self-attention (q|k|v packed in qkv, ld = 1536)
    flash_attn<<<dim3(SEQ/64, N_HEADS, BATCH), 128, FLASH_SMEM>>>(
        qkv, qkv + D_EMBED, qkv + 2*D_EMBED, attn,
        3*D_EMBED, (long)SEQ * 3*D_EMBED,
        3*D_EMBED, (long)SEQ * 3*D_EMBED,
        3*D_EMBED, (long)SEQ * 3*D_EMBED,
        SEQ, 0.125f);
    // 3. self-attn output projection
    sgemm_bias<false><<<dim3(4, M_ROWS/128), 256>>>(attn, sa_out_w, sa_out_b, proj,
                                                    M_ROWS, D_EMBED, D_EMBED);
    // 4. x1 = LN(x + proj)
    add_ln<<<M_ROWS, 128>>>(x, proj, ln1_g, ln1_b, x1);

    // 5. cross-attn Q projection
    sgemm_bias<false><<<dim3(4, M_ROWS/128), 256>>>(x1, ca_q_w, ca_q_b, x2q,
                                                    M_ROWS, D_EMBED, D_EMBED);
    // 6. cross-attn K/V projections from y [154,768]
    sgemm_bias<false><<<dim3(4, 2), 256>>>(y, ca_k_w, ca_k_b, kc, Y_ROWS, D_EMBED, D_CROSS);
    sgemm_bias<false><<<dim3(4, 2), 256>>>(y, ca_v_w, ca_v_b, vc, Y_ROWS, D_EMBED, D_CROSS);
    // 7. cross-attention (Skv = 77)
    flash_attn<<<dim3(SEQ/64, N_HEADS, BATCH), 128, FLASH_SMEM>>>(
        x2q, kc, vc, attn,
        D_EMBED, (long)SEQ * D_EMBED,
        D_EMBED, (long)SKV_C * D_EMBED,
        D_EMBED, (long)SKV_C * D_EMBED,
        SKV_C, 0.125f);
    // 8. cross-attn output projection
    sgemm_bias<false><<<dim3(4, M_ROWS/128), 256>>>(attn, ca_out_w, ca_out_b, proj,
                                                    M_ROWS, D_EMBED, D_EMBED);
    // 9. x2 = LN(x1 + proj)  (overwrite qc buffer; qc is dead now)
    add_ln<<<M_ROWS, 128>>>(x1, proj, ln2_g, ln2_b, x2q);

    // 10. FF1 + GELU: [8192,512] @ [512,2048]
    sgemm_bias<true><<<dim3(FF_DIM/128, M_ROWS/128), 256>>>(x2q, ff_w1, ff_b1, ff,
                                                            M_ROWS, FF_DIM, D_EMBED);
    // 11. FF2: [8192,2048] @ [2048,512]
    sgemm_bias<false><<<dim3(4, M_ROWS/128), 256>>>(ff, ff_w2, ff_b2, proj,
                                                    M_ROWS, D_EMBED, FF_DIM);
    // 12. out = LN(x2 + proj)
    add_ln<<<M_ROWS, 128>>>(x2q, proj, ln3_g, ln3_b, out);
}

// round 3
// speedup vs baseline: 1.0234x; 1.0234x over previous
#include <cuda_runtime.h>
#include <math.h>
#include <stdint.h>

// ---------------- problem constants ----------------
#define D_EMBED 512
#define N_HEADS 8
#define D_HEADD 64
#define FF_DIM  2048
#define D_CROSS 768
#define BATCH   2
#define SEQ     4096
#define SKV_C   77
#define M_ROWS  (BATCH * SEQ)     // 8192
#define Y_ROWS  (BATCH * SKV_C)   // 154

// ---------------- scratch ----------------
__device__ float g_qkv [M_ROWS * 3 * D_EMBED];
__device__ float g_attn[M_ROWS * D_EMBED];
__device__ float g_proj[M_ROWS * D_EMBED];
__device__ float g_x1  [M_ROWS * D_EMBED];
__device__ float g_x2q [M_ROWS * D_EMBED];
__device__ float g_kc  [Y_ROWS * D_EMBED];
__device__ float g_vc  [Y_ROWS * D_EMBED];
__device__ float g_ff  [M_ROWS * FF_DIM];

__device__ __forceinline__ float gelu_tanh(float x) {
    float x3 = x * x * x;
    return 0.5f * x * (1.0f + tanhf(0.7978845608028654f * (x + 0.044715f * x3)));
}

__device__ __forceinline__ float to_tf32(float x) {
    float r;
    asm("{\n\t.reg .b32 t;\n\tcvt.rna.tf32.f32 t, %1;\n\tmov.b32 %0, t;\n\t}"
        : "=f"(r) : "f"(x));
    return r;
}

// mma.sync m16n8k8 tf32: D += A*B  (fragments per PTX ISA; row.col)
__device__ __forceinline__ void mma8(float d[4], const uint32_t a[4], const uint32_t b[2]) {
    asm volatile(
        "mma.sync.aligned.m16n8k8.row.col.f32.tf32.tf32.f32 "
        "{%0,%1,%2,%3}, {%4,%5,%6,%7}, {%8,%9}, {%0,%1,%2,%3};\n"
        : "+f"(d[0]), "+f"(d[1]), "+f"(d[2]), "+f"(d[3])
        : "r"(a[0]), "r"(a[1]), "r"(a[2]), "r"(a[3]), "r"(b[0]), "r"(b[1]));
}

// ================= tf32 GEMM: C[M,N] = A[M,K]@B[K,N] + bias (+GELU) =================
// BM=128, BN=128, BK=16, 256 thr (8 warps in 2x4), warp tile 64x32 = 4x4 mma tiles.
// Requires M%128==0, N%128==0, K%16==0.
#define A_LD 20
#define B_LD 136

template<bool GELU>
__global__ void __launch_bounds__(256)
gemm_tf32(const float* __restrict__ A, const float* __restrict__ B,
          const float* __restrict__ bias, float* __restrict__ C,
          int M, int N, int K)
{
    __shared__ float As[128 * A_LD];
    __shared__ float Bs[16 * B_LD];
    const uint32_t* Asu = (const uint32_t*)As;
    const uint32_t* Bsu = (const uint32_t*)Bs;

    const int tid  = threadIdx.x;
    const int lane = tid & 31;
    const int warp = tid >> 5;
    const int wm = warp >> 2;          // 0..1
    const int wn = warp & 3;           // 0..3
    const int g   = lane >> 2;         // groupID 0..7
    const int tig = lane & 3;          // 0..3

    const int m0 = blockIdx.y * 128;
    const int n0 = blockIdx.x * 128;

    float acc[4][4][4];
#pragma unroll
    for (int i = 0; i < 4; i++)
#pragma unroll
        for (int j = 0; j < 4; j++)
#pragma unroll
            for (int r = 0; r < 4; r++) acc[i][j][r] = 0.0f;

    // staging mapping
    const int arow = tid >> 1;            // 0..127
    const int acol = (tid & 1) * 8;       // 0 or 8
    const int brow = tid >> 4;            // 0..15
    const int bcol = (tid & 15) * 8;      // 0..120

    const float* Ap = A + (long)(m0 + arow) * K + acol;
    const float* Bp = B + (long)brow * N + n0 + bcol;

    for (int k0 = 0; k0 < K; k0 += 16) {
        float4 a0 = *(const float4*)(Ap + k0);
        float4 a1 = *(const float4*)(Ap + k0 + 4);
        float4 b0 = *(const float4*)(Bp + (long)k0 * N);
        float4 b1 = *(const float4*)(Bp + (long)k0 * N + 4);
        __syncthreads();
        float* as = As + arow * A_LD + acol;
        as[0] = to_tf32(a0.x); as[1] = to_tf32(a0.y); as[2] = to_tf32(a0.z); as[3] = to_tf32(a0.w);
        as[4] = to_tf32(a1.x); as[5] = to_tf32(a1.y); as[6] = to_tf32(a1.z); as[7] = to_tf32(a1.w);
        float* bs = Bs + brow * B_LD + bcol;
        bs[0] = to_tf32(b0.x); bs[1] = to_tf32(b0.y); bs[2] = to_tf32(b0.z); bs[3] = to_tf32(b0.w);
        bs[4] = to_tf32(b1.x); bs[5] = to_tf32(b1.y); bs[6] = to_tf32(b1.z); bs[7] = to_tf32(b1.w);
        __syncthreads();

#pragma unroll
        for (int ks = 0; ks < 2; ks++) {
            const int kk = ks * 8;
            uint32_t bf[4][2];
#pragma unroll
            for (int nt = 0; nt < 4; nt++) {
                const int nc = wn * 32 + nt * 8 + g;
                bf[nt][0] = Bsu[(kk + tig)     * B_LD + nc];
                bf[nt][1] = Bsu[(kk + tig + 4) * B_LD + nc];
            }
#pragma unroll
            for (int mt = 0; mt < 4; mt++) {
                const int row = wm * 64 + mt * 16 + g;
                uint32_t af[4];
                af[0] = Asu[row       * A_LD + kk + tig];
                af[1] = Asu[(row + 8) * A_LD + kk + tig];
                af[2] = Asu[row       * A_LD + kk + tig + 4];
                af[3] = Asu[(row + 8) * A_LD + kk + tig + 4];
#pragma unroll
                for (int nt = 0; nt < 4; nt++)
                    mma8(acc[mt][nt], af, bf[nt]);
            }
        }
    }

    // epilogue
    const int cb = n0 + wn * 32;
    float2 bv[4];
#pragma unroll
    for (int nt = 0; nt < 4; nt++)
        bv[nt] = *(const float2*)&bias[cb + nt * 8 + 2 * tig];

#pragma unroll
    for (int mt = 0; mt < 4; mt++) {
        const long r1 = m0 + wm * 64 + mt * 16 + g;
        const long r2 = r1 + 8;
#pragma unroll
        for (int nt = 0; nt < 4; nt++) {
            float c0 = acc[mt][nt][0] + bv[nt].x;
            float c1 = acc[mt][nt][1] + bv[nt].y;
            float c2 = acc[mt][nt][2] + bv[nt].x;
            float c3 = acc[mt][nt][3] + bv[nt].y;
            if (GELU) { c0 = gelu_tanh(c0); c1 = gelu_tanh(c1); c2 = gelu_tanh(c2); c3 = gelu_tanh(c3); }
            *(float2*)&C[r1 * N + cb + nt * 8 + 2 * tig] = make_float2(c0, c1);
            *(float2*)&C[r2 * N + cb + nt * 8 + 2 * tig] = make_float2(c2, c3);
        }
    }
}

// ================= tf32 flash attention (d=64) =================
// BM=64 rows, BN=64 keys; 128 thr (4 warps); warp w owns rows [16w,16w+16).
// smem (floats): Qs[64*68] Ks[64*68] Ss[64*68] Vs[64*72] alpha[64]
#define QS_LD 68
#define VS_LD 72
#define FA_QS 0
#define FA_KS (64 * QS_LD)
#define FA_SS (2 * 64 * QS_LD)
#define FA_VS (3 * 64 * QS_LD)
#define FA_AL (FA_VS + 64 * VS_LD)
#define FA_FLOATS (FA_AL + 64)
#define FA_SMEM (FA_FLOATS * 4)

__global__ void __launch_bounds__(128)
flash_tf32(const float* __restrict__ Q, const float* __restrict__ K,
           const float* __restrict__ V, float* __restrict__ O,
           int ldq, long qbs, int ldk, long kbs, int ldv, long vbs,
           int Skv, float scale)
{
    extern __shared__ float sm[];
    float* Qs = sm + FA_QS;
    float* Ks = sm + FA_KS;
    float* Ss = sm + FA_SS;
    float* Vs = sm + FA_VS;
    float* Al = sm + FA_AL;
    const uint32_t* Qsu = (const uint32_t*)Qs;
    const uint32_t* Ksu = (const uint32_t*)Ks;
    const uint32_t* Ssu = (const uint32_t*)Ss;
    const uint32_t* Vsu = (const uint32_t*)Vs;

    const int tid  = threadIdx.x;
    const int lane = tid & 31;
    const int warp = tid >> 5;
    const int g    = lane >> 2;
    const int tig  = lane & 3;
    const int b = blockIdx.z, h = blockIdx.y;
    const int m0 = blockIdx.x * 64;

    const float* q = Q + b * qbs + h * D_HEADD;
    const float* k = K + b * kbs + h * D_HEADD;
    const float* v = V + b * vbs + h * D_HEADD;

    // stage Q (scaled, tf32): 2 threads/row, 32 cols each
    const int sr   = tid >> 1;
    const int half = tid & 1;
#pragma unroll
    for (int j = 0; j < 8; j++) {
        const int c = half * 32 + j * 4;
        float4 qv = *(const float4*)(q + (long)(m0 + sr) * ldq + c);
        float* d = Qs + sr * QS_LD + c;
        d[0] = to_tf32(qv.x * scale); d[1] = to_tf32(qv.y * scale);
        d[2] = to_tf32(qv.z * scale); d[3] = to_tf32(qv.w * scale);
    }

    float o[8][4];
#pragma unroll
    for (int nt = 0; nt < 8; nt++)
#pragma unroll
        for (int r = 0; r < 4; r++) o[nt][r] = 0.0f;
    float m_i = -1e30f, l_i = 0.0f;

    const int ntiles = (Skv + 63) >> 6;
    for (int t = 0; t < ntiles; t++) {
        const int n0t = t * 64;
        // stage K (tf32) + V (tf32)
#pragma unroll
        for (int j = 0; j < 8; j++) {
            const int c = half * 32 + j * 4;
            float4 kv4, vv4;
            if (n0t + sr < Skv) {
                kv4 = *(const float4*)(k + (long)(n0t + sr) * ldk + c);
                vv4 = *(const float4*)(v + (long)(n0t + sr) * ldv + c);
            } else {
                kv4 = make_float4(0.f, 0.f, 0.f, 0.f);
                vv4 = kv4;
            }
            float* dk = Ks + sr * QS_LD + c;
            dk[0] = to_tf32(kv4.x); dk[1] = to_tf32(kv4.y);
            dk[2] = to_tf32(kv4.z); dk[3] = to_tf32(kv4.w);
            float* dv = Vs + sr * VS_LD + c;
            dv[0] = to_tf32(vv4.x); dv[1] = to_tf32(vv4.y);
            dv[2] = to_tf32(vv4.z); dv[3] = to_tf32(vv4.w);
        }
        __syncthreads();

        // S = Q @ K^T  (per warp: 16 rows x 64 cols)
        float sfr[8][4];
#pragma unroll
        for (int nt = 0; nt < 8; nt++)
#pragma unroll
            for (int r = 0; r < 4; r++) sfr[nt][r] = 0.0f;

#pragma unroll
        for (int kk = 0; kk < 64; kk += 8) {
            const int row = warp * 16 + g;
            uint32_t af[4];
            af[0] = Qsu[row       * QS_LD + kk + tig];
            af[1] = Qsu[(row + 8) * QS_LD + kk + tig];
            af[2] = Qsu[row       * QS_LD + kk + tig + 4];
            af[3] = Qsu[(row + 8) * QS_LD + kk + tig + 4];
#pragma unroll
            for (int nt = 0; nt < 8; nt++) {
                uint32_t bf[2];
                bf[0] = Ksu[(nt * 8 + g) * QS_LD + kk + tig];
                bf[1] = Ksu[(nt * 8 + g) * QS_LD + kk + tig + 4];
                mma8(sfr[nt], af, bf);
            }
        }
        // write S to smem
        {
            const int r1 = warp * 16 + g, r2 = r1 + 8;
#pragma unroll
            for (int nt = 0; nt < 8; nt++) {
                *(float2*)&Ss[r1 * QS_LD + nt * 8 + 2 * tig] = make_float2(sfr[nt][0], sfr[nt][1]);
                *(float2*)&Ss[r2 * QS_LD + nt * 8 + 2 * tig] = make_float2(sfr[nt][2], sfr[nt][3]);
            }
        }
        __syncthreads();

        // online softmax: 2 threads per row (sr, half)
        {
            const bool tail = (n0t + 64 > Skv);
            float mx = -1e30f;
#pragma unroll
            for (int j = 0; j < 8; j++) {
                const int c = half * 32 + j * 4;
                float4 s4 = *(const float4*)&Ss[sr * QS_LD + c];
                float e0 = s4.x, e1 = s4.y, e2 = s4.z, e3 = s4.w;
                if (tail) {
                    if (n0t + c + 0 >= Skv) e0 = -1e30f;
                    if (n0t + c + 1 >= Skv) e1 = -1e30f;
                    if (n0t + c + 2 >= Skv) e2 = -1e30f;
                    if (n0t + c + 3 >= Skv) e3 = -1e30f;
                }
                mx = fmaxf(mx, fmaxf(fmaxf(e0, e1), fmaxf(e2, e3)));
            }
            mx = fmaxf(mx, __shfl_xor_sync(0xffffffffu, mx, 1));
            const float mnew = fmaxf(m_i, mx);
            const float al = __expf(m_i - mnew);
            m_i = mnew;
            float sum = 0.0f;
#pragma unroll
            for (int j = 0; j < 8; j++) {
                const int c = half * 32 + j * 4;
                float* sp = &Ss[sr * QS_LD + c];
                float4 s4 = *(const float4*)sp;
                float p0, p1, p2, p3;
                if (tail) {
                    p0 = (n0t + c + 0 >= Skv) ? 0.f : __expf(s4.x - mnew);
                    p1 = (n0t + c + 1 >= Skv) ? 0.f : __expf(s4.y - mnew);
                    p2 = (n0t + c + 2 >= Skv) ? 0.f : __expf(s4.z - mnew);
                    p3 = (n0t + c + 3 >= Skv) ? 0.f : __expf(s4.w - mnew);
                } else {
                    p0 = __expf(s4.x - mnew); p1 = __expf(s4.y - mnew);
                    p2 = __expf(s4.z - mnew); p3 = __expf(s4.w - mnew);
                }
                sum += p0 + p1 + p2 + p3;
                sp[0] = to_tf32(p0); sp[1] = to_tf32(p1);
                sp[2] = to_tf32(p2); sp[3] = to_tf32(p3);
            }
            sum += __shfl_xor_sync(0xffffffffu, sum, 1);
            l_i = l_i * al + sum;
            if (!half) Al[sr] = al;
        }
        __syncthreads();

        // rescale O, then O += P @ V
        {
            const float a1 = Al[warp * 16 + g];
            const float a2 = Al[warp * 16 + g + 8];
#pragma unroll
            for (int nt = 0; nt < 8; nt++) {
                o[nt][0] *= a1; o[nt][1] *= a1;
                o[nt][2] *= a2; o[nt][3] *= a2;
            }
        }
#pragma unroll
        for (int kk = 0; kk < 64; kk += 8) {
            const int row = warp * 16 + g;
            uint32_t af[4];
            af[0] = Ssu[row       * QS_LD + kk + tig];
            af[1] = Ssu[(row + 8) * QS_LD + kk + tig];
            af[2] = Ssu[row       * QS_LD + kk + tig + 4];
            af[3] = Ssu[(row + 8) * QS_LD + kk + tig + 4];
#pragma unroll
            for (int nt = 0; nt < 8; nt++) {
                uint32_t bf[2];
                bf[0] = Vsu[(kk + tig)     * VS_LD + nt * 8 + g];
                bf[1] = Vsu[(kk + tig + 4) * VS_LD + nt * 8 + g];
                mma8(o[nt], af, bf);
            }
        }
        __syncthreads();
    }

    // epilogue: normalize and write
    if (!half) Al[sr] = 1.0f / l_i;
    __syncthreads();
    const float i1 = Al[warp * 16 + g];
    const float i2 = Al[warp * 16 + g + 8];
    const long r1 = (long)b * SEQ + m0 + warp * 16 + g;
    const long r2 = r1 + 8;
#pragma unroll
    for (int nt = 0; nt < 8; nt++) {
        const int col = h * D_HEADD + nt * 8 + 2 * tig;
        *(float2*)&O[r1 * D_EMBED + col] = make_float2(o[nt][0] * i1, o[nt][1] * i1);
        *(float2*)&O[r2 * D_EMBED + col] = make_float2(o[nt][2] * i2, o[nt][3] * i2);
    }
}

// ================= fp32 SGEMM (small M fallback) =================
template<bool GELU>
__global__ void __launch_bounds__(256, 2)
sgemm_bias(const float* __restrict__ A, const float* __restrict__ B,
           const float* __restrict__ bias, float* __restrict__ C,
           int M, int N, int K)
{
    __shared__ float As[8][128];
    __shared__ float Bs[8][128];
    const int tid = threadIdx.x;
    const int m0 = blockIdx.y * 128;
    const int n0 = blockIdx.x * 128;
    const int tx = tid & 15;
    const int ty = tid >> 4;

    float acc[8][8];
#pragma unroll
    for (int i = 0; i < 8; i++)
#pragma unroll
        for (int j = 0; j < 8; j++) acc[i][j] = 0.0f;

    const int a_row = tid >> 1;
    const int a_col = (tid & 1) * 4;
    const int b_row = tid >> 5;
    const int b_col = (tid & 31) * 4;
    const bool a_valid = (m0 + a_row) < M;
    const float* Aptr = A + (long)(m0 + a_row) * K + a_col;
    const float* Bptr = B + (long)b_row * N + n0 + b_col;

    for (int k0 = 0; k0 < K; k0 += 8) {
        float4 av = a_valid ? *(const float4*)(Aptr + k0) : make_float4(0.f, 0.f, 0.f, 0.f);
        As[a_col + 0][a_row] = av.x;
        As[a_col + 1][a_row] = av.y;
        As[a_col + 2][a_row] = av.z;
        As[a_col + 3][a_row] = av.w;
        *(float4*)&Bs[b_row][b_col] = *(const float4*)(Bptr + (long)k0 * N);
        __syncthreads();
#pragma unroll
        for (int kk = 0; kk < 8; kk++) {
            float ra[8], rb[8];
            *(float4*)&ra[0] = *(const float4*)&As[kk][ty * 8];
            *(float4*)&ra[4] = *(const float4*)&As[kk][ty * 8 + 4];
            *(float4*)&rb[0] = *(const float4*)&Bs[kk][tx * 8];
            *(float4*)&rb[4] = *(const float4*)&Bs[kk][tx * 8 + 4];
#pragma unroll
            for (int i = 0; i < 8; i++)
#pragma unroll
                for (int j = 0; j < 8; j++)
                    acc[i][j] += ra[i] * rb[j];
        }
        __syncthreads();
    }
    float bvv[8];
#pragma unroll
    for (int j = 0; j < 8; j++) bvv[j] = bias[n0 + tx * 8 + j];
#pragma unroll
    for (int i = 0; i < 8; i++) {
        int row = m0 + ty * 8 + i;
        if (row < M) {
            float outv[8];
#pragma unroll
            for (int j = 0; j < 8; j++) {
                float c = acc[i][j] + bvv[j];
                outv[j] = GELU ? gelu_tanh(c) : c;
            }
            float* Cp = C + (long)row * N + n0 + tx * 8;
            *(float4*)&Cp[0] = *(float4*)&outv[0];
            *(float4*)&Cp[4] = *(float4*)&outv[4];
        }
    }
}

// ================= fused residual add + LayerNorm =================
__global__ void __launch_bounds__(128)
add_ln(const float* __restrict__ A, const float* __restrict__ R,
       const float* __restrict__ g, const float* __restrict__ beta,
       float* __restrict__ out)
{
    const long row = blockIdx.x;
    const int tid = threadIdx.x;
    const float4 a = *(const float4*)(A + row * D_EMBED + tid * 4);
    const float4 r = *(const float4*)(R + row * D_EMBED + tid * 4);
    float v[4] = {a.x + r.x, a.y + r.y, a.z + r.z, a.w + r.w};

    float s = v[0] + v[1] + v[2] + v[3];
    float ss = v[0]*v[0] + v[1]*v[1] + v[2]*v[2] + v[3]*v[3];
#pragma unroll
    for (int off = 16; off >= 1; off >>= 1) {
        s  += __shfl_xor_sync(0xffffffffu, s,  off);
        ss += __shfl_xor_sync(0xffffffffu, ss, off);
    }
    __shared__ float sred[8];
    const int warp = tid >> 5, lane = tid & 31;
    if (lane == 0) { sred[warp] = s; sred[warp + 4] = ss; }
    __syncthreads();
    s  = sred[0] + sred[1] + sred[2] + sred[3];
    ss = sred[4] + sred[5] + sred[6] + sred[7];

    const float mean = s * (1.0f / D_EMBED);
    const float var  = ss * (1.0f / D_EMBED) - mean * mean;
    const float rstd = rsqrtf(var + 1e-5f);

    const float4 gg = *(const float4*)(g + tid * 4);
    const float4 bb = *(const float4*)(beta + tid * 4);
    float4 o;
    o.x = (v[0] - mean) * rstd * gg.x + bb.x;
    o.y = (v[1] - mean) * rstd * gg.y + bb.y;
    o.z = (v[2] - mean) * rstd * gg.z + bb.z;
    o.w = (v[3] - mean) * rstd * gg.w + bb.w;
    *(float4*)(out + row * D_EMBED + tid * 4) = o;
}

// ================= host =================
extern "C" void kernel_launch(void* const* d_in, const int* in_sizes, int n_in,
                              void* d_out, int out_size)
{
    const float* x        = (const float*)d_in[0];
    const float* y        = (const float*)d_in[1];
    const float* sa_in_w  = (const float*)d_in[2];
    const float* sa_in_b  = (const float*)d_in[3];
    const float* sa_out_w = (const float*)d_in[4];
    const float* sa_out_b = (const float*)d_in[5];
    const float* ca_q_w   = (const float*)d_in[6];
    const float* ca_q_b   = (const float*)d_in[7];
    const float* ca_k_w   = (const float*)d_in[8];
    const float* ca_k_b   = (const float*)d_in[9];
    const float* ca_v_w   = (const float*)d_in[10];
    const float* ca_v_b   = (const float*)d_in[11];
    const float* ca_out_w = (const float*)d_in[12];
    const float* ca_out_b = (const float*)d_in[13];
    const float* ff_w1    = (const float*)d_in[14];
    const float* ff_b1    = (const float*)d_in[15];
    const float* ff_w2    = (const float*)d_in[16];
    const float* ff_b2    = (const float*)d_in[17];
    const float* ln1_g    = (const float*)d_in[18];
    const float* ln1_b    = (const float*)d_in[19];
    const float* ln2_g    = (const float*)d_in[20];
    const float* ln2_b    = (const float*)d_in[21];
    const float* ln3_g    = (const float*)d_in[22];
    const float* ln3_b    = (const float*)d_in[23];
    float* out = (float*)d_out;

    float *qkv, *attn, *proj, *x1, *x2q, *kc, *vc, *ff;
    cudaGetSymbolAddress((void**)&qkv,  g_qkv);
    cudaGetSymbolAddress((void**)&attn, g_attn);
    cudaGetSymbolAddress((void**)&proj, g_proj);
    cudaGetSymbolAddress((void**)&x1,   g_x1);
    cudaGetSymbolAddress((void**)&x2q,  g_x2q);
    cudaGetSymbolAddress((void**)&kc,   g_kc);
    cudaGetSymbolAddress((void**)&vc,   g_vc);
    cudaGetSymbolAddress((void**)&ff,   g_ff);

    cudaFuncSetAttribute(flash_tf32, cudaFuncAttributeMaxDynamicSharedMemorySize, FA_SMEM);

    // 1. QKV projection: [8192,512] @ [512,1536]
    gemm_tf32<false><<<dim3(1536/128, M_ROWS/128), 256>>>(x, sa_in_w, sa_in_b, qkv,
                                                          M_ROWS, 3*D_EMBED, D_EMBED);
    // 2. self-attention
    flash_tf32<<<dim3(SEQ/64, N_HEADS, BATCH), 128, FA_SMEM>>>(
        qkv, qkv + D_EMBED, qkv + 2*D_EMBED, attn,
        3*D_EMBED, (long)SEQ * 3*D_EMBED,
        3*D_EMBED, (long)SEQ * 3*D_EMBED,
        3*D_EMBED, (long)SEQ * 3*D_EMBED,
        SEQ, 0.125f);
    // 3. self-attn output projection
    gemm_tf32<false><<<dim3(4, M_ROWS/128), 256>>>(attn, sa_out_w, sa_out_b, proj,
                                                   M_ROWS, D_EMBED, D_EMBED);
    // 4. x1 = LN(x + proj)
    add_ln<<<M_ROWS, 128>>>(x, proj, ln1_g, ln1_b, x1);

    // 5. cross-attn Q projection
    gemm_tf32<false><<<dim3(4, M_ROWS/128), 256>>>(x1, ca_q_w, ca_q_b, x2q,
                                                   M_ROWS, D_EMBED, D_EMBED);
    // 6. cross-attn K/V projections (tiny M; fp32 path)
    sgemm_bias<false><<<dim3(4, 2), 256>>>(y, ca_k_w, ca_k_b, kc, Y_ROWS, D_EMBED, D_CROSS);
    sgemm_bias<false><<<dim3(4, 2), 256>>>(y, ca_v_w, ca_v_b, vc, Y_ROWS, D_EMBED, D_CROSS);
    // 7. cross-attention (Skv = 77)
    flash_tf32<<<dim3(SEQ/64, N_HEADS, BATCH), 128, FA_SMEM>>>(
        x2q, kc, vc, attn,
        D_EMBED, (long)SEQ * D_EMBED,
        D_EMBED, (long)SKV_C * D_EMBED,
        D_EMBED, (long)SKV_C * D_EMBED,
        SKV_C, 0.125f);
    // 8. cross-attn output projection
    gemm_tf32<false><<<dim3(4, M_ROWS/128), 256>>>(attn, ca_out_w, ca_out_b, proj,
                                                   M_ROWS, D_EMBED, D_EMBED);
    // 9. x2 = LN(x1 + proj)
    add_ln<<<M_ROWS, 128>>>(x1, proj, ln2_g, ln2_b, x2q);

    // 10. FF1 + GELU
    gemm_tf32<true><<<dim3(FF_DIM/128, M_ROWS/128), 256>>>(x2q, ff_w1, ff_b1, ff,
                                                           M_ROWS, FF_DIM, D_EMBED);
    // 11. FF2
    gemm_tf32<false><<<dim3(4, M_ROWS/128), 256>>>(ff, ff_w2, ff_b2, proj,
                                                   M_ROWS, D_EMBED, FF_DIM);
    // 12. out = LN(x2 + proj)
    add_ln<<<M_ROWS, 128>>>(x2q, proj, ln3_g, ln3_b, out);
}

// round 7
// speedup vs baseline: 1.9710x; 1.9259x over previous
#include <cuda_runtime.h>
#include <cuda_fp16.h>
#include <math.h>
#include <stdint.h>

// ---------------- problem constants ----------------
#define D_EMBED 512
#define N_HEADS 8
#define D_HEADD 64
#define FF_DIM  2048
#define D_CROSS 768
#define BATCH   2
#define SEQ     4096
#define SKV_C   77
#define M_ROWS  (BATCH * SEQ)     // 8192
#define Y_ROWS  (BATCH * SKV_C)   // 154

// ---------------- scratch ----------------
__device__ float g_qkv [M_ROWS * 3 * D_EMBED];
__device__ float g_attn[M_ROWS * D_EMBED];
__device__ float g_proj[M_ROWS * D_EMBED];
__device__ float g_x1  [M_ROWS * D_EMBED];
__device__ float g_x2q [M_ROWS * D_EMBED];
__device__ float g_kc  [Y_ROWS * D_EMBED];
__device__ float g_vc  [Y_ROWS * D_EMBED];
__device__ float g_ff  [M_ROWS * FF_DIM];

// transposed fp16 weights [N,K]
#define WOFF_SAIN  0
#define WOFF_SAOUT 786432
#define WOFF_CAQ   1048576
#define WOFF_CAOUT 1310720
#define WOFF_FF1   1572864
#define WOFF_FF2   2621440
#define WT_TOTAL   3670016
__device__ __half g_w16[WT_TOTAL];

__device__ __forceinline__ float gelu_tanh(float x) {
    float x3 = x * x * x;
    return 0.5f * x * (1.0f + tanhf(0.7978845608028654f * (x + 0.044715f * x3)));
}

__device__ __forceinline__ uint32_t pack2h(float a, float b) {
    __half2 h = __floats2half2_rn(a, b);
    return *(uint32_t*)&h;
}

// fp16 mma m16n8k16, fp32 accum
__device__ __forceinline__ void mma16(float d[4], const uint32_t a[4], const uint32_t b[2]) {
    asm volatile(
        "mma.sync.aligned.m16n8k16.row.col.f32.f16.f16.f32 "
        "{%0,%1,%2,%3}, {%4,%5,%6,%7}, {%8,%9}, {%0,%1,%2,%3};\n"
        : "+f"(d[0]), "+f"(d[1]), "+f"(d[2]), "+f"(d[3])
        : "r"(a[0]), "r"(a[1]), "r"(a[2]), "r"(a[3]), "r"(b[0]), "r"(b[1]));
}

// ================= weight transpose to fp16: W[K,N] -> Wt[N,K] =================
__global__ void __launch_bounds__(256)
transpose_h(const float* __restrict__ W, __half* __restrict__ Wt, int K, int N)
{
    __shared__ float t[32][33];
    const int n0 = blockIdx.x * 32, k0 = blockIdx.y * 32;
    const int tx = threadIdx.x & 31, ty = threadIdx.x >> 5;  // 32 x 8
#pragma unroll
    for (int j = 0; j < 32; j += 8)
        t[ty + j][tx] = W[(long)(k0 + ty + j) * N + n0 + tx];
    __syncthreads();
#pragma unroll
    for (int j = 0; j < 32; j += 8)
        Wt[(long)(n0 + ty + j) * K + k0 + tx] = __float2half_rn(t[tx][ty + j]);
}

// ================= fp16-mma GEMM: C[M,N] = A[M,K] @ Wt[N,K]^T + bias (+GELU) ======
// BM=128, BN=128, BK=32; 256 thr (8 warps 2x4); warp tile 64x32; 4x4 mma tiles,
// 2 k-steps of k16 per BK. Smem stored as half2-packed uint32, LD2=20 (conflict-free).
#define GA_LD2 20

template<bool GELU>
__global__ void __launch_bounds__(256)
gemm_h(const float* __restrict__ A, const __half* __restrict__ Wt,
       const float* __restrict__ bias, float* __restrict__ C,
       int M, int N, int K)
{
    __shared__ uint32_t As2[128 * GA_LD2];
    __shared__ uint32_t Bs2[128 * GA_LD2];

    const int tid  = threadIdx.x;
    const int lane = tid & 31;
    const int warp = tid >> 5;
    const int wm = warp >> 2;          // 0..1
    const int wn = warp & 3;           // 0..3
    const int g   = lane >> 2;         // 0..7
    const int tig = lane & 3;          // 0..3

    const int m0 = blockIdx.y * 128;
    const int n0 = blockIdx.x * 128;

    float acc[4][4][4];
#pragma unroll
    for (int i = 0; i < 4; i++)
#pragma unroll
        for (int j = 0; j < 4; j++)
#pragma unroll
            for (int r = 0; r < 4; r++) acc[i][j][r] = 0.0f;

    // staging: 2 threads per row, 16 cols each
    const int arow = tid >> 1, ahalf = tid & 1;
    const float* Ap = A + (long)(m0 + arow) * K + ahalf * 16;
    const __half* Bp = Wt + (long)(n0 + arow) * K + ahalf * 16;

    float4 ar[4];
    uint4  br[2];
#pragma unroll
    for (int j = 0; j < 4; j++) ar[j] = *(const float4*)(Ap + j * 4);
#pragma unroll
    for (int j = 0; j < 2; j++) br[j] = *(const uint4*)(Bp + j * 8);

    const int NIT = K >> 5;
    for (int it = 0; it < NIT; it++) {
        __syncthreads();
        // store A as half2
#pragma unroll
        for (int j = 0; j < 4; j++) {
            float4 v = ar[j];
            *(uint2*)&As2[arow * GA_LD2 + ahalf * 8 + 2 * j] =
                make_uint2(pack2h(v.x, v.y), pack2h(v.z, v.w));
        }
        // store B (already half)
#pragma unroll
        for (int j = 0; j < 2; j++)
            *(uint4*)&Bs2[arow * GA_LD2 + ahalf * 8 + 4 * j] = br[j];
        __syncthreads();

        if (it + 1 < NIT) {
            const int k0 = (it + 1) * 32;
#pragma unroll
            for (int j = 0; j < 4; j++) ar[j] = *(const float4*)(Ap + k0 + j * 4);
#pragma unroll
            for (int j = 0; j < 2; j++) br[j] = *(const uint4*)(Bp + k0 + j * 8);
        }

#pragma unroll
        for (int ks = 0; ks < 2; ks++) {
            const int kk2 = ks * 8;
            uint32_t bf[4][2];
#pragma unroll
            for (int nt = 0; nt < 4; nt++) {
                const int nc = wn * 32 + nt * 8 + g;
                bf[nt][0] = Bs2[nc * GA_LD2 + kk2 + tig];
                bf[nt][1] = Bs2[nc * GA_LD2 + kk2 + tig + 4];
            }
#pragma unroll
            for (int mt = 0; mt < 4; mt++) {
                const int row = wm * 64 + mt * 16 + g;
                uint32_t af[4];
                af[0] = As2[row       * GA_LD2 + kk2 + tig];
                af[1] = As2[(row + 8) * GA_LD2 + kk2 + tig];
                af[2] = As2[row       * GA_LD2 + kk2 + tig + 4];
                af[3] = As2[(row + 8) * GA_LD2 + kk2 + tig + 4];
#pragma unroll
                for (int nt = 0; nt < 4; nt++)
                    mma16(acc[mt][nt], af, bf[nt]);
            }
        }
    }

    // epilogue (m16n8 C layout: c0,c1 = row g cols 2tig,2tig+1; c2,c3 = row g+8)
    const int cb = n0 + wn * 32;
    float2 bv[4];
#pragma unroll
    for (int nt = 0; nt < 4; nt++)
        bv[nt] = *(const float2*)&bias[cb + nt * 8 + 2 * tig];

#pragma unroll
    for (int mt = 0; mt < 4; mt++) {
        const long r1 = m0 + wm * 64 + mt * 16 + g;
        const long r2 = r1 + 8;
#pragma unroll
        for (int nt = 0; nt < 4; nt++) {
            float c0 = acc[mt][nt][0] + bv[nt].x;
            float c1 = acc[mt][nt][1] + bv[nt].y;
            float c2 = acc[mt][nt][2] + bv[nt].x;
            float c3 = acc[mt][nt][3] + bv[nt].y;
            if (GELU) { c0 = gelu_tanh(c0); c1 = gelu_tanh(c1); c2 = gelu_tanh(c2); c3 = gelu_tanh(c3); }
            *(float2*)&C[r1 * N + cb + nt * 8 + 2 * tig] = make_float2(c0, c1);
            *(float2*)&C[r2 * N + cb + nt * 8 + 2 * tig] = make_float2(c2, c3);
        }
    }
}

// ================= fp16-mma flash attention (d=64) =================
// BM=64 rows, BN=64 keys; 128 thr (4 warps); warp w owns rows [16w,16w+16).
// smem layout (uint32 units):
//   QS2[64][36], KS2[64][36], VT2[64 d][36 key2], SF float[64][68], PS2[64][36], AL[64]
#define FH_LD2 36
#define FH_QS 0
#define FH_KS (64 * FH_LD2)
#define FH_VT (2 * 64 * FH_LD2)
#define FH_SF (3 * 64 * FH_LD2)
#define FH_PS (FH_SF + 64 * 68)
#define FH_AL (FH_PS + 64 * FH_LD2)
#define FH_U32 (FH_AL + 64)
#define FH_SMEM (FH_U32 * 4)

__global__ void __launch_bounds__(128)
flash_h(const float* __restrict__ Q, const float* __restrict__ K,
        const float* __restrict__ V, float* __restrict__ O,
        int ldq, long qbs, int ldk, long kbs, int ldv, long vbs,
        int Skv, float scale)
{
    extern __shared__ uint32_t su[];
    uint32_t* Qs2 = su + FH_QS;
    uint32_t* Ks2 = su + FH_KS;
    uint32_t* Vt2 = su + FH_VT;
    float*    Sf  = (float*)(su + FH_SF);
    uint32_t* Ps2 = su + FH_PS;
    float*    Al  = (float*)(su + FH_AL);
    __half*   VtH = (__half*)Vt2;          // [d][72 halves]

    const int tid  = threadIdx.x;
    const int lane = tid & 31;
    const int warp = tid >> 5;
    const int g    = lane >> 2;
    const int tig  = lane & 3;
    const int b = blockIdx.z, h = blockIdx.y;
    const int m0 = blockIdx.x * 64;

    const float* q = Q + b * qbs + h * D_HEADD;
    const float* k = K + b * kbs + h * D_HEADD;
    const float* v = V + b * vbs + h * D_HEADD;

    const int sr   = tid >> 1;   // 0..63
    const int half = tid & 1;

    // stage Q (scaled, fp16)
#pragma unroll
    for (int j = 0; j < 8; j++) {
        const int c = half * 32 + j * 4;
        float4 qv = *(const float4*)(q + (long)(m0 + sr) * ldq + c);
        *(uint2*)&Qs2[sr * FH_LD2 + c / 2] =
            make_uint2(pack2h(qv.x * scale, qv.y * scale), pack2h(qv.z * scale, qv.w * scale));
    }

    float o[8][4];
#pragma unroll
    for (int nt = 0; nt < 8; nt++)
#pragma unroll
        for (int r = 0; r < 4; r++) o[nt][r] = 0.0f;
    float m_i = -1e30f, l_i = 0.0f;

    const int ntiles = (Skv + 63) >> 6;
    for (int t = 0; t < ntiles; t++) {
        const int n0t = t * 64;
        // stage K (fp16, [key][d]) and V transposed (fp16, [d][key])
#pragma unroll
        for (int j = 0; j < 8; j++) {
            const int c = half * 32 + j * 4;
            float4 kv4, vv4;
            if (n0t + sr < Skv) {
                kv4 = *(const float4*)(k + (long)(n0t + sr) * ldk + c);
                vv4 = *(const float4*)(v + (long)(n0t + sr) * ldv + c);
            } else {
                kv4 = make_float4(0.f, 0.f, 0.f, 0.f);
                vv4 = kv4;
            }
            *(uint2*)&Ks2[sr * FH_LD2 + c / 2] =
                make_uint2(pack2h(kv4.x, kv4.y), pack2h(kv4.z, kv4.w));
            VtH[(c + 0) * 72 + sr] = __float2half_rn(vv4.x);
            VtH[(c + 1) * 72 + sr] = __float2half_rn(vv4.y);
            VtH[(c + 2) * 72 + sr] = __float2half_rn(vv4.z);
            VtH[(c + 3) * 72 + sr] = __float2half_rn(vv4.w);
        }
        __syncthreads();

        // S = Q @ K^T : per warp 16 rows x 64 cols, 4 k-steps of 16
        float sfr[8][4];
#pragma unroll
        for (int nt = 0; nt < 8; nt++)
#pragma unroll
            for (int r = 0; r < 4; r++) sfr[nt][r] = 0.0f;

#pragma unroll
        for (int ks = 0; ks < 4; ks++) {
            const int kk2 = ks * 8;
            const int row = warp * 16 + g;
            uint32_t af[4];
            af[0] = Qs2[row       * FH_LD2 + kk2 + tig];
            af[1] = Qs2[(row + 8) * FH_LD2 + kk2 + tig];
            af[2] = Qs2[row       * FH_LD2 + kk2 + tig + 4];
            af[3] = Qs2[(row + 8) * FH_LD2 + kk2 + tig + 4];
#pragma unroll
            for (int nt = 0; nt < 8; nt++) {
                uint32_t bf[2];
                bf[0] = Ks2[(nt * 8 + g) * FH_LD2 + kk2 + tig];
                bf[1] = Ks2[(nt * 8 + g) * FH_LD2 + kk2 + tig + 4];
                mma16(sfr[nt], af, bf);
            }
        }
        // write S (fp32) to smem
        {
            const int r1 = warp * 16 + g, r2 = r1 + 8;
#pragma unroll
            for (int nt = 0; nt < 8; nt++) {
                *(float2*)&Sf[r1 * 68 + nt * 8 + 2 * tig] = make_float2(sfr[nt][0], sfr[nt][1]);
                *(float2*)&Sf[r2 * 68 + nt * 8 + 2 * tig] = make_float2(sfr[nt][2], sfr[nt][3]);
            }
        }
        __syncthreads();

        // online softmax: 2 threads per row; writes P (fp16) to Ps2
        {
            const bool tail = (n0t + 64 > Skv);
            float mx = -1e30f;
#pragma unroll
            for (int j = 0; j < 8; j++) {
                const int c = half * 32 + j * 4;
                float4 s4 = *(const float4*)&Sf[sr * 68 + c];
                float e0 = s4.x, e1 = s4.y, e2 = s4.z, e3 = s4.w;
                if (tail) {
                    if (n0t + c + 0 >= Skv) e0 = -1e30f;
                    if (n0t + c + 1 >= Skv) e1 = -1e30f;
                    if (n0t + c + 2 >= Skv) e2 = -1e30f;
                    if (n0t + c + 3 >= Skv) e3 = -1e30f;
                }
                mx = fmaxf(mx, fmaxf(fmaxf(e0, e1), fmaxf(e2, e3)));
            }
            mx = fmaxf(mx, __shfl_xor_sync(0xffffffffu, mx, 1));
            const float mnew = fmaxf(m_i, mx);
            const float al = __expf(m_i - mnew);
            m_i = mnew;
            float sum = 0.0f;
#pragma unroll
            for (int j = 0; j < 8; j++) {
                const int c = half * 32 + j * 4;
                float4 s4 = *(const float4*)&Sf[sr * 68 + c];
                float p0, p1, p2, p3;
                if (tail) {
                    p0 = (n0t + c + 0 >= Skv) ? 0.f : __expf(s4.x - mnew);
                    p1 = (n0t + c + 1 >= Skv) ? 0.f : __expf(s4.y - mnew);
                    p2 = (n0t + c + 2 >= Skv) ? 0.f : __expf(s4.z - mnew);
                    p3 = (n0t + c + 3 >= Skv) ? 0.f : __expf(s4.w - mnew);
                } else {
                    p0 = __expf(s4.x - mnew); p1 = __expf(s4.y - mnew);
                    p2 = __expf(s4.z - mnew); p3 = __expf(s4.w - mnew);
                }
                sum += p0 + p1 + p2 + p3;
                *(uint2*)&Ps2[sr * FH_LD2 + c / 2] =
                    make_uint2(pack2h(p0, p1), pack2h(p2, p3));
            }
            sum += __shfl_xor_sync(0xffffffffu, sum, 1);
            l_i = l_i * al + sum;
            if (!half) Al[sr] = al;
        }
        __syncthreads();

        // rescale O, then O += P @ V  (4 k-steps over key dim)
        {
            const float a1 = Al[warp * 16 + g];
            const float a2 = Al[warp * 16 + g + 8];
#pragma unroll
            for (int nt = 0; nt < 8; nt++) {
                o[nt][0] *= a1; o[nt][1] *= a1;
                o[nt][2] *= a2; o[nt][3] *= a2;
            }
        }
#pragma unroll
        for (int ks = 0; ks < 4; ks++) {
            const int kk2 = ks * 8;
            const int row = warp * 16 + g;
            uint32_t af[4];
            af[0] = Ps2[row       * FH_LD2 + kk2 + tig];
            af[1] = Ps2[(row + 8) * FH_LD2 + kk2 + tig];
            af[2] = Ps2[row       * FH_LD2 + kk2 + tig + 4];
            af[3] = Ps2[(row + 8) * FH_LD2 + kk2 + tig + 4];
#pragma unroll
            for (int nt = 0; nt < 8; nt++) {
                uint32_t bf[2];
                bf[0] = Vt2[(nt * 8 + g) * FH_LD2 + kk2 + tig];
                bf[1] = Vt2[(nt * 8 + g) * FH_LD2 + kk2 + tig + 4];
                mma16(o[nt], af, bf);
            }
        }
        __syncthreads();
    }

    // epilogue: normalize and write
    if (!half) Al[sr] = 1.0f / l_i;
    __syncthreads();
    const float i1 = Al[warp * 16 + g];
    const float i2 = Al[warp * 16 + g + 8];
    const long r1 = (long)b * SEQ + m0 + warp * 16 + g;
    const long r2 = r1 + 8;
#pragma unroll
    for (int nt = 0; nt < 8; nt++) {
        const int col = h * D_HEADD + nt * 8 + 2 * tig;
        *(float2*)&O[r1 * D_EMBED + col] = make_float2(o[nt][0] * i1, o[nt][1] * i1);
        *(float2*)&O[r2 * D_EMBED + col] = make_float2(o[nt][2] * i2, o[nt][3] * i2);
    }
}

// ================= fp32 SGEMM (small M fallback for kc/vc) =================
template<bool GELU>
__global__ void __launch_bounds__(256, 2)
sgemm_bias(const float* __restrict__ A, const float* __restrict__ B,
           const float* __restrict__ bias, float* __restrict__ C,
           int M, int N, int K)
{
    __shared__ float As[8][128];
    __shared__ float Bs[8][128];
    const int tid = threadIdx.x;
    const int m0 = blockIdx.y * 128;
    const int n0 = blockIdx.x * 128;
    const int tx = tid & 15;
    const int ty = tid >> 4;

    float acc[8][8];
#pragma unroll
    for (int i = 0; i < 8; i++)
#pragma unroll
        for (int j = 0; j < 8; j++) acc[i][j] = 0.0f;

    const int a_row = tid >> 1;
    const int a_col = (tid & 1) * 4;
    const int b_row = tid >> 5;
    const int b_col = (tid & 31) * 4;
    const bool a_valid = (m0 + a_row) < M;
    const float* Aptr = A + (long)(m0 + a_row) * K + a_col;
    const float* Bptr = B + (long)b_row * N + n0 + b_col;

    for (int k0 = 0; k0 < K; k0 += 8) {
        float4 av = a_valid ? *(const float4*)(Aptr + k0) : make_float4(0.f, 0.f, 0.f, 0.f);
        As[a_col + 0][a_row] = av.x;
        As[a_col + 1][a_row] = av.y;
        As[a_col + 2][a_row] = av.z;
        As[a_col + 3][a_row] = av.w;
        *(float4*)&Bs[b_row][b_col] = *(const float4*)(Bptr + (long)k0 * N);
        __syncthreads();
#pragma unroll
        for (int kk = 0; kk < 8; kk++) {
            float ra[8], rb[8];
            *(float4*)&ra[0] = *(const float4*)&As[kk][ty * 8];
            *(float4*)&ra[4] = *(const float4*)&As[kk][ty * 8 + 4];
            *(float4*)&rb[0] = *(const float4*)&Bs[kk][tx * 8];
            *(float4*)&rb[4] = *(const float4*)&Bs[kk][tx * 8 + 4];
#pragma unroll
            for (int i = 0; i < 8; i++)
#pragma unroll
                for (int j = 0; j < 8; j++)
                    acc[i][j] += ra[i] * rb[j];
        }
        __syncthreads();
    }
    float bvv[8];
#pragma unroll
    for (int j = 0; j < 8; j++) bvv[j] = bias[n0 + tx * 8 + j];
#pragma unroll
    for (int i = 0; i < 8; i++) {
        int row = m0 + ty * 8 + i;
        if (row < M) {
            float outv[8];
#pragma unroll
            for (int j = 0; j < 8; j++) {
                float c = acc[i][j] + bvv[j];
                outv[j] = GELU ? gelu_tanh(c) : c;
            }
            float* Cp = C + (long)row * N + n0 + tx * 8;
            *(float4*)&Cp[0] = *(float4*)&outv[0];
            *(float4*)&Cp[4] = *(float4*)&outv[4];
        }
    }
}

// ================= fused residual add + LayerNorm =================
__global__ void __launch_bounds__(128)
add_ln(const float* __restrict__ A, const float* __restrict__ R,
       const float* __restrict__ g, const float* __restrict__ beta,
       float* __restrict__ out)
{
    const long row = blockIdx.x;
    const int tid = threadIdx.x;
    const float4 a = *(const float4*)(A + row * D_EMBED + tid * 4);
    const float4 r = *(const float4*)(R + row * D_EMBED + tid * 4);
    float v[4] = {a.x + r.x, a.y + r.y, a.z + r.z, a.w + r.w};

    float s = v[0] + v[1] + v[2] + v[3];
    float ss = v[0]*v[0] + v[1]*v[1] + v[2]*v[2] + v[3]*v[3];
#pragma unroll
    for (int off = 16; off >= 1; off >>= 1) {
        s  += __shfl_xor_sync(0xffffffffu, s,  off);
        ss += __shfl_xor_sync(0xffffffffu, ss, off);
    }
    __shared__ float sred[8];
    const int warp = tid >> 5, lane = tid & 31;
    if (lane == 0) { sred[warp] = s; sred[warp + 4] = ss; }
    __syncthreads();
    s  = sred[0] + sred[1] + sred[2] + sred[3];
    ss = sred[4] + sred[5] + sred[6] + sred[7];

    const float mean = s * (1.0f / D_EMBED);
    const float var  = ss * (1.0f / D_EMBED) - mean * mean;
    const float rstd = rsqrtf(var + 1e-5f);

    const float4 gg = *(const float4*)(g + tid * 4);
    const float4 bb = *(const float4*)(beta + tid * 4);
    float4 o;
    o.x = (v[0] - mean) * rstd * gg.x + bb.x;
    o.y = (v[1] - mean) * rstd * gg.y + bb.y;
    o.z = (v[2] - mean) * rstd * gg.z + bb.z;
    o.w = (v[3] - mean) * rstd * gg.w + bb.w;
    *(float4*)(out + row * D_EMBED + tid * 4) = o;
}

// ================= host =================
extern "C" void kernel_launch(void* const* d_in, const int* in_sizes, int n_in,
                              void* d_out, int out_size)
{
    const float* x        = (const float*)d_in[0];
    const float* y        = (const float*)d_in[1];
    const float* sa_in_w  = (const float*)d_in[2];
    const float* sa_in_b  = (const float*)d_in[3];
    const float* sa_out_w = (const float*)d_in[4];
    const float* sa_out_b = (const float*)d_in[5];
    const float* ca_q_w   = (const float*)d_in[6];
    const float* ca_q_b   = (const float*)d_in[7];
    const float* ca_k_w   = (const float*)d_in[8];
    const float* ca_k_b   = (const float*)d_in[9];
    const float* ca_v_w   = (const float*)d_in[10];
    const float* ca_v_b   = (const float*)d_in[11];
    const float* ca_out_w = (const float*)d_in[12];
    const float* ca_out_b = (const float*)d_in[13];
    const float* ff_w1    = (const float*)d_in[14];
    const float* ff_b1    = (const float*)d_in[15];
    const float* ff_w2    = (const float*)d_in[16];
    const float* ff_b2    = (const float*)d_in[17];
    const float* ln1_g    = (const float*)d_in[18];
    const float* ln1_b    = (const float*)d_in[19];
    const float* ln2_g    = (const float*)d_in[20];
    const float* ln2_b    = (const float*)d_in[21];
    const float* ln3_g    = (const float*)d_in[22];
    const float* ln3_b    = (const float*)d_in[23];
    float* out = (float*)d_out;

    float *qkv, *attn, *proj, *x1, *x2q, *kc, *vc, *ff;
    __half* w16;
    cudaGetSymbolAddress((void**)&qkv,  g_qkv);
    cudaGetSymbolAddress((void**)&attn, g_attn);
    cudaGetSymbolAddress((void**)&proj, g_proj);
    cudaGetSymbolAddress((void**)&x1,   g_x1);
    cudaGetSymbolAddress((void**)&x2q,  g_x2q);
    cudaGetSymbolAddress((void**)&kc,   g_kc);
    cudaGetSymbolAddress((void**)&vc,   g_vc);
    cudaGetSymbolAddress((void**)&ff,   g_ff);
    cudaGetSymbolAddress((void**)&w16,  g_w16);

    cudaFuncSetAttribute(flash_h, cudaFuncAttributeMaxDynamicSharedMemorySize, FH_SMEM);

    // 0. transpose + fp16-convert all big weights: W[K,N] -> Wt[N,K]
    transpose_h<<<dim3(1536/32, 512/32),  256>>>(sa_in_w,  w16 + WOFF_SAIN,  512, 1536);
    transpose_h<<<dim3(512/32,  512/32),  256>>>(sa_out_w, w16 + WOFF_SAOUT, 512, 512);
    transpose_h<<<dim3(512/32,  512/32),  256>>>(ca_q_w,   w16 + WOFF_CAQ,   512, 512);
    transpose_h<<<dim3(512/32,  512/32),  256>>>(ca_out_w, w16 + WOFF_CAOUT, 512, 512);
    transpose_h<<<dim3(2048/32, 512/32),  256>>>(ff_w1,    w16 + WOFF_FF1,   512, 2048);
    transpose_h<<<dim3(512/32,  2048/32), 256>>>(ff_w2,    w16 + WOFF_FF2,   2048, 512);

    // 1. QKV projection: [8192,512] @ [512,1536]
    gemm_h<false><<<dim3(1536/128, M_ROWS/128), 256>>>(
        x, w16 + WOFF_SAIN, sa_in_b, qkv, M_ROWS, 3*D_EMBED, D_EMBED);
    // 2. self-attention (q|k|v packed in qkv, ld = 1536)
    flash_h<<<dim3(SEQ/64, N_HEADS, BATCH), 128, FH_SMEM>>>(
        qkv, qkv + D_EMBED, qkv + 2*D_EMBED, attn,
        3*D_EMBED, (long)SEQ * 3*D_EMBED,
        3*D_EMBED, (long)SEQ * 3*D_EMBED,
        3*D_EMBED, (long)SEQ * 3*D_EMBED,
        SEQ, 0.125f);
    // 3. self-attn output projection
    gemm_h<false><<<dim3(4, M_ROWS/128), 256>>>(
        attn, w16 + WOFF_SAOUT, sa_out_b, proj, M_ROWS, D_EMBED, D_EMBED);
    // 4. x1 = LN(x + proj)
    add_ln<<<M_ROWS, 128>>>(x, proj, ln1_g, ln1_b, x1);

    // 5. cross-attn Q projection
    gemm_h<false><<<dim3(4, M_ROWS/128), 256>>>(
        x1, w16 + WOFF_CAQ, ca_q_b, x2q, M_ROWS, D_EMBED, D_EMBED);
    // 6. cross-attn K/V projections (tiny M; fp32 path)
    sgemm_bias<false><<<dim3(4, 2), 256>>>(y, ca_k_w, ca_k_b, kc, Y_ROWS, D_EMBED, D_CROSS);
    sgemm_bias<false><<<dim3(4, 2), 256>>>(y, ca_v_w, ca_v_b, vc, Y_ROWS, D_EMBED, D_CROSS);
    // 7. cross-attention (Skv = 77)
    flash_h<<<dim3(SEQ/64, N_HEADS, BATCH), 128, FH_SMEM>>>(
        x2q, kc, vc, attn,
        D_EMBED, (long)SEQ * D_EMBED,
        D_EMBED, (long)SKV_C * D_EMBED,
        D_EMBED, (long)SKV_C * D_EMBED,
        SKV_C, 0.125f);
    // 8. cross-attn output projection
    gemm_h<false><<<dim3(4, M_ROWS/128), 256>>>(
        attn, w16 + WOFF_CAOUT, ca_out_b, proj, M_ROWS, D_EMBED, D_EMBED);
    // 9. x2 = LN(x1 + proj)
    add_ln<<<M_ROWS, 128>>>(x1, proj, ln2_g, ln2_b, x2q);

    // 10. FF1 + GELU
    gemm_h<true><<<dim3(FF_DIM/128, M_ROWS/128), 256>>>(
        x2q, w16 + WOFF_FF1, ff_b1, ff, M_ROWS, FF_DIM, D_EMBED);
    // 11. FF2
    gemm_h<false><<<dim3(4, M_ROWS/128), 256>>>(
        ff, w16 + WOFF_FF2, ff_b2, proj, M_ROWS, D_EMBED, FF_DIM);
    // 12. out = LN(x2 + proj)
    add_ln<<<M_ROWS, 128>>>(x2q, proj, ln3_g, ln3_b, out);
}

// round 11
// speedup vs baseline: 2.9384x; 1.4908x over previous
#include <cuda_runtime.h>
#include <cuda_fp16.h>
#include <math.h>
#include <stdint.h>

// ---------------- problem constants ----------------
#define D_EMBED 512
#define N_HEADS 8
#define D_HEADD 64
#define FF_DIM  2048
#define D_CROSS 768
#define BATCH   2
#define SEQ     4096
#define SKV_C   77
#define M_ROWS  (BATCH * SEQ)     // 8192
#define Y_ROWS  (BATCH * SKV_C)   // 154

// ---------------- scratch ----------------
__device__ float g_qkv [M_ROWS * 3 * D_EMBED];
__device__ float g_attn[M_ROWS * D_EMBED];
__device__ float g_proj[M_ROWS * D_EMBED];
__device__ float g_x1  [M_ROWS * D_EMBED];
__device__ float g_x2q [M_ROWS * D_EMBED];
__device__ float g_kc  [Y_ROWS * D_EMBED];
__device__ float g_vc  [Y_ROWS * D_EMBED];
__device__ float g_ff  [M_ROWS * FF_DIM];

// transposed fp16 weights [N,K]
#define WOFF_SAIN  0
#define WOFF_SAOUT 786432
#define WOFF_CAQ   1048576
#define WOFF_CAOUT 1310720
#define WOFF_FF1   1572864
#define WOFF_FF2   2621440
#define WT_TOTAL   3670016
__device__ __half g_w16[WT_TOTAL];

__device__ __forceinline__ float gelu_tanh(float x) {
    float x3 = x * x * x;
    return 0.5f * x * (1.0f + tanhf(0.7978845608028654f * (x + 0.044715f * x3)));
}

__device__ __forceinline__ uint32_t pack2h(float a, float b) {
    __half2 h = __floats2half2_rn(a, b);
    return *(uint32_t*)&h;
}

// fp16 mma m16n8k16, fp32 accum
__device__ __forceinline__ void mma16(float d[4], const uint32_t a[4], const uint32_t b[2]) {
    asm volatile(
        "mma.sync.aligned.m16n8k16.row.col.f32.f16.f16.f32 "
        "{%0,%1,%2,%3}, {%4,%5,%6,%7}, {%8,%9}, {%0,%1,%2,%3};\n"
        : "+f"(d[0]), "+f"(d[1]), "+f"(d[2]), "+f"(d[3])
        : "r"(a[0]), "r"(a[1]), "r"(a[2]), "r"(a[3]), "r"(b[0]), "r"(b[1]));
}

// ================= weight transpose to fp16: W[K,N] -> Wt[N,K] =================
__global__ void __launch_bounds__(256)
transpose_h(const float* __restrict__ W, __half* __restrict__ Wt, int K, int N)
{
    __shared__ float t[32][33];
    const int n0 = blockIdx.x * 32, k0 = blockIdx.y * 32;
    const int tx = threadIdx.x & 31, ty = threadIdx.x >> 5;  // 32 x 8
#pragma unroll
    for (int j = 0; j < 32; j += 8)
        t[ty + j][tx] = W[(long)(k0 + ty + j) * N + n0 + tx];
    __syncthreads();
#pragma unroll
    for (int j = 0; j < 32; j += 8)
        Wt[(long)(n0 + ty + j) * K + k0 + tx] = __float2half_rn(t[tx][ty + j]);
}

// ================= fp16-mma GEMM (double-buffered) ============================
// C[M,N] = A[M,K] @ Wt[N,K]^T + bias (+GELU)
// BM=128, BN=128, BK=32; 256 thr (8 warps 2x4); warp tile 64x32.
#define GA_LD2 20

template<bool GELU>
__global__ void __launch_bounds__(256)
gemm_h(const float* __restrict__ A, const __half* __restrict__ Wt,
       const float* __restrict__ bias, float* __restrict__ C,
       int M, int N, int K)
{
    __shared__ uint32_t As2[2][128 * GA_LD2];
    __shared__ uint32_t Bs2[2][128 * GA_LD2];

    const int tid  = threadIdx.x;
    const int lane = tid & 31;
    const int warp = tid >> 5;
    const int wm = warp >> 2;          // 0..1
    const int wn = warp & 3;           // 0..3
    const int g   = lane >> 2;         // 0..7
    const int tig = lane & 3;          // 0..3

    const int m0 = blockIdx.y * 128;
    const int n0 = blockIdx.x * 128;

    float acc[4][4][4];
#pragma unroll
    for (int i = 0; i < 4; i++)
#pragma unroll
        for (int j = 0; j < 4; j++)
#pragma unroll
            for (int r = 0; r < 4; r++) acc[i][j][r] = 0.0f;

    // staging: 2 threads per row, 16 cols each
    const int arow = tid >> 1, ahalf = tid & 1;
    const float* Ap = A + (long)(m0 + arow) * K + ahalf * 16;
    const __half* Bp = Wt + (long)(n0 + arow) * K + ahalf * 16;

    float4 ar[4];
    uint4  br[2];
#pragma unroll
    for (int j = 0; j < 4; j++) ar[j] = *(const float4*)(Ap + j * 4);
#pragma unroll
    for (int j = 0; j < 2; j++) br[j] = *(const uint4*)(Bp + j * 8);

    const int NIT = K >> 5;
    for (int it = 0; it < NIT; it++) {
        const int buf = it & 1;
        // store staged registers (prev reads of this buf finished 2 iters ago)
#pragma unroll
        for (int j = 0; j < 4; j++) {
            float4 v = ar[j];
            *(uint2*)&As2[buf][arow * GA_LD2 + ahalf * 8 + 2 * j] =
                make_uint2(pack2h(v.x, v.y), pack2h(v.z, v.w));
        }
#pragma unroll
        for (int j = 0; j < 2; j++)
            *(uint4*)&Bs2[buf][arow * GA_LD2 + ahalf * 8 + 4 * j] = br[j];

        if (it + 1 < NIT) {
            const int k0 = (it + 1) * 32;
#pragma unroll
            for (int j = 0; j < 4; j++) ar[j] = *(const float4*)(Ap + k0 + j * 4);
#pragma unroll
            for (int j = 0; j < 2; j++) br[j] = *(const uint4*)(Bp + k0 + j * 8);
        }
        __syncthreads();

#pragma unroll
        for (int ks = 0; ks < 2; ks++) {
            const int kk2 = ks * 8;
            uint32_t bf[4][2];
#pragma unroll
            for (int nt = 0; nt < 4; nt++) {
                const int nc = wn * 32 + nt * 8 + g;
                bf[nt][0] = Bs2[buf][nc * GA_LD2 + kk2 + tig];
                bf[nt][1] = Bs2[buf][nc * GA_LD2 + kk2 + tig + 4];
            }
#pragma unroll
            for (int mt = 0; mt < 4; mt++) {
                const int row = wm * 64 + mt * 16 + g;
                uint32_t af[4];
                af[0] = As2[buf][row       * GA_LD2 + kk2 + tig];
                af[1] = As2[buf][(row + 8) * GA_LD2 + kk2 + tig];
                af[2] = As2[buf][row       * GA_LD2 + kk2 + tig + 4];
                af[3] = As2[buf][(row + 8) * GA_LD2 + kk2 + tig + 4];
#pragma unroll
                for (int nt = 0; nt < 4; nt++)
                    mma16(acc[mt][nt], af, bf[nt]);
            }
        }
    }

    // epilogue
    const int cb = n0 + wn * 32;
    float2 bv[4];
#pragma unroll
    for (int nt = 0; nt < 4; nt++)
        bv[nt] = *(const float2*)&bias[cb + nt * 8 + 2 * tig];

#pragma unroll
    for (int mt = 0; mt < 4; mt++) {
        const long r1 = m0 + wm * 64 + mt * 16 + g;
        const long r2 = r1 + 8;
#pragma unroll
        for (int nt = 0; nt < 4; nt++) {
            float c0 = acc[mt][nt][0] + bv[nt].x;
            float c1 = acc[mt][nt][1] + bv[nt].y;
            float c2 = acc[mt][nt][2] + bv[nt].x;
            float c3 = acc[mt][nt][3] + bv[nt].y;
            if (GELU) { c0 = gelu_tanh(c0); c1 = gelu_tanh(c1); c2 = gelu_tanh(c2); c3 = gelu_tanh(c3); }
            *(float2*)&C[r1 * N + cb + nt * 8 + 2 * tig] = make_float2(c0, c1);
            *(float2*)&C[r2 * N + cb + nt * 8 + 2 * tig] = make_float2(c2, c3);
        }
    }
}

// ================= fp16-mma flash attention, register softmax (FA2-style) ======
// BM=128 rows (8 warps; warp w owns rows 16w..16w+15), BN=64 keys, d=64.
// S/P live in registers; softmax via quad shuffles. Smem: Q, K, V^T tiles only.
#define FB_LD2 36

__global__ void __launch_bounds__(256)
flash_h(const float* __restrict__ Q, const float* __restrict__ K,
        const float* __restrict__ V, float* __restrict__ O,
        int ldq, long qbs, int ldk, long kbs, int ldv, long vbs,
        int Skv, float scale)
{
    __shared__ uint32_t Qs2[128 * FB_LD2];
    __shared__ uint32_t Ks2[64 * FB_LD2];
    __shared__ uint32_t Vt2[64 * FB_LD2];
    __half* VtH = (__half*)Vt2;            // [d][72 halves]

    const int tid  = threadIdx.x;
    const int lane = tid & 31;
    const int warp = tid >> 5;
    const int g    = lane >> 2;
    const int tig  = lane & 3;
    const int b = blockIdx.z, h = blockIdx.y;
    const int m0 = blockIdx.x * 128;

    const float* q = Q + b * qbs + h * D_HEADD;
    const float* k = K + b * kbs + h * D_HEADD;
    const float* v = V + b * vbs + h * D_HEADD;

    // ---- stage Q (scaled fp16): 2 threads per row ----
    {
        const int sr = tid >> 1, half = tid & 1;
#pragma unroll
        for (int j = 0; j < 8; j++) {
            const int c = half * 32 + j * 4;
            float4 qv = *(const float4*)(q + (long)(m0 + sr) * ldq + c);
            *(uint2*)&Qs2[sr * FB_LD2 + c / 2] =
                make_uint2(pack2h(qv.x * scale, qv.y * scale),
                           pack2h(qv.z * scale, qv.w * scale));
        }
    }
    __syncthreads();

    // ---- Q fragments in registers (row = 16*warp + g) ----
    uint32_t qf[4][4];
    {
        const int row = warp * 16 + g;
#pragma unroll
        for (int ks = 0; ks < 4; ks++) {
            qf[ks][0] = Qs2[row       * FB_LD2 + 8 * ks + tig];
            qf[ks][1] = Qs2[(row + 8) * FB_LD2 + 8 * ks + tig];
            qf[ks][2] = Qs2[row       * FB_LD2 + 8 * ks + tig + 4];
            qf[ks][3] = Qs2[(row + 8) * FB_LD2 + 8 * ks + tig + 4];
        }
    }

    float o[8][4];
#pragma unroll
    for (int nt = 0; nt < 8; nt++)
#pragma unroll
        for (int r = 0; r < 4; r++) o[nt][r] = 0.0f;
    float m0r = -1e30f, m1r = -1e30f, l0r = 0.0f, l1r = 0.0f;

    const int ntiles = (Skv + 63) >> 6;
    for (int t = 0; t < ntiles; t++) {
        const int n0t = t * 64;

        // ---- stage K [key][d] fp16 and V^T [d][key] fp16: 4 threads per key-row ----
        {
            const int krow = tid >> 2, qtr = tid & 3;
#pragma unroll
            for (int j = 0; j < 4; j++) {
                const int c = qtr * 16 + j * 4;
                float4 kv4, vv4;
                if (n0t + krow < Skv) {
                    kv4 = *(const float4*)(k + (long)(n0t + krow) * ldk + c);
                    vv4 = *(const float4*)(v + (long)(n0t + krow) * ldv + c);
                } else {
                    kv4 = make_float4(0.f, 0.f, 0.f, 0.f);
                    vv4 = kv4;
                }
                *(uint2*)&Ks2[krow * FB_LD2 + c / 2] =
                    make_uint2(pack2h(kv4.x, kv4.y), pack2h(kv4.z, kv4.w));
                VtH[(c + 0) * 72 + krow] = __float2half_rn(vv4.x);
                VtH[(c + 1) * 72 + krow] = __float2half_rn(vv4.y);
                VtH[(c + 2) * 72 + krow] = __float2half_rn(vv4.z);
                VtH[(c + 3) * 72 + krow] = __float2half_rn(vv4.w);
            }
        }
        __syncthreads();

        // ---- S = Q @ K^T (registers) ----
        float sfr[8][4];
#pragma unroll
        for (int nt = 0; nt < 8; nt++)
#pragma unroll
            for (int r = 0; r < 4; r++) sfr[nt][r] = 0.0f;

#pragma unroll
        for (int ks = 0; ks < 4; ks++) {
            const int kk2 = ks * 8;
#pragma unroll
            for (int nt = 0; nt < 8; nt++) {
                uint32_t bf[2];
                bf[0] = Ks2[(nt * 8 + g) * FB_LD2 + kk2 + tig];
                bf[1] = Ks2[(nt * 8 + g) * FB_LD2 + kk2 + tig + 4];
                mma16(sfr[nt], qf[ks], bf);
            }
        }

        // ---- tail mask (by key column) ----
        if (n0t + 64 > Skv) {
#pragma unroll
            for (int nt = 0; nt < 8; nt++) {
                const int c0 = n0t + nt * 8 + 2 * tig;
                if (c0 >= Skv)     { sfr[nt][0] = -1e30f; sfr[nt][2] = -1e30f; }
                if (c0 + 1 >= Skv) { sfr[nt][1] = -1e30f; sfr[nt][3] = -1e30f; }
            }
        }

        // ---- online softmax in registers (rows g and g+8) ----
        float mx0 = -1e30f, mx1 = -1e30f;
#pragma unroll
        for (int nt = 0; nt < 8; nt++) {
            mx0 = fmaxf(mx0, fmaxf(sfr[nt][0], sfr[nt][1]));
            mx1 = fmaxf(mx1, fmaxf(sfr[nt][2], sfr[nt][3]));
        }
        mx0 = fmaxf(mx0, __shfl_xor_sync(0xffffffffu, mx0, 1));
        mx0 = fmaxf(mx0, __shfl_xor_sync(0xffffffffu, mx0, 2));
        mx1 = fmaxf(mx1, __shfl_xor_sync(0xffffffffu, mx1, 1));
        mx1 = fmaxf(mx1, __shfl_xor_sync(0xffffffffu, mx1, 2));

        const float mn0 = fmaxf(m0r, mx0), mn1 = fmaxf(m1r, mx1);
        const float al0 = __expf(m0r - mn0), al1 = __expf(m1r - mn1);
        m0r = mn0; m1r = mn1;

        float s0 = 0.0f, s1 = 0.0f;
#pragma unroll
        for (int nt = 0; nt < 8; nt++) {
            float p0 = __expf(sfr[nt][0] - mn0);
            float p1 = __expf(sfr[nt][1] - mn0);
            float p2 = __expf(sfr[nt][2] - mn1);
            float p3 = __expf(sfr[nt][3] - mn1);
            sfr[nt][0] = p0; sfr[nt][1] = p1; sfr[nt][2] = p2; sfr[nt][3] = p3;
            s0 += p0 + p1; s1 += p2 + p3;
        }
        s0 += __shfl_xor_sync(0xffffffffu, s0, 1);
        s0 += __shfl_xor_sync(0xffffffffu, s0, 2);
        s1 += __shfl_xor_sync(0xffffffffu, s1, 1);
        s1 += __shfl_xor_sync(0xffffffffu, s1, 2);
        l0r = l0r * al0 + s0;
        l1r = l1r * al1 + s1;

#pragma unroll
        for (int nt = 0; nt < 8; nt++) {
            o[nt][0] *= al0; o[nt][1] *= al0;
            o[nt][2] *= al1; o[nt][3] *= al1;
        }

        // ---- O += P @ V : P frags packed directly from S accumulators ----
#pragma unroll
        for (int ks = 0; ks < 4; ks++) {
            uint32_t af[4];
            af[0] = pack2h(sfr[2 * ks][0],     sfr[2 * ks][1]);
            af[1] = pack2h(sfr[2 * ks][2],     sfr[2 * ks][3]);
            af[2] = pack2h(sfr[2 * ks + 1][0], sfr[2 * ks + 1][1]);
            af[3] = pack2h(sfr[2 * ks + 1][2], sfr[2 * ks + 1][3]);
            const int kk2 = ks * 8;
#pragma unroll
            for (int nt = 0; nt < 8; nt++) {
                uint32_t bf[2];
                bf[0] = Vt2[(nt * 8 + g) * FB_LD2 + kk2 + tig];
                bf[1] = Vt2[(nt * 8 + g) * FB_LD2 + kk2 + tig + 4];
                mma16(o[nt], af, bf);
            }
        }
        __syncthreads();   // before next tile overwrites Ks2/Vt2
    }

    // ---- epilogue: normalize and write ----
    const float i0 = 1.0f / l0r, i1 = 1.0f / l1r;
    const long r1 = (long)b * SEQ + m0 + warp * 16 + g;
    const long r2 = r1 + 8;
#pragma unroll
    for (int nt = 0; nt < 8; nt++) {
        const int col = h * D_HEADD + nt * 8 + 2 * tig;
        *(float2*)&O[r1 * D_EMBED + col] = make_float2(o[nt][0] * i0, o[nt][1] * i0);
        *(float2*)&O[r2 * D_EMBED + col] = make_float2(o[nt][2] * i1, o[nt][3] * i1);
    }
}

// ================= fp32 SGEMM (small M fallback for kc/vc) =================
template<bool GELU>
__global__ void __launch_bounds__(256, 2)
sgemm_bias(const float* __restrict__ A, const float* __restrict__ B,
           const float* __restrict__ bias, float* __restrict__ C,
           int M, int N, int K)
{
    __shared__ float As[8][128];
    __shared__ float Bs[8][128];
    const int tid = threadIdx.x;
    const int m0 = blockIdx.y * 128;
    const int n0 = blockIdx.x * 128;
    const int tx = tid & 15;
    const int ty = tid >> 4;

    float acc[8][8];
#pragma unroll
    for (int i = 0; i < 8; i++)
#pragma unroll
        for (int j = 0; j < 8; j++) acc[i][j] = 0.0f;

    const int a_row = tid >> 1;
    const int a_col = (tid & 1) * 4;
    const int b_row = tid >> 5;
    const int b_col = (tid & 31) * 4;
    const bool a_valid = (m0 + a_row) < M;
    const float* Aptr = A + (long)(m0 + a_row) * K + a_col;
    const float* Bptr = B + (long)b_row * N + n0 + b_col;

    for (int k0 = 0; k0 < K; k0 += 8) {
        float4 av = a_valid ? *(const float4*)(Aptr + k0) : make_float4(0.f, 0.f, 0.f, 0.f);
        As[a_col + 0][a_row] = av.x;
        As[a_col + 1][a_row] = av.y;
        As[a_col + 2][a_row] = av.z;
        As[a_col + 3][a_row] = av.w;
        *(float4*)&Bs[b_row][b_col] = *(const float4*)(Bptr + (long)k0 * N);
        __syncthreads();
#pragma unroll
        for (int kk = 0; kk < 8; kk++) {
            float ra[8], rb[8];
            *(float4*)&ra[0] = *(const float4*)&As[kk][ty * 8];
            *(float4*)&ra[4] = *(const float4*)&As[kk][ty * 8 + 4];
            *(float4*)&rb[0] = *(const float4*)&Bs[kk][tx * 8];
            *(float4*)&rb[4] = *(const float4*)&Bs[kk][tx * 8 + 4];
#pragma unroll
            for (int i = 0; i < 8; i++)
#pragma unroll
                for (int j = 0; j < 8; j++)
                    acc[i][j] += ra[i] * rb[j];
        }
        __syncthreads();
    }
    float bvv[8];
#pragma unroll
    for (int j = 0; j < 8; j++) bvv[j] = bias[n0 + tx * 8 + j];
#pragma unroll
    for (int i = 0; i < 8; i++) {
        int row = m0 + ty * 8 + i;
        if (row < M) {
            float outv[8];
#pragma unroll
            for (int j = 0; j < 8; j++) {
                float c = acc[i][j] + bvv[j];
                outv[j] = GELU ? gelu_tanh(c) : c;
            }
            float* Cp = C + (long)row * N + n0 + tx * 8;
            *(float4*)&Cp[0] = *(float4*)&outv[0];
            *(float4*)&Cp[4] = *(float4*)&outv[4];
        }
    }
}

// ================= fused residual add + LayerNorm =================
__global__ void __launch_bounds__(128)
add_ln(const float* __restrict__ A, const float* __restrict__ R,
       const float* __restrict__ g, const float* __restrict__ beta,
       float* __restrict__ out)
{
    const long row = blockIdx.x;
    const int tid = threadIdx.x;
    const float4 a = *(const float4*)(A + row * D_EMBED + tid * 4);
    const float4 r = *(const float4*)(R + row * D_EMBED + tid * 4);
    float v[4] = {a.x + r.x, a.y + r.y, a.z + r.z, a.w + r.w};

    float s = v[0] + v[1] + v[2] + v[3];
    float ss = v[0]*v[0] + v[1]*v[1] + v[2]*v[2] + v[3]*v[3];
#pragma unroll
    for (int off = 16; off >= 1; off >>= 1) {
        s  += __shfl_xor_sync(0xffffffffu, s,  off);
        ss += __shfl_xor_sync(0xffffffffu, ss, off);
    }
    __shared__ float sred[8];
    const int warp = tid >> 5, lane = tid & 31;
    if (lane == 0) { sred[warp] = s; sred[warp + 4] = ss; }
    __syncthreads();
    s  = sred[0] + sred[1] + sred[2] + sred[3];
    ss = sred[4] + sred[5] + sred[6] + sred[7];

    const float mean = s * (1.0f / D_EMBED);
    const float var  = ss * (1.0f / D_EMBED) - mean * mean;
    const float rstd = rsqrtf(var + 1e-5f);

    const float4 gg = *(const float4*)(g + tid * 4);
    const float4 bb = *(const float4*)(beta + tid * 4);
    float4 o;
    o.x = (v[0] - mean) * rstd * gg.x + bb.x;
    o.y = (v[1] - mean) * rstd * gg.y + bb.y;
    o.z = (v[2] - mean) * rstd * gg.z + bb.z;
    o.w = (v[3] - mean) * rstd * gg.w + bb.w;
    *(float4*)(out + row * D_EMBED + tid * 4) = o;
}

// ================= host =================
extern "C" void kernel_launch(void* const* d_in, const int* in_sizes, int n_in,
                              void* d_out, int out_size)
{
    const float* x        = (const float*)d_in[0];
    const float* y        = (const float*)d_in[1];
    const float* sa_in_w  = (const float*)d_in[2];
    const float* sa_in_b  = (const float*)d_in[3];
    const float* sa_out_w = (const float*)d_in[4];
    const float* sa_out_b = (const float*)d_in[5];
    const float* ca_q_w   = (const float*)d_in[6];
    const float* ca_q_b   = (const float*)d_in[7];
    const float* ca_k_w   = (const float*)d_in[8];
    const float* ca_k_b   = (const float*)d_in[9];
    const float* ca_v_w   = (const float*)d_in[10];
    const float* ca_v_b   = (const float*)d_in[11];
    const float* ca_out_w = (const float*)d_in[12];
    const float* ca_out_b = (const float*)d_in[13];
    const float* ff_w1    = (const float*)d_in[14];
    const float* ff_b1    = (const float*)d_in[15];
    const float* ff_w2    = (const float*)d_in[16];
    const float* ff_b2    = (const float*)d_in[17];
    const float* ln1_g    = (const float*)d_in[18];
    const float* ln1_b    = (const float*)d_in[19];
    const float* ln2_g    = (const float*)d_in[20];
    const float* ln2_b    = (const float*)d_in[21];
    const float* ln3_g    = (const float*)d_in[22];
    const float* ln3_b    = (const float*)d_in[23];
    float* out = (float*)d_out;

    float *qkv, *attn, *proj, *x1, *x2q, *kc, *vc, *ff;
    __half* w16;
    cudaGetSymbolAddress((void**)&qkv,  g_qkv);
    cudaGetSymbolAddress((void**)&attn, g_attn);
    cudaGetSymbolAddress((void**)&proj, g_proj);
    cudaGetSymbolAddress((void**)&x1,   g_x1);
    cudaGetSymbolAddress((void**)&x2q,  g_x2q);
    cudaGetSymbolAddress((void**)&kc,   g_kc);
    cudaGetSymbolAddress((void**)&vc,   g_vc);
    cudaGetSymbolAddress((void**)&ff,   g_ff);
    cudaGetSymbolAddress((void**)&w16,  g_w16);

    // 0. transpose + fp16-convert all big weights: W[K,N] -> Wt[N,K]
    transpose_h<<<dim3(1536/32, 512/32),  256>>>(sa_in_w,  w16 + WOFF_SAIN,  512, 1536);
    transpose_h<<<dim3(512/32,  512/32),  256>>>(sa_out_w, w16 + WOFF_SAOUT, 512, 512);
    transpose_h<<<dim3(512/32,  512/32),  256>>>(ca_q_w,   w16 + WOFF_CAQ,   512, 512);
    transpose_h<<<dim3(512/32,  512/32),  256>>>(ca_out_w, w16 + WOFF_CAOUT, 512, 512);
    transpose_h<<<dim3(2048/32, 512/32),  256>>>(ff_w1,    w16 + WOFF_FF1,   512, 2048);
    transpose_h<<<dim3(512/32,  2048/32), 256>>>(ff_w2,    w16 + WOFF_FF2,   2048, 512);

    // 1. QKV projection: [8192,512] @ [512,1536]
    gemm_h<false><<<dim3(1536/128, M_ROWS/128), 256>>>(
        x, w16 + WOFF_SAIN, sa_in_b, qkv, M_ROWS, 3*D_EMBED, D_EMBED);
    // 2. self-attention (q|k|v packed in qkv, ld = 1536)
    flash_h<<<dim3(SEQ/128, N_HEADS, BATCH), 256>>>(
        qkv, qkv + D_EMBED, qkv + 2*D_EMBED, attn,
        3*D_EMBED, (long)SEQ * 3*D_EMBED,
        3*D_EMBED, (long)SEQ * 3*D_EMBED,
        3*D_EMBED, (long)SEQ * 3*D_EMBED,
        SEQ, 0.125f);
    // 3. self-attn output projection
    gemm_h<false><<<dim3(4, M_ROWS/128), 256>>>(
        attn, w16 + WOFF_SAOUT, sa_out_b, proj, M_ROWS, D_EMBED, D_EMBED);
    // 4. x1 = LN(x + proj)
    add_ln<<<M_ROWS, 128>>>(x, proj, ln1_g, ln1_b, x1);

    // 5. cross-attn Q projection
    gemm_h<false><<<dim3(4, M_ROWS/128), 256>>>(
        x1, w16 + WOFF_CAQ, ca_q_b, x2q, M_ROWS, D_EMBED, D_EMBED);
    // 6. cross-attn K/V projections (tiny M; fp32 path)
    sgemm_bias<false><<<dim3(4, 2), 256>>>(y, ca_k_w, ca_k_b, kc, Y_ROWS, D_EMBED, D_CROSS);
    sgemm_bias<false><<<dim3(4, 2), 256>>>(y, ca_v_w, ca_v_b, vc, Y_ROWS, D_EMBED, D_CROSS);
    // 7. cross-attention (Skv = 77)
    flash_h<<<dim3(SEQ/128, N_HEADS, BATCH), 256>>>(
        x2q, kc, vc, attn,
        D_EMBED, (long)SEQ * D_EMBED,
        D_EMBED, (long)SKV_C * D_EMBED,
        D_EMBED, (long)SKV_C * D_EMBED,
        SKV_C, 0.125f);
    // 8. cross-attn output projection
    gemm_h<false><<<dim3(4, M_ROWS/128), 256>>>(
        attn, w16 + WOFF_CAOUT, ca_out_b, proj, M_ROWS, D_EMBED, D_EMBED);
    // 9. x2 = LN(x1 + proj)
    add_ln<<<M_ROWS, 128>>>(x1, proj, ln2_g, ln2_b, x2q);

    // 10. FF1 + GELU
    gemm_h<true><<<dim3(FF_DIM/128, M_ROWS/128), 256>>>(
        x2q, w16 + WOFF_FF1, ff_b1, ff, M_ROWS, FF_DIM, D_EMBED);
    // 11. FF2
    gemm_h<false><<<dim3(4, M_ROWS/128), 256>>>(
        ff, w16 + WOFF_FF2, ff_b2, proj, M_ROWS, D_EMBED, FF_DIM);
    // 12. out = LN(x2 + proj)
    add_ln<<<M_ROWS, 128>>>(x2q, proj, ln3_g, ln3_b, out);
}

// round 14
// speedup vs baseline: 3.3984x; 1.1565x over previous
#include <cuda_runtime.h>
#include <cuda_fp16.h>
#include <math.h>
#include <stdint.h>

// ---------------- problem constants ----------------
#define D_EMBED 512
#define N_HEADS 8
#define D_HEADD 64
#define FF_DIM  2048
#define D_CROSS 768
#define BATCH   2
#define SEQ     4096
#define SKV_C   77
#define M_ROWS  (BATCH * SEQ)     // 8192
#define Y_ROWS  (BATCH * SKV_C)   // 154

// ---------------- scratch ----------------
__device__ __half g_qkvh[M_ROWS * 3 * D_EMBED];   // fp16 qkv
__device__ __half g_attnh[M_ROWS * D_EMBED];      // fp16 attention output
__device__ __half g_qch [M_ROWS * D_EMBED];       // fp16 cross-attn q
__device__ __half g_ffh [M_ROWS * FF_DIM];        // fp16 GELU output
__device__ __half g_kch [Y_ROWS * D_EMBED];
__device__ __half g_vch [Y_ROWS * D_EMBED];
__device__ float  g_proj[M_ROWS * D_EMBED];       // fp32 (residual path)
__device__ float  g_x1  [M_ROWS * D_EMBED];
__device__ float  g_x2q [M_ROWS * D_EMBED];

// transposed fp16 weights [N,K]
#define WOFF_SAIN  0
#define WOFF_SAOUT 786432
#define WOFF_CAQ   1048576
#define WOFF_CAOUT 1310720
#define WOFF_FF1   1572864
#define WOFF_FF2   2621440
#define WT_TOTAL   3670016
__device__ __half g_w16[WT_TOTAL];

__device__ __forceinline__ float gelu_tanh(float x) {
    float x3 = x * x * x;
    return 0.5f * x * (1.0f + tanhf(0.7978845608028654f * (x + 0.044715f * x3)));
}

__device__ __forceinline__ uint32_t pack2h(float a, float b) {
    __half2 h = __floats2half2_rn(a, b);
    return *(uint32_t*)&h;
}

// fp16 mma m16n8k16, fp32 accum
__device__ __forceinline__ void mma16(float d[4], const uint32_t a[4], const uint32_t b[2]) {
    asm volatile(
        "mma.sync.aligned.m16n8k16.row.col.f32.f16.f16.f32 "
        "{%0,%1,%2,%3}, {%4,%5,%6,%7}, {%8,%9}, {%0,%1,%2,%3};\n"
        : "+f"(d[0]), "+f"(d[1]), "+f"(d[2]), "+f"(d[3])
        : "r"(a[0]), "r"(a[1]), "r"(a[2]), "r"(a[3]), "r"(b[0]), "r"(b[1]));
}

// ================= weight transpose to fp16: W[K,N] -> Wt[N,K] =================
__global__ void __launch_bounds__(256)
transpose_h(const float* __restrict__ W, __half* __restrict__ Wt, int K, int N)
{
    __shared__ float t[32][33];
    const int n0 = blockIdx.x * 32, k0 = blockIdx.y * 32;
    const int tx = threadIdx.x & 31, ty = threadIdx.x >> 5;  // 32 x 8
#pragma unroll
    for (int j = 0; j < 32; j += 8)
        t[ty + j][tx] = W[(long)(k0 + ty + j) * N + n0 + tx];
    __syncthreads();
#pragma unroll
    for (int j = 0; j < 32; j += 8)
        Wt[(long)(n0 + ty + j) * K + k0 + tx] = __float2half_rn(t[tx][ty + j]);
}

// ================= fp16-mma GEMM (double-buffered) ============================
// C[M,N] = A[M,K] @ Wt[N,K]^T + bias (+GELU)
// BM=128, BN=128, BK=32; 256 thr (8 warps 2x4); warp tile 64x32.
// AHALF: A is fp16 (direct copy staging); OHALF: write fp16 output.
#define GA_LD2 20

template<bool GELU, bool AHALF, bool OHALF>
__global__ void __launch_bounds__(256)
gemm_h(const void* __restrict__ Av, const __half* __restrict__ Wt,
       const float* __restrict__ bias, void* __restrict__ Cv,
       int M, int N, int K)
{
    __shared__ uint32_t As2[2][128 * GA_LD2];
    __shared__ uint32_t Bs2[2][128 * GA_LD2];

    const float*  Af = (const float*)Av;
    const __half* Ah = (const __half*)Av;
    float*  Cf = (float*)Cv;
    __half* Ch = (__half*)Cv;

    const int tid  = threadIdx.x;
    const int lane = tid & 31;
    const int warp = tid >> 5;
    const int wm = warp >> 2;          // 0..1
    const int wn = warp & 3;           // 0..3
    const int g   = lane >> 2;         // 0..7
    const int tig = lane & 3;          // 0..3

    const int m0 = blockIdx.y * 128;
    const int n0 = blockIdx.x * 128;

    float acc[4][4][4];
#pragma unroll
    for (int i = 0; i < 4; i++)
#pragma unroll
        for (int j = 0; j < 4; j++)
#pragma unroll
            for (int r = 0; r < 4; r++) acc[i][j][r] = 0.0f;

    // staging: 2 threads per row, 16 cols each
    const int arow = tid >> 1, ahalf = tid & 1;
    const float*  Apf = Af + (long)(m0 + arow) * K + ahalf * 16;
    const __half* Aph = Ah + (long)(m0 + arow) * K + ahalf * 16;
    const __half* Bp  = Wt + (long)(n0 + arow) * K + ahalf * 16;

    float4 ar[4];
    uint4  arh[2];
    uint4  br[2];
    if (AHALF) {
#pragma unroll
        for (int j = 0; j < 2; j++) arh[j] = *(const uint4*)(Aph + j * 8);
    } else {
#pragma unroll
        for (int j = 0; j < 4; j++) ar[j] = *(const float4*)(Apf + j * 4);
    }
#pragma unroll
    for (int j = 0; j < 2; j++) br[j] = *(const uint4*)(Bp + j * 8);

    const int NIT = K >> 5;
    for (int it = 0; it < NIT; it++) {
        const int buf = it & 1;
        if (AHALF) {
#pragma unroll
            for (int j = 0; j < 2; j++)
                *(uint4*)&As2[buf][arow * GA_LD2 + ahalf * 8 + 4 * j] = arh[j];
        } else {
#pragma unroll
            for (int j = 0; j < 4; j++) {
                float4 v = ar[j];
                *(uint2*)&As2[buf][arow * GA_LD2 + ahalf * 8 + 2 * j] =
                    make_uint2(pack2h(v.x, v.y), pack2h(v.z, v.w));
            }
        }
#pragma unroll
        for (int j = 0; j < 2; j++)
            *(uint4*)&Bs2[buf][arow * GA_LD2 + ahalf * 8 + 4 * j] = br[j];

        if (it + 1 < NIT) {
            const int k0 = (it + 1) * 32;
            if (AHALF) {
#pragma unroll
                for (int j = 0; j < 2; j++) arh[j] = *(const uint4*)(Aph + k0 + j * 8);
            } else {
#pragma unroll
                for (int j = 0; j < 4; j++) ar[j] = *(const float4*)(Apf + k0 + j * 4);
            }
#pragma unroll
            for (int j = 0; j < 2; j++) br[j] = *(const uint4*)(Bp + k0 + j * 8);
        }
        __syncthreads();

#pragma unroll
        for (int ks = 0; ks < 2; ks++) {
            const int kk2 = ks * 8;
            uint32_t bf[4][2];
#pragma unroll
            for (int nt = 0; nt < 4; nt++) {
                const int nc = wn * 32 + nt * 8 + g;
                bf[nt][0] = Bs2[buf][nc * GA_LD2 + kk2 + tig];
                bf[nt][1] = Bs2[buf][nc * GA_LD2 + kk2 + tig + 4];
            }
#pragma unroll
            for (int mt = 0; mt < 4; mt++) {
                const int row = wm * 64 + mt * 16 + g;
                uint32_t af[4];
                af[0] = As2[buf][row       * GA_LD2 + kk2 + tig];
                af[1] = As2[buf][(row + 8) * GA_LD2 + kk2 + tig];
                af[2] = As2[buf][row       * GA_LD2 + kk2 + tig + 4];
                af[3] = As2[buf][(row + 8) * GA_LD2 + kk2 + tig + 4];
#pragma unroll
                for (int nt = 0; nt < 4; nt++)
                    mma16(acc[mt][nt], af, bf[nt]);
            }
        }
    }

    // epilogue
    const int cb = n0 + wn * 32;
    float2 bv[4];
#pragma unroll
    for (int nt = 0; nt < 4; nt++)
        bv[nt] = *(const float2*)&bias[cb + nt * 8 + 2 * tig];

#pragma unroll
    for (int mt = 0; mt < 4; mt++) {
        const long r1 = m0 + wm * 64 + mt * 16 + g;
        const long r2 = r1 + 8;
#pragma unroll
        for (int nt = 0; nt < 4; nt++) {
            float c0 = acc[mt][nt][0] + bv[nt].x;
            float c1 = acc[mt][nt][1] + bv[nt].y;
            float c2 = acc[mt][nt][2] + bv[nt].x;
            float c3 = acc[mt][nt][3] + bv[nt].y;
            if (GELU) { c0 = gelu_tanh(c0); c1 = gelu_tanh(c1); c2 = gelu_tanh(c2); c3 = gelu_tanh(c3); }
            const long o1 = r1 * N + cb + nt * 8 + 2 * tig;
            const long o2 = r2 * N + cb + nt * 8 + 2 * tig;
            if (OHALF) {
                *(uint32_t*)&Ch[o1] = pack2h(c0, c1);
                *(uint32_t*)&Ch[o2] = pack2h(c2, c3);
            } else {
                *(float2*)&Cf[o1] = make_float2(c0, c1);
                *(float2*)&Cf[o2] = make_float2(c2, c3);
            }
        }
    }
}

// ================= fp16-mma flash attention, register softmax (FA2-style) ======
// All-fp16 inputs/outputs. BM=128 (8 warps), BN=64 keys, d=64.
// Scale folded into fp32 S post-mma. S/P in registers; 2 syncs per tile.
#define FB_LD2 36

__global__ void __launch_bounds__(256)
flash_h(const __half* __restrict__ Q, const __half* __restrict__ K,
        const __half* __restrict__ V, __half* __restrict__ O,
        int ldq, long qbs, int ldk, long kbs, int ldv, long vbs,
        int Skv, float scale)
{
    __shared__ uint32_t Qs2[128 * FB_LD2];
    __shared__ uint32_t Ks2[64 * FB_LD2];
    __shared__ uint32_t Vt2[64 * FB_LD2];
    __half* VtH = (__half*)Vt2;            // [d][72 halves]

    const int tid  = threadIdx.x;
    const int lane = tid & 31;
    const int warp = tid >> 5;
    const int g    = lane >> 2;
    const int tig  = lane & 3;
    const int b = blockIdx.z, h = blockIdx.y;
    const int m0 = blockIdx.x * 128;

    const __half* q = Q + b * qbs + h * D_HEADD;
    const __half* k = K + b * kbs + h * D_HEADD;
    const __half* v = V + b * vbs + h * D_HEADD;

    // ---- stage Q (fp16 direct copy): 2 threads per row, 32 halves each ----
    {
        const int sr = tid >> 1, hf = tid & 1;
        const __half* qrow = q + (long)(m0 + sr) * ldq + hf * 32;
#pragma unroll
        for (int j = 0; j < 4; j++)
            *(uint4*)&Qs2[sr * FB_LD2 + hf * 16 + j * 4] = *(const uint4*)(qrow + j * 8);
    }
    __syncthreads();

    // ---- Q fragments in registers (row = 16*warp + g) ----
    uint32_t qf[4][4];
    {
        const int row = warp * 16 + g;
#pragma unroll
        for (int ks = 0; ks < 4; ks++) {
            qf[ks][0] = Qs2[row       * FB_LD2 + 8 * ks + tig];
            qf[ks][1] = Qs2[(row + 8) * FB_LD2 + 8 * ks + tig];
            qf[ks][2] = Qs2[row       * FB_LD2 + 8 * ks + tig + 4];
            qf[ks][3] = Qs2[(row + 8) * FB_LD2 + 8 * ks + tig + 4];
        }
    }

    float o[8][4];
#pragma unroll
    for (int nt = 0; nt < 8; nt++)
#pragma unroll
        for (int r = 0; r < 4; r++) o[nt][r] = 0.0f;
    float m0r = -1e30f, m1r = -1e30f, l0r = 0.0f, l1r = 0.0f;

    const int ntiles = (Skv + 63) >> 6;
    for (int t = 0; t < ntiles; t++) {
        const int n0t = t * 64;

        // ---- stage K [key][d] (direct copy) and V^T [d][key]: 4 threads/key-row ----
        {
            const int krow = tid >> 2, qtr = tid & 3;
            if (n0t + krow < Skv) {
                const __half* kp = k + (long)(n0t + krow) * ldk + qtr * 16;
                *(uint4*)&Ks2[krow * FB_LD2 + qtr * 8]     = *(const uint4*)kp;
                *(uint4*)&Ks2[krow * FB_LD2 + qtr * 8 + 4] = *(const uint4*)(kp + 8);
                const __half* vp = v + (long)(n0t + krow) * ldv + qtr * 16;
                __half hv[16];
                *(uint4*)&hv[0] = *(const uint4*)vp;
                *(uint4*)&hv[8] = *(const uint4*)(vp + 8);
#pragma unroll
                for (int i = 0; i < 16; i++)
                    VtH[(qtr * 16 + i) * 72 + krow] = hv[i];
            } else {
                const uint4 z = make_uint4(0, 0, 0, 0);
                *(uint4*)&Ks2[krow * FB_LD2 + qtr * 8]     = z;
                *(uint4*)&Ks2[krow * FB_LD2 + qtr * 8 + 4] = z;
                const __half hz = __float2half(0.0f);
#pragma unroll
                for (int i = 0; i < 16; i++)
                    VtH[(qtr * 16 + i) * 72 + krow] = hz;
            }
        }
        __syncthreads();

        // ---- S = Q @ K^T (registers) ----
        float sfr[8][4];
#pragma unroll
        for (int nt = 0; nt < 8; nt++)
#pragma unroll
            for (int r = 0; r < 4; r++) sfr[nt][r] = 0.0f;

#pragma unroll
        for (int ks = 0; ks < 4; ks++) {
            const int kk2 = ks * 8;
#pragma unroll
            for (int nt = 0; nt < 8; nt++) {
                uint32_t bf[2];
                bf[0] = Ks2[(nt * 8 + g) * FB_LD2 + kk2 + tig];
                bf[1] = Ks2[(nt * 8 + g) * FB_LD2 + kk2 + tig + 4];
                mma16(sfr[nt], qf[ks], bf);
            }
        }

        // ---- apply softmax scale in fp32 ----
#pragma unroll
        for (int nt = 0; nt < 8; nt++) {
            sfr[nt][0] *= scale; sfr[nt][1] *= scale;
            sfr[nt][2] *= scale; sfr[nt][3] *= scale;
        }

        // ---- tail mask (by key column) ----
        if (n0t + 64 > Skv) {
#pragma unroll
            for (int nt = 0; nt < 8; nt++) {
                const int c0 = n0t + nt * 8 + 2 * tig;
                if (c0 >= Skv)     { sfr[nt][0] = -1e30f; sfr[nt][2] = -1e30f; }
                if (c0 + 1 >= Skv) { sfr[nt][1] = -1e30f; sfr[nt][3] = -1e30f; }
            }
        }

        // ---- online softmax in registers (rows g and g+8) ----
        float mx0 = -1e30f, mx1 = -1e30f;
#pragma unroll
        for (int nt = 0; nt < 8; nt++) {
            mx0 = fmaxf(mx0, fmaxf(sfr[nt][0], sfr[nt][1]));
            mx1 = fmaxf(mx1, fmaxf(sfr[nt][2], sfr[nt][3]));
        }
        mx0 = fmaxf(mx0, __shfl_xor_sync(0xffffffffu, mx0, 1));
        mx0 = fmaxf(mx0, __shfl_xor_sync(0xffffffffu, mx0, 2));
        mx1 = fmaxf(mx1, __shfl_xor_sync(0xffffffffu, mx1, 1));
        mx1 = fmaxf(mx1, __shfl_xor_sync(0xffffffffu, mx1, 2));

        const float mn0 = fmaxf(m0r, mx0), mn1 = fmaxf(m1r, mx1);
        const float al0 = __expf(m0r - mn0), al1 = __expf(m1r - mn1);
        m0r = mn0; m1r = mn1;

        float s0 = 0.0f, s1 = 0.0f;
#pragma unroll
        for (int nt = 0; nt < 8; nt++) {
            float p0 = __expf(sfr[nt][0] - mn0);
            float p1 = __expf(sfr[nt][1] - mn0);
            float p2 = __expf(sfr[nt][2] - mn1);
            float p3 = __expf(sfr[nt][3] - mn1);
            sfr[nt][0] = p0; sfr[nt][1] = p1; sfr[nt][2] = p2; sfr[nt][3] = p3;
            s0 += p0 + p1; s1 += p2 + p3;
        }
        s0 += __shfl_xor_sync(0xffffffffu, s0, 1);
        s0 += __shfl_xor_sync(0xffffffffu, s0, 2);
        s1 += __shfl_xor_sync(0xffffffffu, s1, 1);
        s1 += __shfl_xor_sync(0xffffffffu, s1, 2);
        l0r = l0r * al0 + s0;
        l1r = l1r * al1 + s1;

#pragma unroll
        for (int nt = 0; nt < 8; nt++) {
            o[nt][0] *= al0; o[nt][1] *= al0;
            o[nt][2] *= al1; o[nt][3] *= al1;
        }

        // ---- O += P @ V : P frags packed directly from S accumulators ----
#pragma unroll
        for (int ks = 0; ks < 4; ks++) {
            uint32_t af[4];
            af[0] = pack2h(sfr[2 * ks][0],     sfr[2 * ks][1]);
            af[1] = pack2h(sfr[2 * ks][2],     sfr[2 * ks][3]);
            af[2] = pack2h(sfr[2 * ks + 1][0], sfr[2 * ks + 1][1]);
            af[3] = pack2h(sfr[2 * ks + 1][2], sfr[2 * ks + 1][3]);
            const int kk2 = ks * 8;
#pragma unroll
            for (int nt = 0; nt < 8; nt++) {
                uint32_t bf[2];
                bf[0] = Vt2[(nt * 8 + g) * FB_LD2 + kk2 + tig];
                bf[1] = Vt2[(nt * 8 + g) * FB_LD2 + kk2 + tig + 4];
                mma16(o[nt], af, bf);
            }
        }
        __syncthreads();   // before next tile overwrites Ks2/Vt2
    }

    // ---- epilogue: normalize and write fp16 ----
    const float i0 = 1.0f / l0r, i1 = 1.0f / l1r;
    const long r1 = (long)b * SEQ + m0 + warp * 16 + g;
    const long r2 = r1 + 8;
#pragma unroll
    for (int nt = 0; nt < 8; nt++) {
        const int col = h * D_HEADD + nt * 8 + 2 * tig;
        *(uint32_t*)&O[r1 * D_EMBED + col] = pack2h(o[nt][0] * i0, o[nt][1] * i0);
        *(uint32_t*)&O[r2 * D_EMBED + col] = pack2h(o[nt][2] * i1, o[nt][3] * i1);
    }
}

// ================= fp32 SGEMM -> fp16 out (small M, kc/vc) =================
__global__ void __launch_bounds__(256, 2)
sgemm_bias_h(const float* __restrict__ A, const float* __restrict__ B,
             const float* __restrict__ bias, __half* __restrict__ C,
             int M, int N, int K)
{
    __shared__ float As[8][128];
    __shared__ float Bs[8][128];
    const int tid = threadIdx.x;
    const int m0 = blockIdx.y * 128;
    const int n0 = blockIdx.x * 128;
    const int tx = tid & 15;
    const int ty = tid >> 4;

    float acc[8][8];
#pragma unroll
    for (int i = 0; i < 8; i++)
#pragma unroll
        for (int j = 0; j < 8; j++) acc[i][j] = 0.0f;

    const int a_row = tid >> 1;
    const int a_col = (tid & 1) * 4;
    const int b_row = tid >> 5;
    const int b_col = (tid & 31) * 4;
    const bool a_valid = (m0 + a_row) < M;
    const float* Aptr = A + (long)(m0 + a_row) * K + a_col;
    const float* Bptr = B + (long)b_row * N + n0 + b_col;

    for (int k0 = 0; k0 < K; k0 += 8) {
        float4 av = a_valid ? *(const float4*)(Aptr + k0) : make_float4(0.f, 0.f, 0.f, 0.f);
        As[a_col + 0][a_row] = av.x;
        As[a_col + 1][a_row] = av.y;
        As[a_col + 2][a_row] = av.z;
        As[a_col + 3][a_row] = av.w;
        *(float4*)&Bs[b_row][b_col] = *(const float4*)(Bptr + (long)k0 * N);
        __syncthreads();
#pragma unroll
        for (int kk = 0; kk < 8; kk++) {
            float ra[8], rb[8];
            *(float4*)&ra[0] = *(const float4*)&As[kk][ty * 8];
            *(float4*)&ra[4] = *(const float4*)&As[kk][ty * 8 + 4];
            *(float4*)&rb[0] = *(const float4*)&Bs[kk][tx * 8];
            *(float4*)&rb[4] = *(const float4*)&Bs[kk][tx * 8 + 4];
#pragma unroll
            for (int i = 0; i < 8; i++)
#pragma unroll
                for (int j = 0; j < 8; j++)
                    acc[i][j] += ra[i] * rb[j];
        }
        __syncthreads();
    }
    float bvv[8];
#pragma unroll
    for (int j = 0; j < 8; j++) bvv[j] = bias[n0 + tx * 8 + j];
#pragma unroll
    for (int i = 0; i < 8; i++) {
        int row = m0 + ty * 8 + i;
        if (row < M) {
            __half* Cp = C + (long)row * N + n0 + tx * 8;
#pragma unroll
            for (int j = 0; j < 4; j++)
                *(uint32_t*)&Cp[2 * j] = pack2h(acc[i][2 * j] + bvv[2 * j],
                                                acc[i][2 * j + 1] + bvv[2 * j + 1]);
        }
    }
}

// ================= fused residual add + LayerNorm =================
__global__ void __launch_bounds__(128)
add_ln(const float* __restrict__ A, const float* __restrict__ R,
       const float* __restrict__ g, const float* __restrict__ beta,
       float* __restrict__ out)
{
    const long row = blockIdx.x;
    const int tid = threadIdx.x;
    const float4 a = *(const float4*)(A + row * D_EMBED + tid * 4);
    const float4 r = *(const float4*)(R + row * D_EMBED + tid * 4);
    float v[4] = {a.x + r.x, a.y + r.y, a.z + r.z, a.w + r.w};

    float s = v[0] + v[1] + v[2] + v[3];
    float ss = v[0]*v[0] + v[1]*v[1] + v[2]*v[2] + v[3]*v[3];
#pragma unroll
    for (int off = 16; off >= 1; off >>= 1) {
        s  += __shfl_xor_sync(0xffffffffu, s,  off);
        ss += __shfl_xor_sync(0xffffffffu, ss, off);
    }
    __shared__ float sred[8];
    const int warp = tid >> 5, lane = tid & 31;
    if (lane == 0) { sred[warp] = s; sred[warp + 4] = ss; }
    __syncthreads();
    s  = sred[0] + sred[1] + sred[2] + sred[3];
    ss = sred[4] + sred[5] + sred[6] + sred[7];

    const float mean = s * (1.0f / D_EMBED);
    const float var  = ss * (1.0f / D_EMBED) - mean * mean;
    const float rstd = rsqrtf(var + 1e-5f);

    const float4 gg = *(const float4*)(g + tid * 4);
    const float4 bb = *(const float4*)(beta + tid * 4);
    float4 o;
    o.x = (v[0] - mean) * rstd * gg.x + bb.x;
    o.y = (v[1] - mean) * rstd * gg.y + bb.y;
    o.z = (v[2] - mean) * rstd * gg.z + bb.z;
    o.w = (v[3] - mean) * rstd * gg.w + bb.w;
    *(float4*)(out + row * D_EMBED + tid * 4) = o;
}

// ================= host =================
extern "C" void kernel_launch(void* const* d_in, const int* in_sizes, int n_in,
                              void* d_out, int out_size)
{
    const float* x        = (const float*)d_in[0];
    const float* y        = (const float*)d_in[1];
    const float* sa_in_w  = (const float*)d_in[2];
    const float* sa_in_b  = (const float*)d_in[3];
    const float* sa_out_w = (const float*)d_in[4];
    const float* sa_out_b = (const float*)d_in[5];
    const float* ca_q_w   = (const float*)d_in[6];
    const float* ca_q_b   = (const float*)d_in[7];
    const float* ca_k_w   = (const float*)d_in[8];
    const float* ca_k_b   = (const float*)d_in[9];
    const float* ca_v_w   = (const float*)d_in[10];
    const float* ca_v_b   = (const float*)d_in[11];
    const float* ca_out_w = (const float*)d_in[12];
    const float* ca_out_b = (const float*)d_in[13];
    const float* ff_w1    = (const float*)d_in[14];
    const float* ff_b1    = (const float*)d_in[15];
    const float* ff_w2    = (const float*)d_in[16];
    const float* ff_b2    = (const float*)d_in[17];
    const float* ln1_g    = (const float*)d_in[18];
    const float* ln1_b    = (const float*)d_in[19];
    const float* ln2_g    = (const float*)d_in[20];
    const float* ln2_b    = (const float*)d_in[21];
    const float* ln3_g    = (const float*)d_in[22];
    const float* ln3_b    = (const float*)d_in[23];
    float* out = (float*)d_out;

    __half *qkvh, *attnh, *qch, *ffh, *kch, *vch, *w16;
    float *proj, *x1, *x2q;
    cudaGetSymbolAddress((void**)&qkvh,  g_qkvh);
    cudaGetSymbolAddress((void**)&attnh, g_attnh);
    cudaGetSymbolAddress((void**)&qch,   g_qch);
    cudaGetSymbolAddress((void**)&ffh,   g_ffh);
    cudaGetSymbolAddress((void**)&kch,   g_kch);
    cudaGetSymbolAddress((void**)&vch,   g_vch);
    cudaGetSymbolAddress((void**)&w16,   g_w16);
    cudaGetSymbolAddress((void**)&proj,  g_proj);
    cudaGetSymbolAddress((void**)&x1,    g_x1);
    cudaGetSymbolAddress((void**)&x2q,   g_x2q);

    // 0. transpose + fp16-convert all big weights: W[K,N] -> Wt[N,K]
    transpose_h<<<dim3(1536/32, 512/32),  256>>>(sa_in_w,  w16 + WOFF_SAIN,  512, 1536);
    transpose_h<<<dim3(512/32,  512/32),  256>>>(sa_out_w, w16 + WOFF_SAOUT, 512, 512);
    transpose_h<<<dim3(512/32,  512/32),  256>>>(ca_q_w,   w16 + WOFF_CAQ,   512, 512);
    transpose_h<<<dim3(512/32,  512/32),  256>>>(ca_out_w, w16 + WOFF_CAOUT, 512, 512);
    transpose_h<<<dim3(2048/32, 512/32),  256>>>(ff_w1,    w16 + WOFF_FF1,   512, 2048);
    transpose_h<<<dim3(512/32,  2048/32), 256>>>(ff_w2,    w16 + WOFF_FF2,   2048, 512);

    // 1. QKV projection (fp32 in, fp16 out): [8192,512] @ [512,1536]
    gemm_h<false, false, true><<<dim3(1536/128, M_ROWS/128), 256>>>(
        x, w16 + WOFF_SAIN, sa_in_b, qkvh, M_ROWS, 3*D_EMBED, D_EMBED);
    // 2. self-attention (all fp16; q|k|v packed, ld = 1536)
    flash_h<<<dim3(SEQ/128, N_HEADS, BATCH), 256>>>(
        qkvh, qkvh + D_EMBED, qkvh + 2*D_EMBED, attnh,
        3*D_EMBED, (long)SEQ * 3*D_EMBED,
        3*D_EMBED, (long)SEQ * 3*D_EMBED,
        3*D_EMBED, (long)SEQ * 3*D_EMBED,
        SEQ, 0.125f);
    // 3. self-attn output projection (fp16 in, fp32 out)
    gemm_h<false, true, false><<<dim3(4, M_ROWS/128), 256>>>(
        attnh, w16 + WOFF_SAOUT, sa_out_b, proj, M_ROWS, D_EMBED, D_EMBED);
    // 4. x1 = LN(x + proj)
    add_ln<<<M_ROWS, 128>>>(x, proj, ln1_g, ln1_b, x1);

    // 5. cross-attn Q projection (fp32 in, fp16 out)
    gemm_h<false, false, true><<<dim3(4, M_ROWS/128), 256>>>(
        x1, w16 + WOFF_CAQ, ca_q_b, qch, M_ROWS, D_EMBED, D_EMBED);
    // 6. cross-attn K/V projections (tiny M; fp32 compute, fp16 out)
    sgemm_bias_h<<<dim3(4, 2), 256>>>(y, ca_k_w, ca_k_b, kch, Y_ROWS, D_EMBED, D_CROSS);
    sgemm_bias_h<<<dim3(4, 2), 256>>>(y, ca_v_w, ca_v_b, vch, Y_ROWS, D_EMBED, D_CROSS);
    // 7. cross-attention (Skv = 77)
    flash_h<<<dim3(SEQ/128, N_HEADS, BATCH), 256>>>(
        qch, kch, vch, attnh,
        D_EMBED, (long)SEQ * D_EMBED,
        D_EMBED, (long)SKV_C * D_EMBED,
        D_EMBED, (long)SKV_C * D_EMBED,
        SKV_C, 0.125f);
    // 8. cross-attn output projection (fp16 in, fp32 out)
    gemm_h<false, true, false><<<dim3(4, M_ROWS/128), 256>>>(
        attnh, w16 + WOFF_CAOUT, ca_out_b, proj, M_ROWS, D_EMBED, D_EMBED);
    // 9. x2 = LN(x1 + proj)
    add_ln<<<M_ROWS, 128>>>(x1, proj, ln2_g, ln2_b, x2q);

    // 10. FF1 + GELU (fp32 in, fp16 out)
    gemm_h<true, false, true><<<dim3(FF_DIM/128, M_ROWS/128), 256>>>(
        x2q, w16 + WOFF_FF1, ff_b1, ffh, M_ROWS, FF_DIM, D_EMBED);
    // 11. FF2 (fp16 in, fp32 out)
    gemm_h<false, true, false><<<dim3(4, M_ROWS/128), 256>>>(
        ffh, w16 + WOFF_FF2, ff_b2, proj, M_ROWS, D_EMBED, FF_DIM);
    // 12. out = LN(x2 + proj)
    add_ln<<<M_ROWS, 128>>>(x2q, proj, ln3_g, ln3_b, out);
}

// round 15
// speedup vs baseline: 4.2830x; 1.2603x over previous
#include <cuda_runtime.h>
#include <cuda_fp16.h>
#include <math.h>
#include <stdint.h>

// ---------------- problem constants ----------------
#define D_EMBED 512
#define N_HEADS 8
#define D_HEADD 64
#define FF_DIM  2048
#define D_CROSS 768
#define BATCH   2
#define SEQ     4096
#define SKV_C   77
#define M_ROWS  (BATCH * SEQ)     // 8192
#define Y_ROWS  (BATCH * SKV_C)   // 154

// ---------------- scratch ----------------
__device__ __half g_qkvh[M_ROWS * 3 * D_EMBED];
__device__ __half g_attnh[M_ROWS * D_EMBED];
__device__ __half g_qch [M_ROWS * D_EMBED];
__device__ __half g_ffh [M_ROWS * FF_DIM];
__device__ __half g_kch [Y_ROWS * D_EMBED];
__device__ __half g_vch [Y_ROWS * D_EMBED];
__device__ float  g_proj[M_ROWS * D_EMBED];
__device__ float  g_x1  [M_ROWS * D_EMBED];
__device__ float  g_x2q [M_ROWS * D_EMBED];

// transposed fp16 weights [N,K]
#define WOFF_SAIN  0
#define WOFF_SAOUT 786432
#define WOFF_CAQ   1048576
#define WOFF_CAOUT 1310720
#define WOFF_FF1   1572864
#define WOFF_FF2   2621440
#define WT_TOTAL   3670016
__device__ __half g_w16[WT_TOTAL];

__device__ __forceinline__ float gelu_tanh(float x) {
    float x3 = x * x * x;
    return 0.5f * x * (1.0f + tanhf(0.7978845608028654f * (x + 0.044715f * x3)));
}

__device__ __forceinline__ uint32_t pack2h(float a, float b) {
    __half2 h = __floats2half2_rn(a, b);
    return *(uint32_t*)&h;
}

__device__ __forceinline__ uint32_t smem_u32(const void* p) {
    uint32_t a;
    asm("{ .reg .u64 t; cvta.to.shared.u64 t, %1; cvt.u32.u64 %0, t; }" : "=r"(a) : "l"(p));
    return a;
}

// fp16 mma m16n8k16, fp32 accum
__device__ __forceinline__ void mma16(float d[4], const uint32_t a[4], const uint32_t b[2]) {
    asm volatile(
        "mma.sync.aligned.m16n8k16.row.col.f32.f16.f16.f32 "
        "{%0,%1,%2,%3}, {%4,%5,%6,%7}, {%8,%9}, {%0,%1,%2,%3};\n"
        : "+f"(d[0]), "+f"(d[1]), "+f"(d[2]), "+f"(d[3])
        : "r"(a[0]), "r"(a[1]), "r"(a[2]), "r"(a[3]), "r"(b[0]), "r"(b[1]));
}

// ================= fused weight transposes (6 segments, 1 launch) =================
struct TPack {
    const float* W[6];
    __half* Wt[6];
    int K[6];
    int N[6];
};

__global__ void __launch_bounds__(256)
transpose_all(TPack p)
{
    const int s = blockIdx.z;
    const int K = p.K[s], N = p.N[s];
    const int n0 = blockIdx.x * 32, k0 = blockIdx.y * 32;
    if (n0 >= N || k0 >= K) return;
    const float* W = p.W[s];
    __half* Wt = p.Wt[s];

    __shared__ float t[32][33];
    const int tx = threadIdx.x & 31, ty = threadIdx.x >> 5;  // 32 x 8
#pragma unroll
    for (int j = 0; j < 32; j += 8)
        t[ty + j][tx] = W[(long)(k0 + ty + j) * N + n0 + tx];
    __syncthreads();
#pragma unroll
    for (int j = 0; j < 32; j += 8)
        Wt[(long)(n0 + ty + j) * K + k0 + tx] = __float2half_rn(t[tx][ty + j]);
}

// ================= fp16-mma GEMM (double-buffered) ============================
// C[M,N] = A[M,K] @ Wt[N,K]^T + bias (+GELU); BM=128, BN=128, BK=32; 256 thr.
#define GA_LD2 20

template<bool GELU, bool AHALF, bool OHALF>
__global__ void __launch_bounds__(256)
gemm_h(const void* __restrict__ Av, const __half* __restrict__ Wt,
       const float* __restrict__ bias, void* __restrict__ Cv,
       int M, int N, int K)
{
    __shared__ uint32_t As2[2][128 * GA_LD2];
    __shared__ uint32_t Bs2[2][128 * GA_LD2];

    const float*  Af = (const float*)Av;
    const __half* Ah = (const __half*)Av;
    float*  Cf = (float*)Cv;
    __half* Ch = (__half*)Cv;

    const int tid  = threadIdx.x;
    const int lane = tid & 31;
    const int warp = tid >> 5;
    const int wm = warp >> 2;
    const int wn = warp & 3;
    const int g   = lane >> 2;
    const int tig = lane & 3;

    const int m0 = blockIdx.y * 128;
    const int n0 = blockIdx.x * 128;

    float acc[4][4][4];
#pragma unroll
    for (int i = 0; i < 4; i++)
#pragma unroll
        for (int j = 0; j < 4; j++)
#pragma unroll
            for (int r = 0; r < 4; r++) acc[i][j][r] = 0.0f;

    const int arow = tid >> 1, ahalf = tid & 1;
    const float*  Apf = Af + (long)(m0 + arow) * K + ahalf * 16;
    const __half* Aph = Ah + (long)(m0 + arow) * K + ahalf * 16;
    const __half* Bp  = Wt + (long)(n0 + arow) * K + ahalf * 16;

    float4 ar[4];
    uint4  arh[2];
    uint4  br[2];
    if (AHALF) {
#pragma unroll
        for (int j = 0; j < 2; j++) arh[j] = *(const uint4*)(Aph + j * 8);
    } else {
#pragma unroll
        for (int j = 0; j < 4; j++) ar[j] = *(const float4*)(Apf + j * 4);
    }
#pragma unroll
    for (int j = 0; j < 2; j++) br[j] = *(const uint4*)(Bp + j * 8);

    const int NIT = K >> 5;
    for (int it = 0; it < NIT; it++) {
        const int buf = it & 1;
        if (AHALF) {
#pragma unroll
            for (int j = 0; j < 2; j++)
                *(uint4*)&As2[buf][arow * GA_LD2 + ahalf * 8 + 4 * j] = arh[j];
        } else {
#pragma unroll
            for (int j = 0; j < 4; j++) {
                float4 v = ar[j];
                *(uint2*)&As2[buf][arow * GA_LD2 + ahalf * 8 + 2 * j] =
                    make_uint2(pack2h(v.x, v.y), pack2h(v.z, v.w));
            }
        }
#pragma unroll
        for (int j = 0; j < 2; j++)
            *(uint4*)&Bs2[buf][arow * GA_LD2 + ahalf * 8 + 4 * j] = br[j];

        if (it + 1 < NIT) {
            const int k0 = (it + 1) * 32;
            if (AHALF) {
#pragma unroll
                for (int j = 0; j < 2; j++) arh[j] = *(const uint4*)(Aph + k0 + j * 8);
            } else {
#pragma unroll
                for (int j = 0; j < 4; j++) ar[j] = *(const float4*)(Apf + k0 + j * 4);
            }
#pragma unroll
            for (int j = 0; j < 2; j++) br[j] = *(const uint4*)(Bp + k0 + j * 8);
        }
        __syncthreads();

#pragma unroll
        for (int ks = 0; ks < 2; ks++) {
            const int kk2 = ks * 8;
            uint32_t bf[4][2];
#pragma unroll
            for (int nt = 0; nt < 4; nt++) {
                const int nc = wn * 32 + nt * 8 + g;
                bf[nt][0] = Bs2[buf][nc * GA_LD2 + kk2 + tig];
                bf[nt][1] = Bs2[buf][nc * GA_LD2 + kk2 + tig + 4];
            }
#pragma unroll
            for (int mt = 0; mt < 4; mt++) {
                const int row = wm * 64 + mt * 16 + g;
                uint32_t af[4];
                af[0] = As2[buf][row       * GA_LD2 + kk2 + tig];
                af[1] = As2[buf][(row + 8) * GA_LD2 + kk2 + tig];
                af[2] = As2[buf][row       * GA_LD2 + kk2 + tig + 4];
                af[3] = As2[buf][(row + 8) * GA_LD2 + kk2 + tig + 4];
#pragma unroll
                for (int nt = 0; nt < 4; nt++)
                    mma16(acc[mt][nt], af, bf[nt]);
            }
        }
    }

    const int cb = n0 + wn * 32;
    float2 bv[4];
#pragma unroll
    for (int nt = 0; nt < 4; nt++)
        bv[nt] = *(const float2*)&bias[cb + nt * 8 + 2 * tig];

#pragma unroll
    for (int mt = 0; mt < 4; mt++) {
        const long r1 = m0 + wm * 64 + mt * 16 + g;
        const long r2 = r1 + 8;
#pragma unroll
        for (int nt = 0; nt < 4; nt++) {
            float c0 = acc[mt][nt][0] + bv[nt].x;
            float c1 = acc[mt][nt][1] + bv[nt].y;
            float c2 = acc[mt][nt][2] + bv[nt].x;
            float c3 = acc[mt][nt][3] + bv[nt].y;
            if (GELU) { c0 = gelu_tanh(c0); c1 = gelu_tanh(c1); c2 = gelu_tanh(c2); c3 = gelu_tanh(c3); }
            const long o1 = r1 * N + cb + nt * 8 + 2 * tig;
            const long o2 = r2 * N + cb + nt * 8 + 2 * tig;
            if (OHALF) {
                *(uint32_t*)&Ch[o1] = pack2h(c0, c1);
                *(uint32_t*)&Ch[o2] = pack2h(c2, c3);
            } else {
                *(float2*)&Cf[o1] = make_float2(c0, c1);
                *(float2*)&Cf[o2] = make_float2(c2, c3);
            }
        }
    }
}

// ================= fp16-mma flash attention (pipelined K/V) ======================
// BM=128 (8 warps), BN=64 keys, d=64. Register softmax.
// Dynamic smem: Qs[128*36] | Ks[2][64*36] | Vt[2][64*36]  (uint32 units)
#define FB_LD2 36
#define FQ_OFF 0
#define FK_OFF 4608
#define FV_OFF 9216
#define FBUF   2304
#define FLASH_SMEM ((4608 + 4 * 2304) * 4)   // 55296 B

__global__ void __launch_bounds__(256)
flash_h(const __half* __restrict__ Q, const __half* __restrict__ K,
        const __half* __restrict__ V, __half* __restrict__ O,
        int ldq, long qbs, int ldk, long kbs, int ldv, long vbs,
        int Skv, float scale)
{
    extern __shared__ uint32_t sm[];
    uint32_t* Qs2 = sm + FQ_OFF;

    const int tid  = threadIdx.x;
    const int lane = tid & 31;
    const int warp = tid >> 5;
    const int g    = lane >> 2;
    const int tig  = lane & 3;
    const int b = blockIdx.z, h = blockIdx.y;
    const int m0 = blockIdx.x * 128;

    const __half* q = Q + b * qbs + h * D_HEADD;
    const __half* k = K + b * kbs + h * D_HEADD;
    const __half* v = V + b * vbs + h * D_HEADD;

    // ---- stage Q (direct copy) ----
    {
        const int sr = tid >> 1, hf = tid & 1;
        const __half* qrow = q + (long)(m0 + sr) * ldq + hf * 32;
#pragma unroll
        for (int j = 0; j < 4; j++)
            *(uint4*)&Qs2[sr * FB_LD2 + hf * 16 + j * 4] = *(const uint4*)(qrow + j * 8);
    }

    const int krow = tid >> 2, qtr = tid & 3;  // K/V staging: 4 threads per key-row
    const int ntiles = (Skv + 63) >> 6;

    // ---- prologue: cp.async K(0) + register-load V(0) ----
    uint4 vr0, vr1;
    {
        uint32_t sa = smem_u32(&sm[FK_OFF + krow * FB_LD2 + qtr * 8]);
        if (krow < Skv) {
            const __half* kp = k + (long)krow * ldk + qtr * 16;
            asm volatile("cp.async.cg.shared.global [%0], [%1], 16;\n" :: "r"(sa), "l"(kp) : "memory");
            asm volatile("cp.async.cg.shared.global [%0], [%1], 16;\n" :: "r"(sa + 16), "l"(kp + 8) : "memory");
            const __half* vp = v + (long)krow * ldv + qtr * 16;
            vr0 = *(const uint4*)vp;
            vr1 = *(const uint4*)(vp + 8);
        } else {
            const uint4 z = make_uint4(0, 0, 0, 0);
            *(uint4*)&sm[FK_OFF + krow * FB_LD2 + qtr * 8]     = z;
            *(uint4*)&sm[FK_OFF + krow * FB_LD2 + qtr * 8 + 4] = z;
            vr0 = z; vr1 = z;
        }
        asm volatile("cp.async.commit_group;\n" ::: "memory");
    }
    __syncthreads();   // Q visible

    // ---- Q fragments in registers ----
    uint32_t qf[4][4];
    {
        const int row = warp * 16 + g;
#pragma unroll
        for (int ks = 0; ks < 4; ks++) {
            qf[ks][0] = Qs2[row       * FB_LD2 + 8 * ks + tig];
            qf[ks][1] = Qs2[(row + 8) * FB_LD2 + 8 * ks + tig];
            qf[ks][2] = Qs2[row       * FB_LD2 + 8 * ks + tig + 4];
            qf[ks][3] = Qs2[(row + 8) * FB_LD2 + 8 * ks + tig + 4];
        }
    }

    float o[8][4];
#pragma unroll
    for (int nt = 0; nt < 8; nt++)
#pragma unroll
        for (int r = 0; r < 4; r++) o[nt][r] = 0.0f;
    float m0r = -1e30f, m1r = -1e30f, l0r = 0.0f, l1r = 0.0f;

    for (int t = 0; t < ntiles; t++) {
        const int n0t = t * 64, buf = t & 1;
        uint32_t* Ks2 = sm + FK_OFF + buf * FBUF;
        uint32_t* Vt2 = sm + FV_OFF + buf * FBUF;
        __half*   VtH = (__half*)Vt2;          // [d][72 halves]

        asm volatile("cp.async.wait_group 0;\n" ::: "memory");   // K(t) landed

        // scatter V(t) from registers (transpose to [d][key])
        {
            __half hv[16];
            *(uint4*)&hv[0] = vr0;
            *(uint4*)&hv[8] = vr1;
#pragma unroll
            for (int i = 0; i < 16; i++)
                VtH[(qtr * 16 + i) * 72 + krow] = hv[i];
        }
        __syncthreads();   // K(t)/V(t) visible everywhere; compute(t-1) done

        // prefetch tile t+1 (after barrier: safe to touch buf^1)
        if (t + 1 < ntiles) {
            const int nb = buf ^ 1, nk = (t + 1) * 64 + krow;
            uint32_t sa = smem_u32(&sm[FK_OFF + nb * FBUF + krow * FB_LD2 + qtr * 8]);
            if (nk < Skv) {
                const __half* kp = k + (long)nk * ldk + qtr * 16;
                asm volatile("cp.async.cg.shared.global [%0], [%1], 16;\n" :: "r"(sa), "l"(kp) : "memory");
                asm volatile("cp.async.cg.shared.global [%0], [%1], 16;\n" :: "r"(sa + 16), "l"(kp + 8) : "memory");
                const __half* vp = v + (long)nk * ldv + qtr * 16;
                vr0 = *(const uint4*)vp;
                vr1 = *(const uint4*)(vp + 8);
            } else {
                const uint4 z = make_uint4(0, 0, 0, 0);
                *(uint4*)&sm[FK_OFF + nb * FBUF + krow * FB_LD2 + qtr * 8]     = z;
                *(uint4*)&sm[FK_OFF + nb * FBUF + krow * FB_LD2 + qtr * 8 + 4] = z;
                vr0 = z; vr1 = z;
            }
            asm volatile("cp.async.commit_group;\n" ::: "memory");
        }

        // ---- S = Q @ K^T ----
        float sfr[8][4];
#pragma unroll
        for (int nt = 0; nt < 8; nt++)
#pragma unroll
            for (int r = 0; r < 4; r++) sfr[nt][r] = 0.0f;

#pragma unroll
        for (int ks = 0; ks < 4; ks++) {
            const int kk2 = ks * 8;
#pragma unroll
            for (int nt = 0; nt < 8; nt++) {
                uint32_t bf[2];
                bf[0] = Ks2[(nt * 8 + g) * FB_LD2 + kk2 + tig];
                bf[1] = Ks2[(nt * 8 + g) * FB_LD2 + kk2 + tig + 4];
                mma16(sfr[nt], qf[ks], bf);
            }
        }

        // scale in fp32
#pragma unroll
        for (int nt = 0; nt < 8; nt++) {
            sfr[nt][0] *= scale; sfr[nt][1] *= scale;
            sfr[nt][2] *= scale; sfr[nt][3] *= scale;
        }

        // tail mask
        if (n0t + 64 > Skv) {
#pragma unroll
            for (int nt = 0; nt < 8; nt++) {
                const int c0 = n0t + nt * 8 + 2 * tig;
                if (c0 >= Skv)     { sfr[nt][0] = -1e30f; sfr[nt][2] = -1e30f; }
                if (c0 + 1 >= Skv) { sfr[nt][1] = -1e30f; sfr[nt][3] = -1e30f; }
            }
        }

        // ---- online softmax in registers ----
        float mx0 = -1e30f, mx1 = -1e30f;
#pragma unroll
        for (int nt = 0; nt < 8; nt++) {
            mx0 = fmaxf(mx0, fmaxf(sfr[nt][0], sfr[nt][1]));
            mx1 = fmaxf(mx1, fmaxf(sfr[nt][2], sfr[nt][3]));
        }
        mx0 = fmaxf(mx0, __shfl_xor_sync(0xffffffffu, mx0, 1));
        mx0 = fmaxf(mx0, __shfl_xor_sync(0xffffffffu, mx0, 2));
        mx1 = fmaxf(mx1, __shfl_xor_sync(0xffffffffu, mx1, 1));
        mx1 = fmaxf(mx1, __shfl_xor_sync(0xffffffffu, mx1, 2));

        const float mn0 = fmaxf(m0r, mx0), mn1 = fmaxf(m1r, mx1);
        const float al0 = __expf(m0r - mn0), al1 = __expf(m1r - mn1);
        m0r = mn0; m1r = mn1;

        float s0 = 0.0f, s1 = 0.0f;
#pragma unroll
        for (int nt = 0; nt < 8; nt++) {
            float p0 = __expf(sfr[nt][0] - mn0);
            float p1 = __expf(sfr[nt][1] - mn0);
            float p2 = __expf(sfr[nt][2] - mn1);
            float p3 = __expf(sfr[nt][3] - mn1);
            sfr[nt][0] = p0; sfr[nt][1] = p1; sfr[nt][2] = p2; sfr[nt][3] = p3;
            s0 += p0 + p1; s1 += p2 + p3;
        }
        s0 += __shfl_xor_sync(0xffffffffu, s0, 1);
        s0 += __shfl_xor_sync(0xffffffffu, s0, 2);
        s1 += __shfl_xor_sync(0xffffffffu, s1, 1);
        s1 += __shfl_xor_sync(0xffffffffu, s1, 2);
        l0r = l0r * al0 + s0;
        l1r = l1r * al1 + s1;

#pragma unroll
        for (int nt = 0; nt < 8; nt++) {
            o[nt][0] *= al0; o[nt][1] *= al0;
            o[nt][2] *= al1; o[nt][3] *= al1;
        }

        // ---- O += P @ V ----
#pragma unroll
        for (int ks = 0; ks < 4; ks++) {
            uint32_t af[4];
            af[0] = pack2h(sfr[2 * ks][0],     sfr[2 * ks][1]);
            af[1] = pack2h(sfr[2 * ks][2],     sfr[2 * ks][3]);
            af[2] = pack2h(sfr[2 * ks + 1][0], sfr[2 * ks + 1][1]);
            af[3] = pack2h(sfr[2 * ks + 1][2], sfr[2 * ks + 1][3]);
            const int kk2 = ks * 8;
#pragma unroll
            for (int nt = 0; nt < 8; nt++) {
                uint32_t bf[2];
                bf[0] = Vt2[(nt * 8 + g) * FB_LD2 + kk2 + tig];
                bf[1] = Vt2[(nt * 8 + g) * FB_LD2 + kk2 + tig + 4];
                mma16(o[nt], af, bf);
            }
        }
        // no trailing sync: next iteration's wait/scatter is ordered by the barrier above
    }

    // ---- epilogue ----
    const float i0 = 1.0f / l0r, i1 = 1.0f / l1r;
    const long r1 = (long)b * SEQ + m0 + warp * 16 + g;
    const long r2 = r1 + 8;
#pragma unroll
    for (int nt = 0; nt < 8; nt++) {
        const int col = h * D_HEADD + nt * 8 + 2 * tig;
        *(uint32_t*)&O[r1 * D_EMBED + col] = pack2h(o[nt][0] * i0, o[nt][1] * i0);
        *(uint32_t*)&O[r2 * D_EMBED + col] = pack2h(o[nt][2] * i1, o[nt][3] * i1);
    }
}

// ================= fused kc/vc SGEMM (fp32 SIMT, double-buffered) =================
// grid (8, 2): x 0-3 -> kc tiles, 4-7 -> vc tiles. M=154, N=512, K=768.
__global__ void __launch_bounds__(256)
sgemm_kv(const float* __restrict__ Y,
         const float* __restrict__ Wk, const float* __restrict__ bk, __half* __restrict__ Ck,
         const float* __restrict__ Wv, const float* __restrict__ bv, __half* __restrict__ Cv)
{
    const bool isv = blockIdx.x >= 4;
    const float* B    = isv ? Wv : Wk;
    const float* bias = isv ? bv : bk;
    __half* C         = isv ? Cv : Ck;
    const int n0 = (blockIdx.x & 3) * 128;
    const int m0 = blockIdx.y * 128;
    const int M = Y_ROWS, N = 512, K = D_CROSS;

    __shared__ float As[2][8][128];
    __shared__ float Bs[2][8][128];
    const int tid = threadIdx.x;
    const int tx = tid & 15;
    const int ty = tid >> 4;

    float acc[8][8];
#pragma unroll
    for (int i = 0; i < 8; i++)
#pragma unroll
        for (int j = 0; j < 8; j++) acc[i][j] = 0.0f;

    const int a_row = tid >> 1;
    const int a_col = (tid & 1) * 4;
    const int b_row = tid >> 5;
    const int b_col = (tid & 31) * 4;
    const bool a_valid = (m0 + a_row) < M;
    const float* Aptr = Y + (long)(m0 + a_row) * K + a_col;
    const float* Bptr = B + (long)b_row * N + n0 + b_col;

    float4 av = a_valid ? *(const float4*)Aptr : make_float4(0.f, 0.f, 0.f, 0.f);
    float4 bv4 = *(const float4*)Bptr;

    const int NIT = K >> 3;   // 96
    for (int it = 0; it < NIT; it++) {
        const int buf = it & 1;
        As[buf][a_col + 0][a_row] = av.x;
        As[buf][a_col + 1][a_row] = av.y;
        As[buf][a_col + 2][a_row] = av.z;
        As[buf][a_col + 3][a_row] = av.w;
        *(float4*)&Bs[buf][b_row][b_col] = bv4;

        if (it + 1 < NIT) {
            const int k0 = (it + 1) * 8;
            av = a_valid ? *(const float4*)(Aptr + k0) : make_float4(0.f, 0.f, 0.f, 0.f);
            bv4 = *(const float4*)(Bptr + (long)k0 * N);
        }
        __syncthreads();

#pragma unroll
        for (int kk = 0; kk < 8; kk++) {
            float ra[8], rb[8];
            *(float4*)&ra[0] = *(const float4*)&As[buf][kk][ty * 8];
            *(float4*)&ra[4] = *(const float4*)&As[buf][kk][ty * 8 + 4];
            *(float4*)&rb[0] = *(const float4*)&Bs[buf][kk][tx * 8];
            *(float4*)&rb[4] = *(const float4*)&Bs[buf][kk][tx * 8 + 4];
#pragma unroll
            for (int i = 0; i < 8; i++)
#pragma unroll
                for (int j = 0; j < 8; j++)
                    acc[i][j] += ra[i] * rb[j];
        }
    }

    float bvv[8];
#pragma unroll
    for (int j = 0; j < 8; j++) bvv[j] = bias[n0 + tx * 8 + j];
#pragma unroll
    for (int i = 0; i < 8; i++) {
        int row = m0 + ty * 8 + i;
        if (row < M) {
            __half* Cp = C + (long)row * N + n0 + tx * 8;
#pragma unroll
            for (int j = 0; j < 4; j++)
                *(uint32_t*)&Cp[2 * j] = pack2h(acc[i][2 * j] + bvv[2 * j],
                                                acc[i][2 * j + 1] + bvv[2 * j + 1]);
        }
    }
}

// ================= fused residual add + LayerNorm =================
__global__ void __launch_bounds__(128)
add_ln(const float* __restrict__ A, const float* __restrict__ R,
       const float* __restrict__ g, const float* __restrict__ beta,
       float* __restrict__ out)
{
    const long row = blockIdx.x;
    const int tid = threadIdx.x;
    const float4 a = *(const float4*)(A + row * D_EMBED + tid * 4);
    const float4 r = *(const float4*)(R + row * D_EMBED + tid * 4);
    float v[4] = {a.x + r.x, a.y + r.y, a.z + r.z, a.w + r.w};

    float s = v[0] + v[1] + v[2] + v[3];
    float ss = v[0]*v[0] + v[1]*v[1] + v[2]*v[2] + v[3]*v[3];
#pragma unroll
    for (int off = 16; off >= 1; off >>= 1) {
        s  += __shfl_xor_sync(0xffffffffu, s,  off);
        ss += __shfl_xor_sync(0xffffffffu, ss, off);
    }
    __shared__ float sred[8];
    const int warp = tid >> 5, lane = tid & 31;
    if (lane == 0) { sred[warp] = s; sred[warp + 4] = ss; }
    __syncthreads();
    s  = sred[0] + sred[1] + sred[2] + sred[3];
    ss = sred[4] + sred[5] + sred[6] + sred[7];

    const float mean = s * (1.0f / D_EMBED);
    const float var  = ss * (1.0f / D_EMBED) - mean * mean;
    const float rstd = rsqrtf(var + 1e-5f);

    const float4 gg = *(const float4*)(g + tid * 4);
    const float4 bb = *(const float4*)(beta + tid * 4);
    float4 o;
    o.x = (v[0] - mean) * rstd * gg.x + bb.x;
    o.y = (v[1] - mean) * rstd * gg.y + bb.y;
    o.z = (v[2] - mean) * rstd * gg.z + bb.z;
    o.w = (v[3] - mean) * rstd * gg.w + bb.w;
    *(float4*)(out + row * D_EMBED + tid * 4) = o;
}

// ================= host =================
extern "C" void kernel_launch(void* const* d_in, const int* in_sizes, int n_in,
                              void* d_out, int out_size)
{
    const float* x        = (const float*)d_in[0];
    const float* y        = (const float*)d_in[1];
    const float* sa_in_w  = (const float*)d_in[2];
    const float* sa_in_b  = (const float*)d_in[3];
    const float* sa_out_w = (const float*)d_in[4];
    const float* sa_out_b = (const float*)d_in[5];
    const float* ca_q_w   = (const float*)d_in[6];
    const float* ca_q_b   = (const float*)d_in[7];
    const float* ca_k_w   = (const float*)d_in[8];
    const float* ca_k_b   = (const float*)d_in[9];
    const float* ca_v_w   = (const float*)d_in[10];
    const float* ca_v_b   = (const float*)d_in[11];
    const float* ca_out_w = (const float*)d_in[12];
    const float* ca_out_b = (const float*)d_in[13];
    const float* ff_w1    = (const float*)d_in[14];
    const float* ff_b1    = (const float*)d_in[15];
    const float* ff_w2    = (const float*)d_in[16];
    const float* ff_b2    = (const float*)d_in[17];
    const float* ln1_g    = (const float*)d_in[18];
    const float* ln1_b    = (const float*)d_in[19];
    const float* ln2_g    = (const float*)d_in[20];
    const float* ln2_b    = (const float*)d_in[21];
    const float* ln3_g    = (const float*)d_in[22];
    const float* ln3_b    = (const float*)d_in[23];
    float* out = (float*)d_out;

    __half *qkvh, *attnh, *qch, *ffh, *kch, *vch, *w16;
    float *proj, *x1, *x2q;
    cudaGetSymbolAddress((void**)&qkvh,  g_qkvh);
    cudaGetSymbolAddress((void**)&attnh, g_attnh);
    cudaGetSymbolAddress((void**)&qch,   g_qch);
    cudaGetSymbolAddress((void**)&ffh,   g_ffh);
    cudaGetSymbolAddress((void**)&kch,   g_kch);
    cudaGetSymbolAddress((void**)&vch,   g_vch);
    cudaGetSymbolAddress((void**)&w16,   g_w16);
    cudaGetSymbolAddress((void**)&proj,  g_proj);
    cudaGetSymbolAddress((void**)&x1,    g_x1);
    cudaGetSymbolAddress((void**)&x2q,   g_x2q);

    cudaFuncSetAttribute(flash_h, cudaFuncAttributeMaxDynamicSharedMemorySize, FLASH_SMEM);

    // 0. all six weight transposes in one launch
    TPack tp;
    tp.W[0] = sa_in_w;  tp.Wt[0] = w16 + WOFF_SAIN;  tp.K[0] = 512;  tp.N[0] = 1536;
    tp.W[1] = sa_out_w; tp.Wt[1] = w16 + WOFF_SAOUT; tp.K[1] = 512;  tp.N[1] = 512;
    tp.W[2] = ca_q_w;   tp.Wt[2] = w16 + WOFF_CAQ;   tp.K[2] = 512;  tp.N[2] = 512;
    tp.W[3] = ca_out_w; tp.Wt[3] = w16 + WOFF_CAOUT; tp.K[3] = 512;  tp.N[3] = 512;
    tp.W[4] = ff_w1;    tp.Wt[4] = w16 + WOFF_FF1;   tp.K[4] = 512;  tp.N[4] = 2048;
    tp.W[5] = ff_w2;    tp.Wt[5] = w16 + WOFF_FF2;   tp.K[5] = 2048; tp.N[5] = 512;
    transpose_all<<<dim3(64, 64, 6), 256>>>(tp);

    // cross-attn K/V projections (independent of everything above; run early)
    sgemm_kv<<<dim3(8, 2), 256>>>(y, ca_k_w, ca_k_b, kch, ca_v_w, ca_v_b, vch);

    // 1. QKV projection (fp32 in, fp16 out)
    gemm_h<false, false, true><<<dim3(1536/128, M_ROWS/128), 256>>>(
        x, w16 + WOFF_SAIN, sa_in_b, qkvh, M_ROWS, 3*D_EMBED, D_EMBED);
    // 2. self-attention
    flash_h<<<dim3(SEQ/128, N_HEADS, BATCH), 256, FLASH_SMEM>>>(
        qkvh, qkvh + D_EMBED, qkvh + 2*D_EMBED, attnh,
        3*D_EMBED, (long)SEQ * 3*D_EMBED,
        3*D_EMBED, (long)SEQ * 3*D_EMBED,
        3*D_EMBED, (long)SEQ * 3*D_EMBED,
        SEQ, 0.125f);
    // 3. self-attn output projection (fp16 in, fp32 out)
    gemm_h<false, true, false><<<dim3(4, M_ROWS/128), 256>>>(
        attnh, w16 + WOFF_SAOUT, sa_out_b, proj, M_ROWS, D_EMBED, D_EMBED);
    // 4. x1 = LN(x + proj)
    add_ln<<<M_ROWS, 128>>>(x, proj, ln1_g, ln1_b, x1);

    // 5. cross-attn Q projection (fp32 in, fp16 out)
    gemm_h<false, false, true><<<dim3(4, M_ROWS/128), 256>>>(
        x1, w16 + WOFF_CAQ, ca_q_b, qch, M_ROWS, D_EMBED, D_EMBED);
    // 7. cross-attention (Skv = 77)
    flash_h<<<dim3(SEQ/128, N_HEADS, BATCH), 256, FLASH_SMEM>>>(
        qch, kch, vch, attnh,
        D_EMBED, (long)SEQ * D_EMBED,
        D_EMBED, (long)SKV_C * D_EMBED,
        D_EMBED, (long)SKV_C * D_EMBED,
        SKV_C, 0.125f);
    // 8. cross-attn output projection (fp16 in, fp32 out)
    gemm_h<false, true, false><<<dim3(4, M_ROWS/128), 256>>>(
        attnh, w16 + WOFF_CAOUT, ca_out_b, proj, M_ROWS, D_EMBED, D_EMBED);
    // 9. x2 = LN(x1 + proj)
    add_ln<<<M_ROWS, 128>>>(x1, proj, ln2_g, ln2_b, x2q);

    // 10. FF1 + GELU (fp32 in, fp16 out)
    gemm_h<true, false, true><<<dim3(FF_DIM/128, M_ROWS/128), 256>>>(
        x2q, w16 + WOFF_FF1, ff_b1, ffh, M_ROWS, FF_DIM, D_EMBED);
    // 11. FF2 (fp16 in, fp32 out)
    gemm_h<false, true, false><<<dim3(4, M_ROWS/128), 256>>>(
        ffh, w16 + WOFF_FF2, ff_b2, proj, M_ROWS, D_EMBED, FF_DIM);
    // 12. out = LN(x2 + proj)
    add_ln<<<M_ROWS, 128>>>(x2q, proj, ln3_g, ln3_b, out);
}

// round 16
// speedup vs baseline: 4.7408x; 1.1069x over previous
#include <cuda_runtime.h>
#include <cuda_fp16.h>
#include <math.h>
#include <stdint.h>

// ---------------- problem constants ----------------
#define D_EMBED 512
#define N_HEADS 8
#define D_HEADD 64
#define FF_DIM  2048
#define D_CROSS 768
#define BATCH   2
#define SEQ     4096
#define SKV_C   77
#define M_ROWS  (BATCH * SEQ)     // 8192
#define Y_ROWS  (BATCH * SKV_C)   // 154

// ---------------- scratch ----------------
__device__ __half g_qkvh[M_ROWS * 3 * D_EMBED];
__device__ __half g_attnh[M_ROWS * D_EMBED];
__device__ __half g_qch [M_ROWS * D_EMBED];
__device__ __half g_ffh [M_ROWS * FF_DIM];
__device__ __half g_kch [Y_ROWS * D_EMBED];
__device__ __half g_vch [Y_ROWS * D_EMBED];
__device__ float  g_proj[M_ROWS * D_EMBED];
__device__ float  g_x1  [M_ROWS * D_EMBED];
__device__ float  g_x2q [M_ROWS * D_EMBED];

// transposed fp16 weights [N,K]
#define WOFF_SAIN  0
#define WOFF_SAOUT 786432
#define WOFF_CAQ   1048576
#define WOFF_CAOUT 1310720
#define WOFF_FF1   1572864
#define WOFF_FF2   2621440
#define WT_TOTAL   3670016
__device__ __half g_w16[WT_TOTAL];

__device__ __forceinline__ float gelu_tanh(float x) {
    float x3 = x * x * x;
    return 0.5f * x * (1.0f + tanhf(0.7978845608028654f * (x + 0.044715f * x3)));
}

__device__ __forceinline__ uint32_t pack2h(float a, float b) {
    __half2 h = __floats2half2_rn(a, b);
    return *(uint32_t*)&h;
}

__device__ __forceinline__ uint32_t smem_u32(const void* p) {
    uint32_t a;
    asm("{ .reg .u64 t; cvta.to.shared.u64 t, %1; cvt.u32.u64 %0, t; }" : "=r"(a) : "l"(p));
    return a;
}

// fp16 mma m16n8k16, fp32 accum
__device__ __forceinline__ void mma16(float d[4], const uint32_t a[4], const uint32_t b[2]) {
    asm volatile(
        "mma.sync.aligned.m16n8k16.row.col.f32.f16.f16.f32 "
        "{%0,%1,%2,%3}, {%4,%5,%6,%7}, {%8,%9}, {%0,%1,%2,%3};\n"
        : "+f"(d[0]), "+f"(d[1]), "+f"(d[2]), "+f"(d[3])
        : "r"(a[0]), "r"(a[1]), "r"(a[2]), "r"(a[3]), "r"(b[0]), "r"(b[1]));
}

__device__ __forceinline__ void ldsm4(uint32_t r[4], uint32_t a) {
    asm volatile("ldmatrix.sync.aligned.m8n8.x4.shared.b16 {%0,%1,%2,%3}, [%4];"
        : "=r"(r[0]), "=r"(r[1]), "=r"(r[2]), "=r"(r[3]) : "r"(a));
}
__device__ __forceinline__ void ldsm4t(uint32_t r[4], uint32_t a) {
    asm volatile("ldmatrix.sync.aligned.m8n8.x4.trans.shared.b16 {%0,%1,%2,%3}, [%4];"
        : "=r"(r[0]), "=r"(r[1]), "=r"(r[2]), "=r"(r[3]) : "r"(a));
}

#define CP16(dst, src, pred) \
    asm volatile("cp.async.cg.shared.global [%0], [%1], 16, %2;\n" \
        :: "r"(dst), "l"(src), "r"((pred) ? 16 : 0) : "memory")

// ================= fused weight transposes (6 segments, 1 launch) =================
struct TPack {
    const float* W[6];
    __half* Wt[6];
    int K[6];
    int N[6];
};

__global__ void __launch_bounds__(256)
transpose_all(TPack p)
{
    const int s = blockIdx.z;
    const int K = p.K[s], N = p.N[s];
    const int n0 = blockIdx.x * 32, k0 = blockIdx.y * 32;
    if (n0 >= N || k0 >= K) return;
    const float* W = p.W[s];
    __half* Wt = p.Wt[s];

    __shared__ float t[32][33];
    const int tx = threadIdx.x & 31, ty = threadIdx.x >> 5;
#pragma unroll
    for (int j = 0; j < 32; j += 8)
        t[ty + j][tx] = W[(long)(k0 + ty + j) * N + n0 + tx];
    __syncthreads();
#pragma unroll
    for (int j = 0; j < 32; j += 8)
        Wt[(long)(n0 + ty + j) * K + k0 + tx] = __float2half_rn(t[tx][ty + j]);
}

// ================= fp16-mma GEMM (double-buffered, ldmatrix frags) ============
// C[M,N] = A[M,K] @ Wt[N,K]^T + bias (+GELU); BM=128, BN=128, BK=32; 256 thr.
#define GA_LD2 20

template<bool GELU, bool AHALF, bool OHALF>
__global__ void __launch_bounds__(256)
gemm_h(const void* __restrict__ Av, const __half* __restrict__ Wt,
       const float* __restrict__ bias, void* __restrict__ Cv,
       int M, int N, int K)
{
    __shared__ uint32_t As2[2][128 * GA_LD2];
    __shared__ uint32_t Bs2[2][128 * GA_LD2];

    const float*  Af = (const float*)Av;
    const __half* Ah = (const __half*)Av;
    float*  Cf = (float*)Cv;
    __half* Ch = (__half*)Cv;

    const int tid  = threadIdx.x;
    const int lane = tid & 31;
    const int warp = tid >> 5;
    const int wm = warp >> 2;
    const int wn = warp & 3;
    const int g   = lane >> 2;
    const int tig = lane & 3;
    const int mq  = lane >> 3;   // matrix index 0..3
    const int mr  = lane & 7;    // row within matrix

    const int m0 = blockIdx.y * 128;
    const int n0 = blockIdx.x * 128;

    float acc[4][4][4];
#pragma unroll
    for (int i = 0; i < 4; i++)
#pragma unroll
        for (int j = 0; j < 4; j++)
#pragma unroll
            for (int r = 0; r < 4; r++) acc[i][j][r] = 0.0f;

    const int arow = tid >> 1, ahalf = tid & 1;
    const float*  Apf = Af + (long)(m0 + arow) * K + ahalf * 16;
    const __half* Aph = Ah + (long)(m0 + arow) * K + ahalf * 16;
    const __half* Bp  = Wt + (long)(n0 + arow) * K + ahalf * 16;

    // ldmatrix per-lane base offsets (bytes)
    const uint32_t asb0 = smem_u32(&As2[0][0]);
    const uint32_t bsb0 = smem_u32(&Bs2[0][0]);
    const uint32_t a_off = ((wm * 64 + (mq & 1) * 8 + mr) * GA_LD2 + (mq >> 1) * 4) * 4;
    const uint32_t b_off = ((wn * 32 + (mq >> 1) * 8 + mr) * GA_LD2 + (mq & 1) * 4) * 4;

    float4 ar[4];
    uint4  arh[2];
    uint4  br[2];
    if (AHALF) {
#pragma unroll
        for (int j = 0; j < 2; j++) arh[j] = *(const uint4*)(Aph + j * 8);
    } else {
#pragma unroll
        for (int j = 0; j < 4; j++) ar[j] = *(const float4*)(Apf + j * 4);
    }
#pragma unroll
    for (int j = 0; j < 2; j++) br[j] = *(const uint4*)(Bp + j * 8);

    const int NIT = K >> 5;
    for (int it = 0; it < NIT; it++) {
        const int buf = it & 1;
        if (AHALF) {
#pragma unroll
            for (int j = 0; j < 2; j++)
                *(uint4*)&As2[buf][arow * GA_LD2 + ahalf * 8 + 4 * j] = arh[j];
        } else {
#pragma unroll
            for (int j = 0; j < 4; j++) {
                float4 v = ar[j];
                *(uint2*)&As2[buf][arow * GA_LD2 + ahalf * 8 + 2 * j] =
                    make_uint2(pack2h(v.x, v.y), pack2h(v.z, v.w));
            }
        }
#pragma unroll
        for (int j = 0; j < 2; j++)
            *(uint4*)&Bs2[buf][arow * GA_LD2 + ahalf * 8 + 4 * j] = br[j];

        if (it + 1 < NIT) {
            const int k0 = (it + 1) * 32;
            if (AHALF) {
#pragma unroll
                for (int j = 0; j < 2; j++) arh[j] = *(const uint4*)(Aph + k0 + j * 8);
            } else {
#pragma unroll
                for (int j = 0; j < 4; j++) ar[j] = *(const float4*)(Apf + k0 + j * 4);
            }
#pragma unroll
            for (int j = 0; j < 2; j++) br[j] = *(const uint4*)(Bp + k0 + j * 8);
        }
        __syncthreads();

        const uint32_t ab = asb0 + buf * (128 * GA_LD2 * 4) + a_off;
        const uint32_t bb = bsb0 + buf * (128 * GA_LD2 * 4) + b_off;
#pragma unroll
        for (int ks = 0; ks < 2; ks++) {
            uint32_t bf[2][4];   // [p][4] = {bf[2p][0], bf[2p][1], bf[2p+1][0], bf[2p+1][1]}
#pragma unroll
            for (int p = 0; p < 2; p++)
                ldsm4(bf[p], bb + (p * 16 * GA_LD2 + ks * 8) * 4);
            uint32_t af[4][4];
#pragma unroll
            for (int mt = 0; mt < 4; mt++)
                ldsm4(af[mt], ab + (mt * 16 * GA_LD2 + ks * 8) * 4);
#pragma unroll
            for (int mt = 0; mt < 4; mt++)
#pragma unroll
                for (int nt = 0; nt < 4; nt++)
                    mma16(acc[mt][nt], af[mt], &bf[nt >> 1][(nt & 1) * 2]);
        }
    }

    const int cb = n0 + wn * 32;
    float2 bv[4];
#pragma unroll
    for (int nt = 0; nt < 4; nt++)
        bv[nt] = *(const float2*)&bias[cb + nt * 8 + 2 * tig];

#pragma unroll
    for (int mt = 0; mt < 4; mt++) {
        const long r1 = m0 + wm * 64 + mt * 16 + g;
        const long r2 = r1 + 8;
#pragma unroll
        for (int nt = 0; nt < 4; nt++) {
            float c0 = acc[mt][nt][0] + bv[nt].x;
            float c1 = acc[mt][nt][1] + bv[nt].y;
            float c2 = acc[mt][nt][2] + bv[nt].x;
            float c3 = acc[mt][nt][3] + bv[nt].y;
            if (GELU) { c0 = gelu_tanh(c0); c1 = gelu_tanh(c1); c2 = gelu_tanh(c2); c3 = gelu_tanh(c3); }
            const long o1 = r1 * N + cb + nt * 8 + 2 * tig;
            const long o2 = r2 * N + cb + nt * 8 + 2 * tig;
            if (OHALF) {
                *(uint32_t*)&Ch[o1] = pack2h(c0, c1);
                *(uint32_t*)&Ch[o2] = pack2h(c2, c3);
            } else {
                *(float2*)&Cf[o1] = make_float2(c0, c1);
                *(float2*)&Cf[o2] = make_float2(c2, c3);
            }
        }
    }
}

// ================= fp16-mma flash attention (cp.async + ldmatrix) ===============
// BM=128 (8 warps), BN=64 keys, d=64. Register softmax.
// Dynamic smem (uint32 words): Qs[128*36] | Ks[2][64*36] | Vs[2][64*36]
#define FB_LD2 36
#define FQ_OFF 0
#define FK_OFF 4608
#define FV_OFF 9216
#define FBUF   2304
#define FLASH_SMEM ((4608 + 4 * 2304) * 4)   // 55296 B

__global__ void __launch_bounds__(256)
flash_h(const __half* __restrict__ Q, const __half* __restrict__ K,
        const __half* __restrict__ V, __half* __restrict__ O,
        int ldq, long qbs, int ldk, long kbs, int ldv, long vbs,
        int Skv, float scale)
{
    extern __shared__ uint32_t sm[];
    uint32_t* Qs2 = sm + FQ_OFF;

    const int tid  = threadIdx.x;
    const int lane = tid & 31;
    const int warp = tid >> 5;
    const int g    = lane >> 2;
    const int tig  = lane & 3;
    const int mq   = lane >> 3;
    const int mr   = lane & 7;
    const int b = blockIdx.z, h = blockIdx.y;
    const int m0 = blockIdx.x * 128;

    const __half* q = Q + b * qbs + h * D_HEADD;
    const __half* k = K + b * kbs + h * D_HEADD;
    const __half* v = V + b * vbs + h * D_HEADD;

    // ---- stage Q (direct copy) ----
    {
        const int sr = tid >> 1, hf = tid & 1;
        const __half* qrow = q + (long)(m0 + sr) * ldq + hf * 32;
#pragma unroll
        for (int j = 0; j < 4; j++)
            *(uint4*)&Qs2[sr * FB_LD2 + hf * 16 + j * 4] = *(const uint4*)(qrow + j * 8);
    }

    const int krow = tid >> 2, qtr = tid & 3;  // staging: 4 threads per key-row
    const int ntiles = (Skv + 63) >> 6;
    const uint32_t kb0 = smem_u32(sm + FK_OFF);
    const uint32_t vb0 = smem_u32(sm + FV_OFF);

    // ---- prologue: cp.async K(0)+V(0) ----
    {
        const bool val = krow < Skv;
        uint32_t ka = kb0 + (krow * FB_LD2 + qtr * 8) * 4;
        uint32_t va = vb0 + (krow * FB_LD2 + qtr * 8) * 4;
        const __half* kp = k + (long)krow * ldk + qtr * 16;
        const __half* vp = v + (long)krow * ldv + qtr * 16;
        CP16(ka,      kp,     val);
        CP16(ka + 16, kp + 8, val);
        CP16(va,      vp,     val);
        CP16(va + 16, vp + 8, val);
        asm volatile("cp.async.commit_group;\n" ::: "memory");
    }
    __syncthreads();   // Q visible

    // ---- Q fragments ----
    uint32_t qf[4][4];
    {
        const int row = warp * 16 + g;
#pragma unroll
        for (int ks = 0; ks < 4; ks++) {
            qf[ks][0] = Qs2[row       * FB_LD2 + 8 * ks + tig];
            qf[ks][1] = Qs2[(row + 8) * FB_LD2 + 8 * ks + tig];
            qf[ks][2] = Qs2[row       * FB_LD2 + 8 * ks + tig + 4];
            qf[ks][3] = Qs2[(row + 8) * FB_LD2 + 8 * ks + tig + 4];
        }
    }

    // ldmatrix per-lane base offsets (bytes)
    // K (no-trans): matrices (nt=2p+(mq>>1), khalf=mq&1); row = pair-block row + nt*8
    const uint32_t k_off = (((mq >> 1) * 8 + mr) * FB_LD2 + (mq & 1) * 4) * 4;
    // V (trans): matrices (key-half=mq&1, nt=2p+(mq>>1)); row = key row
    const uint32_t v_off = (((mq & 1) * 8 + mr) * FB_LD2 + (mq >> 1) * 4) * 4;

    float o[8][4];
#pragma unroll
    for (int nt = 0; nt < 8; nt++)
#pragma unroll
        for (int r = 0; r < 4; r++) o[nt][r] = 0.0f;
    float m0r = -1e30f, m1r = -1e30f, l0r = 0.0f, l1r = 0.0f;

    for (int t = 0; t < ntiles; t++) {
        const int n0t = t * 64, buf = t & 1;
        const uint32_t kbB = kb0 + buf * (FBUF * 4) + k_off;
        const uint32_t vbB = vb0 + buf * (FBUF * 4) + v_off;

        asm volatile("cp.async.wait_group 0;\n" ::: "memory");
        __syncthreads();   // tile t visible; compute(t-1) done

        // prefetch t+1
        if (t + 1 < ntiles) {
            const int nb = buf ^ 1, nk = (t + 1) * 64 + krow;
            const bool val = nk < Skv;
            uint32_t ka = kb0 + (nb * FBUF + krow * FB_LD2 + qtr * 8) * 4;
            uint32_t va = vb0 + (nb * FBUF + krow * FB_LD2 + qtr * 8) * 4;
            const __half* kp = k + (long)nk * ldk + qtr * 16;
            const __half* vp = v + (long)nk * ldv + qtr * 16;
            CP16(ka,      kp,     val);
            CP16(ka + 16, kp + 8, val);
            CP16(va,      vp,     val);
            CP16(va + 16, vp + 8, val);
            asm volatile("cp.async.commit_group;\n" ::: "memory");
        }

        // ---- S = Q @ K^T ----
        float sfr[8][4];
#pragma unroll
        for (int nt = 0; nt < 8; nt++)
#pragma unroll
            for (int r = 0; r < 4; r++) sfr[nt][r] = 0.0f;

#pragma unroll
        for (int ks = 0; ks < 4; ks++) {
#pragma unroll
            for (int p = 0; p < 4; p++) {
                uint32_t bf4[4];
                ldsm4(bf4, kbB + (p * 16 * FB_LD2 + ks * 8) * 4);
                mma16(sfr[2 * p],     qf[ks], &bf4[0]);
                mma16(sfr[2 * p + 1], qf[ks], &bf4[2]);
            }
        }

        // scale in fp32
#pragma unroll
        for (int nt = 0; nt < 8; nt++) {
            sfr[nt][0] *= scale; sfr[nt][1] *= scale;
            sfr[nt][2] *= scale; sfr[nt][3] *= scale;
        }

        // tail mask
        if (n0t + 64 > Skv) {
#pragma unroll
            for (int nt = 0; nt < 8; nt++) {
                const int c0 = n0t + nt * 8 + 2 * tig;
                if (c0 >= Skv)     { sfr[nt][0] = -1e30f; sfr[nt][2] = -1e30f; }
                if (c0 + 1 >= Skv) { sfr[nt][1] = -1e30f; sfr[nt][3] = -1e30f; }
            }
        }

        // ---- online softmax ----
        float mx0 = -1e30f, mx1 = -1e30f;
#pragma unroll
        for (int nt = 0; nt < 8; nt++) {
            mx0 = fmaxf(mx0, fmaxf(sfr[nt][0], sfr[nt][1]));
            mx1 = fmaxf(mx1, fmaxf(sfr[nt][2], sfr[nt][3]));
        }
        mx0 = fmaxf(mx0, __shfl_xor_sync(0xffffffffu, mx0, 1));
        mx0 = fmaxf(mx0, __shfl_xor_sync(0xffffffffu, mx0, 2));
        mx1 = fmaxf(mx1, __shfl_xor_sync(0xffffffffu, mx1, 1));
        mx1 = fmaxf(mx1, __shfl_xor_sync(0xffffffffu, mx1, 2));

        const float mn0 = fmaxf(m0r, mx0), mn1 = fmaxf(m1r, mx1);
        const float al0 = __expf(m0r - mn0), al1 = __expf(m1r - mn1);
        m0r = mn0; m1r = mn1;

        float s0 = 0.0f, s1 = 0.0f;
#pragma unroll
        for (int nt = 0; nt < 8; nt++) {
            float p0 = __expf(sfr[nt][0] - mn0);
            float p1 = __expf(sfr[nt][1] - mn0);
            float p2 = __expf(sfr[nt][2] - mn1);
            float p3 = __expf(sfr[nt][3] - mn1);
            sfr[nt][0] = p0; sfr[nt][1] = p1; sfr[nt][2] = p2; sfr[nt][3] = p3;
            s0 += p0 + p1; s1 += p2 + p3;
        }
        s0 += __shfl_xor_sync(0xffffffffu, s0, 1);
        s0 += __shfl_xor_sync(0xffffffffu, s0, 2);
        s1 += __shfl_xor_sync(0xffffffffu, s1, 1);
        s1 += __shfl_xor_sync(0xffffffffu, s1, 2);
        l0r = l0r * al0 + s0;
        l1r = l1r * al1 + s1;

#pragma unroll
        for (int nt = 0; nt < 8; nt++) {
            o[nt][0] *= al0; o[nt][1] *= al0;
            o[nt][2] *= al1; o[nt][3] *= al1;
        }

        // ---- O += P @ V (ldmatrix.trans on natural-layout V) ----
#pragma unroll
        for (int ks = 0; ks < 4; ks++) {
            uint32_t af[4];
            af[0] = pack2h(sfr[2 * ks][0],     sfr[2 * ks][1]);
            af[1] = pack2h(sfr[2 * ks][2],     sfr[2 * ks][3]);
            af[2] = pack2h(sfr[2 * ks + 1][0], sfr[2 * ks + 1][1]);
            af[3] = pack2h(sfr[2 * ks + 1][2], sfr[2 * ks + 1][3]);
#pragma unroll
            for (int p = 0; p < 4; p++) {
                uint32_t bv4[4];
                ldsm4t(bv4, vbB + (ks * 16 * FB_LD2 + p * 8) * 4);
                mma16(o[2 * p],     af, &bv4[0]);
                mma16(o[2 * p + 1], af, &bv4[2]);
            }
        }
    }

    // ---- epilogue ----
    const float i0 = 1.0f / l0r, i1 = 1.0f / l1r;
    const long r1 = (long)b * SEQ + m0 + warp * 16 + g;
    const long r2 = r1 + 8;
#pragma unroll
    for (int nt = 0; nt < 8; nt++) {
        const int col = h * D_HEADD + nt * 8 + 2 * tig;
        *(uint32_t*)&O[r1 * D_EMBED + col] = pack2h(o[nt][0] * i0, o[nt][1] * i0);
        *(uint32_t*)&O[r2 * D_EMBED + col] = pack2h(o[nt][2] * i1, o[nt][3] * i1);
    }
}

// ================= fused kc/vc SGEMM (fp32 SIMT, double-buffered) =================
__global__ void __launch_bounds__(256)
sgemm_kv(const float* __restrict__ Y,
         const float* __restrict__ Wk, const float* __restrict__ bk, __half* __restrict__ Ck,
         const float* __restrict__ Wv, const float* __restrict__ bv, __half* __restrict__ Cv)
{
    const bool isv = blockIdx.x >= 4;
    const float* B    = isv ? Wv : Wk;
    const float* bias = isv ? bv : bk;
    __half* C         = isv ? Cv : Ck;
    const int n0 = (blockIdx.x & 3) * 128;
    const int m0 = blockIdx.y * 128;
    const int M = Y_ROWS, N = 512, K = D_CROSS;

    __shared__ float As[2][8][128];
    __shared__ float Bs[2][8][128];
    const int tid = threadIdx.x;
    const int tx = tid & 15;
    const int ty = tid >> 4;

    float acc[8][8];
#pragma unroll
    for (int i = 0; i < 8; i++)
#pragma unroll
        for (int j = 0; j < 8; j++) acc[i][j] = 0.0f;

    const int a_row = tid >> 1;
    const int a_col = (tid & 1) * 4;
    const int b_row = tid >> 5;
    const int b_col = (tid & 31) * 4;
    const bool a_valid = (m0 + a_row) < M;
    const float* Aptr = Y + (long)(m0 + a_row) * K + a_col;
    const float* Bptr = B + (long)b_row * N + n0 + b_col;

    float4 av = a_valid ? *(const float4*)Aptr : make_float4(0.f, 0.f, 0.f, 0.f);
    float4 bv4 = *(const float4*)Bptr;

    const int NIT = K >> 3;
    for (int it = 0; it < NIT; it++) {
        const int buf = it & 1;
        As[buf][a_col + 0][a_row] = av.x;
        As[buf][a_col + 1][a_row] = av.y;
        As[buf][a_col + 2][a_row] = av.z;
        As[buf][a_col + 3][a_row] = av.w;
        *(float4*)&Bs[buf][b_row][b_col] = bv4;

        if (it + 1 < NIT) {
            const int k0 = (it + 1) * 8;
            av = a_valid ? *(const float4*)(Aptr + k0) : make_float4(0.f, 0.f, 0.f, 0.f);
            bv4 = *(const float4*)(Bptr + (long)k0 * N);
        }
        __syncthreads();

#pragma unroll
        for (int kk = 0; kk < 8; kk++) {
            float ra[8], rb[8];
            *(float4*)&ra[0] = *(const float4*)&As[buf][kk][ty * 8];
            *(float4*)&ra[4] = *(const float4*)&As[buf][kk][ty * 8 + 4];
            *(float4*)&rb[0] = *(const float4*)&Bs[buf][kk][tx * 8];
            *(float4*)&rb[4] = *(const float4*)&Bs[buf][kk][tx * 8 + 4];
#pragma unroll
            for (int i = 0; i < 8; i++)
#pragma unroll
                for (int j = 0; j < 8; j++)
                    acc[i][j] += ra[i] * rb[j];
        }
    }

    float bvv[8];
#pragma unroll
    for (int j = 0; j < 8; j++) bvv[j] = bias[n0 + tx * 8 + j];
#pragma unroll
    for (int i = 0; i < 8; i++) {
        int row = m0 + ty * 8 + i;
        if (row < M) {
            __half* Cp = C + (long)row * N + n0 + tx * 8;
#pragma unroll
            for (int j = 0; j < 4; j++)
                *(uint32_t*)&Cp[2 * j] = pack2h(acc[i][2 * j] + bvv[2 * j],
                                                acc[i][2 * j + 1] + bvv[2 * j + 1]);
        }
    }
}

// ================= fused residual add + LayerNorm =================
__global__ void __launch_bounds__(128)
add_ln(const float* __restrict__ A, const float* __restrict__ R,
       const float* __restrict__ g, const float* __restrict__ beta,
       float* __restrict__ out)
{
    const long row = blockIdx.x;
    const int tid = threadIdx.x;
    const float4 a = *(const float4*)(A + row * D_EMBED + tid * 4);
    const float4 r = *(const float4*)(R + row * D_EMBED + tid * 4);
    float v[4] = {a.x + r.x, a.y + r.y, a.z + r.z, a.w + r.w};

    float s = v[0] + v[1] + v[2] + v[3];
    float ss = v[0]*v[0] + v[1]*v[1] + v[2]*v[2] + v[3]*v[3];
#pragma unroll
    for (int off = 16; off >= 1; off >>= 1) {
        s  += __shfl_xor_sync(0xffffffffu, s,  off);
        ss += __shfl_xor_sync(0xffffffffu, ss, off);
    }
    __shared__ float sred[8];
    const int warp = tid >> 5, lane = tid & 31;
    if (lane == 0) { sred[warp] = s; sred[warp + 4] = ss; }
    __syncthreads();
    s  = sred[0] + sred[1] + sred[2] + sred[3];
    ss = sred[4] + sred[5] + sred[6] + sred[7];

    const float mean = s * (1.0f / D_EMBED);
    const float var  = ss * (1.0f / D_EMBED) - mean * mean;
    const float rstd = rsqrtf(var + 1e-5f);

    const float4 gg = *(const float4*)(g + tid * 4);
    const float4 bb = *(const float4*)(beta + tid * 4);
    float4 o;
    o.x = (v[0] - mean) * rstd * gg.x + bb.x;
    o.y = (v[1] - mean) * rstd * gg.y + bb.y;
    o.z = (v[2] - mean) * rstd * gg.z + bb.z;
    o.w = (v[3] - mean) * rstd * gg.w + bb.w;
    *(float4*)(out + row * D_EMBED + tid * 4) = o;
}

// ================= host =================
extern "C" void kernel_launch(void* const* d_in, const int* in_sizes, int n_in,
                              void* d_out, int out_size)
{
    const float* x        = (const float*)d_in[0];
    const float* y        = (const float*)d_in[1];
    const float* sa_in_w  = (const float*)d_in[2];
    const float* sa_in_b  = (const float*)d_in[3];
    const float* sa_out_w = (const float*)d_in[4];
    const float* sa_out_b = (const float*)d_in[5];
    const float* ca_q_w   = (const float*)d_in[6];
    const float* ca_q_b   = (const float*)d_in[7];
    const float* ca_k_w   = (const float*)d_in[8];
    const float* ca_k_b   = (const float*)d_in[9];
    const float* ca_v_w   = (const float*)d_in[10];
    const float* ca_v_b   = (const float*)d_in[11];
    const float* ca_out_w = (const float*)d_in[12];
    const float* ca_out_b = (const float*)d_in[13];
    const float* ff_w1    = (const float*)d_in[14];
    const float* ff_b1    = (const float*)d_in[15];
    const float* ff_w2    = (const float*)d_in[16];
    const float* ff_b2    = (const float*)d_in[17];
    const float* ln1_g    = (const float*)d_in[18];
    const float* ln1_b    = (const float*)d_in[19];
    const float* ln2_g    = (const float*)d_in[20];
    const float* ln2_b    = (const float*)d_in[21];
    const float* ln3_g    = (const float*)d_in[22];
    const float* ln3_b    = (const float*)d_in[23];
    float* out = (float*)d_out;

    __half *qkvh, *attnh, *qch, *ffh, *kch, *vch, *w16;
    float *proj, *x1, *x2q;
    cudaGetSymbolAddress((void**)&qkvh,  g_qkvh);
    cudaGetSymbolAddress((void**)&attnh, g_attnh);
    cudaGetSymbolAddress((void**)&qch,   g_qch);
    cudaGetSymbolAddress((void**)&ffh,   g_ffh);
    cudaGetSymbolAddress((void**)&kch,   g_kch);
    cudaGetSymbolAddress((void**)&vch,   g_vch);
    cudaGetSymbolAddress((void**)&w16,   g_w16);
    cudaGetSymbolAddress((void**)&proj,  g_proj);
    cudaGetSymbolAddress((void**)&x1,    g_x1);
    cudaGetSymbolAddress((void**)&x2q,   g_x2q);

    cudaFuncSetAttribute(flash_h, cudaFuncAttributeMaxDynamicSharedMemorySize, FLASH_SMEM);

    // 0. all six weight transposes in one launch
    TPack tp;
    tp.W[0] = sa_in_w;  tp.Wt[0] = w16 + WOFF_SAIN;  tp.K[0] = 512;  tp.N[0] = 1536;
    tp.W[1] = sa_out_w; tp.Wt[1] = w16 + WOFF_SAOUT; tp.K[1] = 512;  tp.N[1] = 512;
    tp.W[2] = ca_q_w;   tp.Wt[2] = w16 + WOFF_CAQ;   tp.K[2] = 512;  tp.N[2] = 512;
    tp.W[3] = ca_out_w; tp.Wt[3] = w16 + WOFF_CAOUT; tp.K[3] = 512;  tp.N[3] = 512;
    tp.W[4] = ff_w1;    tp.Wt[4] = w16 + WOFF_FF1;   tp.K[4] = 512;  tp.N[4] = 2048;
    tp.W[5] = ff_w2;    tp.Wt[5] = w16 + WOFF_FF2;   tp.K[5] = 2048; tp.N[5] = 512;
    transpose_all<<<dim3(64, 64, 6), 256>>>(tp);

    // cross-attn K/V projections
    sgemm_kv<<<dim3(8, 2), 256>>>(y, ca_k_w, ca_k_b, kch, ca_v_w, ca_v_b, vch);

    // 1. QKV projection (fp32 in, fp16 out)
    gemm_h<false, false, true><<<dim3(1536/128, M_ROWS/128), 256>>>(
        x, w16 + WOFF_SAIN, sa_in_b, qkvh, M_ROWS, 3*D_EMBED, D_EMBED);
    // 2. self-attention
    flash_h<<<dim3(SEQ/128, N_HEADS, BATCH), 256, FLASH_SMEM>>>(
        qkvh, qkvh + D_EMBED, qkvh + 2*D_EMBED, attnh,
        3*D_EMBED, (long)SEQ * 3*D_EMBED,
        3*D_EMBED, (long)SEQ * 3*D_EMBED,
        3*D_EMBED, (long)SEQ * 3*D_EMBED,
        SEQ, 0.125f);
    // 3. self-attn output projection (fp16 in, fp32 out)
    gemm_h<false, true, false><<<dim3(4, M_ROWS/128), 256>>>(
        attnh, w16 + WOFF_SAOUT, sa_out_b, proj, M_ROWS, D_EMBED, D_EMBED);
    // 4. x1 = LN(x + proj)
    add_ln<<<M_ROWS, 128>>>(x, proj, ln1_g, ln1_b, x1);

    // 5. cross-attn Q projection (fp32 in, fp16 out)
    gemm_h<false, false, true><<<dim3(4, M_ROWS/128), 256>>>(
        x1, w16 + WOFF_CAQ, ca_q_b, qch, M_ROWS, D_EMBED, D_EMBED);
    // 7. cross-attention (Skv = 77)
    flash_h<<<dim3(SEQ/128, N_HEADS, BATCH), 256, FLASH_SMEM>>>(
        qch, kch, vch, attnh,
        D_EMBED, (long)SEQ * D_EMBED,
        D_EMBED, (long)SKV_C * D_EMBED,
        D_EMBED, (long)SKV_C * D_EMBED,
        SKV_C, 0.125f);
    // 8. cross-attn output projection (fp16 in, fp32 out)
    gemm_h<false, true, false><<<dim3(4, M_ROWS/128), 256>>>(
        attnh, w16 + WOFF_CAOUT, ca_out_b, proj, M_ROWS, D_EMBED, D_EMBED);
    // 9. x2 = LN(x1 + proj)
    add_ln<<<M_ROWS, 128>>>(x1, proj, ln2_g, ln2_b, x2q);

    // 10. FF1 + GELU (fp32 in, fp16 out)
    gemm_h<true, false, true><<<dim3(FF_DIM/128, M_ROWS/128), 256>>>(
        x2q, w16 + WOFF_FF1, ff_b1, ffh, M_ROWS, FF_DIM, D_EMBED);
    // 11. FF2 (fp16 in, fp32 out)
    gemm_h<false, true, false><<<dim3(4, M_ROWS/128), 256>>>(
        ffh, w16 + WOFF_FF2, ff_b2, proj, M_ROWS, D_EMBED, FF_DIM);
    // 12. out = LN(x2 + proj)
    add_ln<<<M_ROWS, 128>>>(x2q, proj, ln3_g, ln3_b, out);
}

// round 17
// speedup vs baseline: 5.1748x; 1.0915x over previous
#include <cuda_runtime.h>
#include <cuda_fp16.h>
#include <math.h>
#include <stdint.h>

// ---------------- problem constants ----------------
#define D_EMBED 512
#define N_HEADS 8
#define D_HEADD 64
#define FF_DIM  2048
#define D_CROSS 768
#define BATCH   2
#define SEQ     4096
#define SKV_C   77
#define M_ROWS  (BATCH * SEQ)     // 8192
#define Y_ROWS  (BATCH * SKV_C)   // 154

// ---------------- scratch ----------------
__device__ __half g_qkvh[M_ROWS * 3 * D_EMBED];
__device__ __half g_attnh[M_ROWS * D_EMBED];
__device__ __half g_qch [M_ROWS * D_EMBED];
__device__ __half g_ffh [M_ROWS * FF_DIM];
__device__ __half g_kch [Y_ROWS * D_EMBED];
__device__ __half g_vch [Y_ROWS * D_EMBED];
__device__ __half g_xh  [M_ROWS * D_EMBED];      // fp16 copy of x
__device__ __half g_x1h [M_ROWS * D_EMBED];      // fp16 copy of x1
__device__ __half g_x2qh[M_ROWS * D_EMBED];      // fp16 copy of x2
__device__ float  g_proj[M_ROWS * D_EMBED];
__device__ float  g_x1  [M_ROWS * D_EMBED];
__device__ float  g_x2q [M_ROWS * D_EMBED];

// transposed fp16 weights [N,K]
#define WOFF_SAIN  0
#define WOFF_SAOUT 786432
#define WOFF_CAQ   1048576
#define WOFF_CAOUT 1310720
#define WOFF_FF1   1572864
#define WOFF_FF2   2621440
#define WT_TOTAL   3670016
__device__ __half g_w16[WT_TOTAL];

__device__ __forceinline__ float gelu_tanh(float x) {
    float x3 = x * x * x;
    return 0.5f * x * (1.0f + tanhf(0.7978845608028654f * (x + 0.044715f * x3)));
}

__device__ __forceinline__ uint32_t pack2h(float a, float b) {
    __half2 h = __floats2half2_rn(a, b);
    return *(uint32_t*)&h;
}

__device__ __forceinline__ uint32_t smem_u32(const void* p) {
    uint32_t a;
    asm("{ .reg .u64 t; cvta.to.shared.u64 t, %1; cvt.u32.u64 %0, t; }" : "=r"(a) : "l"(p));
    return a;
}

// fp16 mma m16n8k16, fp32 accum
__device__ __forceinline__ void mma16(float d[4], const uint32_t a[4], const uint32_t b[2]) {
    asm volatile(
        "mma.sync.aligned.m16n8k16.row.col.f32.f16.f16.f32 "
        "{%0,%1,%2,%3}, {%4,%5,%6,%7}, {%8,%9}, {%0,%1,%2,%3};\n"
        : "+f"(d[0]), "+f"(d[1]), "+f"(d[2]), "+f"(d[3])
        : "r"(a[0]), "r"(a[1]), "r"(a[2]), "r"(a[3]), "r"(b[0]), "r"(b[1]));
}

__device__ __forceinline__ void ldsm4(uint32_t r[4], uint32_t a) {
    asm volatile("ldmatrix.sync.aligned.m8n8.x4.shared.b16 {%0,%1,%2,%3}, [%4];"
        : "=r"(r[0]), "=r"(r[1]), "=r"(r[2]), "=r"(r[3]) : "r"(a));
}
__device__ __forceinline__ void ldsm4t(uint32_t r[4], uint32_t a) {
    asm volatile("ldmatrix.sync.aligned.m8n8.x4.trans.shared.b16 {%0,%1,%2,%3}, [%4];"
        : "=r"(r[0]), "=r"(r[1]), "=r"(r[2]), "=r"(r[3]) : "r"(a));
}

#define CP16(dst, src, pred) \
    asm volatile("cp.async.cg.shared.global [%0], [%1], 16, %2;\n" \
        :: "r"(dst), "l"(src), "r"((pred) ? 16 : 0) : "memory")
#define CP_COMMIT()  asm volatile("cp.async.commit_group;\n" ::: "memory")
#define CP_WAIT0()   asm volatile("cp.async.wait_group 0;\n" ::: "memory")

// ================= x -> fp16 =================
__global__ void __launch_bounds__(256)
f2h(const float* __restrict__ X, __half* __restrict__ Xh, int n8)
{
    const long i = (long)(blockIdx.x * 256 + threadIdx.x);
    if (i < n8) {
        float4 a = *(const float4*)(X + i * 8);
        float4 b = *(const float4*)(X + i * 8 + 4);
        uint4 o;
        o.x = pack2h(a.x, a.y); o.y = pack2h(a.z, a.w);
        o.z = pack2h(b.x, b.y); o.w = pack2h(b.z, b.w);
        *(uint4*)(Xh + i * 8) = o;
    }
}

// ================= fused weight transposes (6 segments, 1 launch) =================
struct TPack {
    const float* W[6];
    __half* Wt[6];
    int K[6];
    int N[6];
};

__global__ void __launch_bounds__(256)
transpose_all(TPack p)
{
    const int s = blockIdx.z;
    const int K = p.K[s], N = p.N[s];
    const int n0 = blockIdx.x * 32, k0 = blockIdx.y * 32;
    if (n0 >= N || k0 >= K) return;
    const float* W = p.W[s];
    __half* Wt = p.Wt[s];

    __shared__ float t[32][33];
    const int tx = threadIdx.x & 31, ty = threadIdx.x >> 5;
#pragma unroll
    for (int j = 0; j < 32; j += 8)
        t[ty + j][tx] = W[(long)(k0 + ty + j) * N + n0 + tx];
    __syncthreads();
#pragma unroll
    for (int j = 0; j < 32; j += 8)
        Wt[(long)(n0 + ty + j) * K + k0 + tx] = __float2half_rn(t[tx][ty + j]);
}

// ================= fp16 GEMM (cp.async double-buffered, ldmatrix frags) ========
// C[M,N] = A[M,K] @ Wt[N,K]^T + bias (+GELU); BM=128, BN=128, BK=32; 256 thr.
// A is fp16. M%128==0, K%32==0.
#define GA_LD2 20

template<bool GELU, bool OHALF>
__global__ void __launch_bounds__(256)
gemm_h(const __half* __restrict__ Ah, const __half* __restrict__ Wt,
       const float* __restrict__ bias, void* __restrict__ Cv,
       int M, int N, int K)
{
    __shared__ uint32_t As2[2][128 * GA_LD2];
    __shared__ uint32_t Bs2[2][128 * GA_LD2];

    float*  Cf = (float*)Cv;
    __half* Ch = (__half*)Cv;

    const int tid  = threadIdx.x;
    const int lane = tid & 31;
    const int warp = tid >> 5;
    const int wm = warp >> 2;
    const int wn = warp & 3;
    const int g   = lane >> 2;
    const int tig = lane & 3;
    const int mq  = lane >> 3;
    const int mr  = lane & 7;

    const int m0 = blockIdx.y * 128;
    const int n0 = blockIdx.x * 128;

    float acc[4][4][4];
#pragma unroll
    for (int i = 0; i < 4; i++)
#pragma unroll
        for (int j = 0; j < 4; j++)
#pragma unroll
            for (int r = 0; r < 4; r++) acc[i][j][r] = 0.0f;

    const int arow = tid >> 1, ahalf = tid & 1;
    const __half* Ap = Ah + (long)(m0 + arow) * K + ahalf * 16;
    const __half* Bp = Wt + (long)(n0 + arow) * K + ahalf * 16;

    const uint32_t asb0 = smem_u32(&As2[0][0]);
    const uint32_t bsb0 = smem_u32(&Bs2[0][0]);
    const uint32_t st_a = asb0 + (arow * GA_LD2 + ahalf * 8) * 4;
    const uint32_t st_b = bsb0 + (arow * GA_LD2 + ahalf * 8) * 4;
    const uint32_t a_off = ((wm * 64 + (mq & 1) * 8 + mr) * GA_LD2 + (mq >> 1) * 4) * 4;
    const uint32_t b_off = ((wn * 32 + (mq >> 1) * 8 + mr) * GA_LD2 + (mq & 1) * 4) * 4;
    const uint32_t BUFB = 128 * GA_LD2 * 4;

    // prologue: stage iter 0 into buf 0
    CP16(st_a,      Ap,     true);
    CP16(st_a + 16, Ap + 8, true);
    CP16(st_b,      Bp,     true);
    CP16(st_b + 16, Bp + 8, true);
    CP_COMMIT();

    const int NIT = K >> 5;
    for (int it = 0; it < NIT; it++) {
        const int buf = it & 1;
        CP_WAIT0();
        __syncthreads();

        if (it + 1 < NIT) {
            const int k0 = (it + 1) * 32;
            const uint32_t nb = (buf ^ 1) * BUFB;
            CP16(st_a + nb,      Ap + k0,     true);
            CP16(st_a + nb + 16, Ap + k0 + 8, true);
            CP16(st_b + nb,      Bp + k0,     true);
            CP16(st_b + nb + 16, Bp + k0 + 8, true);
            CP_COMMIT();
        }

        const uint32_t ab = asb0 + buf * BUFB + a_off - asb0;   // keep additive form
        const uint32_t aB = asb0 + buf * BUFB + a_off;
        const uint32_t bB = bsb0 + buf * BUFB + b_off;
        (void)ab;
#pragma unroll
        for (int ks = 0; ks < 2; ks++) {
            uint32_t bf[2][4];
#pragma unroll
            for (int p = 0; p < 2; p++)
                ldsm4(bf[p], bB + (p * 16 * GA_LD2 + ks * 8) * 4);
            uint32_t af[4][4];
#pragma unroll
            for (int mt = 0; mt < 4; mt++)
                ldsm4(af[mt], aB + (mt * 16 * GA_LD2 + ks * 8) * 4);
#pragma unroll
            for (int mt = 0; mt < 4; mt++)
#pragma unroll
                for (int nt = 0; nt < 4; nt++)
                    mma16(acc[mt][nt], af[mt], &bf[nt >> 1][(nt & 1) * 2]);
        }
        __syncthreads();
    }

    const int cb = n0 + wn * 32;
    float2 bv[4];
#pragma unroll
    for (int nt = 0; nt < 4; nt++)
        bv[nt] = *(const float2*)&bias[cb + nt * 8 + 2 * tig];

#pragma unroll
    for (int mt = 0; mt < 4; mt++) {
        const long r1 = m0 + wm * 64 + mt * 16 + g;
        const long r2 = r1 + 8;
#pragma unroll
        for (int nt = 0; nt < 4; nt++) {
            float c0 = acc[mt][nt][0] + bv[nt].x;
            float c1 = acc[mt][nt][1] + bv[nt].y;
            float c2 = acc[mt][nt][2] + bv[nt].x;
            float c3 = acc[mt][nt][3] + bv[nt].y;
            if (GELU) { c0 = gelu_tanh(c0); c1 = gelu_tanh(c1); c2 = gelu_tanh(c2); c3 = gelu_tanh(c3); }
            const long o1 = r1 * N + cb + nt * 8 + 2 * tig;
            const long o2 = r2 * N + cb + nt * 8 + 2 * tig;
            if (OHALF) {
                *(uint32_t*)&Ch[o1] = pack2h(c0, c1);
                *(uint32_t*)&Ch[o2] = pack2h(c2, c3);
            } else {
                *(float2*)&Cf[o1] = make_float2(c0, c1);
                *(float2*)&Cf[o2] = make_float2(c2, c3);
            }
        }
    }
}

// ================= fp16-mma flash attention (cp.async + ldmatrix) ===============
// BM=128 (8 warps), BN=64 keys, d=64. Register softmax; scale folded into Q (exact).
#define FB_LD2 36
#define FQ_OFF 0
#define FK_OFF 4608
#define FV_OFF 9216
#define FBUF   2304
#define FLASH_SMEM ((4608 + 4 * 2304) * 4)   // 55296 B

__global__ void __launch_bounds__(256)
flash_h(const __half* __restrict__ Q, const __half* __restrict__ K,
        const __half* __restrict__ V, __half* __restrict__ O,
        int ldq, long qbs, int ldk, long kbs, int ldv, long vbs,
        int Skv, float scale)
{
    extern __shared__ uint32_t sm[];
    uint32_t* Qs2 = sm + FQ_OFF;

    const int tid  = threadIdx.x;
    const int lane = tid & 31;
    const int warp = tid >> 5;
    const int g    = lane >> 2;
    const int tig  = lane & 3;
    const int mq   = lane >> 3;
    const int mr   = lane & 7;
    const int b = blockIdx.z, h = blockIdx.y;
    const int m0 = blockIdx.x * 128;

    const __half* q = Q + b * qbs + h * D_HEADD;
    const __half* k = K + b * kbs + h * D_HEADD;
    const __half* v = V + b * vbs + h * D_HEADD;

    // ---- stage Q, scaled by exact power-of-two (bit-identical to scaling S) ----
    {
        const __half2 sc2 = __floats2half2_rn(scale, scale);
        const int sr = tid >> 1, hf = tid & 1;
        const __half* qrow = q + (long)(m0 + sr) * ldq + hf * 32;
#pragma unroll
        for (int j = 0; j < 4; j++) {
            uint4 w = *(const uint4*)(qrow + j * 8);
            __half2* hw = (__half2*)&w;
            hw[0] = __hmul2(hw[0], sc2);
            hw[1] = __hmul2(hw[1], sc2);
            hw[2] = __hmul2(hw[2], sc2);
            hw[3] = __hmul2(hw[3], sc2);
            *(uint4*)&Qs2[sr * FB_LD2 + hf * 16 + j * 4] = w;
        }
    }

    const int krow = tid >> 2, qtr = tid & 3;
    const int ntiles = (Skv + 63) >> 6;
    const uint32_t kb0 = smem_u32(sm + FK_OFF);
    const uint32_t vb0 = smem_u32(sm + FV_OFF);

    // ---- prologue: cp.async K(0)+V(0) ----
    {
        const bool val = krow < Skv;
        uint32_t ka = kb0 + (krow * FB_LD2 + qtr * 8) * 4;
        uint32_t va = vb0 + (krow * FB_LD2 + qtr * 8) * 4;
        const __half* kp = k + (long)krow * ldk + qtr * 16;
        const __half* vp = v + (long)krow * ldv + qtr * 16;
        CP16(ka,      kp,     val);
        CP16(ka + 16, kp + 8, val);
        CP16(va,      vp,     val);
        CP16(va + 16, vp + 8, val);
        CP_COMMIT();
    }
    __syncthreads();   // Q visible

    // ---- Q fragments ----
    uint32_t qf[4][4];
    {
        const int row = warp * 16 + g;
#pragma unroll
        for (int ks = 0; ks < 4; ks++) {
            qf[ks][0] = Qs2[row       * FB_LD2 + 8 * ks + tig];
            qf[ks][1] = Qs2[(row + 8) * FB_LD2 + 8 * ks + tig];
            qf[ks][2] = Qs2[row       * FB_LD2 + 8 * ks + tig + 4];
            qf[ks][3] = Qs2[(row + 8) * FB_LD2 + 8 * ks + tig + 4];
        }
    }

    const uint32_t k_off = (((mq >> 1) * 8 + mr) * FB_LD2 + (mq & 1) * 4) * 4;
    const uint32_t v_off = (((mq & 1) * 8 + mr) * FB_LD2 + (mq >> 1) * 4) * 4;

    float o[8][4];
#pragma unroll
    for (int nt = 0; nt < 8; nt++)
#pragma unroll
        for (int r = 0; r < 4; r++) o[nt][r] = 0.0f;
    float m0r = -1e30f, m1r = -1e30f, l0r = 0.0f, l1r = 0.0f;

    for (int t = 0; t < ntiles; t++) {
        const int n0t = t * 64, buf = t & 1;
        const uint32_t kbB = kb0 + buf * (FBUF * 4) + k_off;
        const uint32_t vbB = vb0 + buf * (FBUF * 4) + v_off;

        CP_WAIT0();
        __syncthreads();

        if (t + 1 < ntiles) {
            const int nb = buf ^ 1, nk = (t + 1) * 64 + krow;
            const bool val = nk < Skv;
            uint32_t ka = kb0 + (nb * FBUF + krow * FB_LD2 + qtr * 8) * 4;
            uint32_t va = vb0 + (nb * FBUF + krow * FB_LD2 + qtr * 8) * 4;
            const __half* kp = k + (long)nk * ldk + qtr * 16;
            const __half* vp = v + (long)nk * ldv + qtr * 16;
            CP16(ka,      kp,     val);
            CP16(ka + 16, kp + 8, val);
            CP16(va,      vp,     val);
            CP16(va + 16, vp + 8, val);
            CP_COMMIT();
        }

        // ---- S = Q @ K^T ----
        float sfr[8][4];
#pragma unroll
        for (int nt = 0; nt < 8; nt++)
#pragma unroll
            for (int r = 0; r < 4; r++) sfr[nt][r] = 0.0f;

#pragma unroll
        for (int ks = 0; ks < 4; ks++) {
#pragma unroll
            for (int p = 0; p < 4; p++) {
                uint32_t bf4[4];
                ldsm4(bf4, kbB + (p * 16 * FB_LD2 + ks * 8) * 4);
                mma16(sfr[2 * p],     qf[ks], &bf4[0]);
                mma16(sfr[2 * p + 1], qf[ks], &bf4[2]);
            }
        }

        // tail mask
        if (n0t + 64 > Skv) {
#pragma unroll
            for (int nt = 0; nt < 8; nt++) {
                const int c0 = n0t + nt * 8 + 2 * tig;
                if (c0 >= Skv)     { sfr[nt][0] = -1e30f; sfr[nt][2] = -1e30f; }
                if (c0 + 1 >= Skv) { sfr[nt][1] = -1e30f; sfr[nt][3] = -1e30f; }
            }
        }

        // ---- online softmax ----
        float mx0 = -1e30f, mx1 = -1e30f;
#pragma unroll
        for (int nt = 0; nt < 8; nt++) {
            mx0 = fmaxf(mx0, fmaxf(sfr[nt][0], sfr[nt][1]));
            mx1 = fmaxf(mx1, fmaxf(sfr[nt][2], sfr[nt][3]));
        }
        mx0 = fmaxf(mx0, __shfl_xor_sync(0xffffffffu, mx0, 1));
        mx0 = fmaxf(mx0, __shfl_xor_sync(0xffffffffu, mx0, 2));
        mx1 = fmaxf(mx1, __shfl_xor_sync(0xffffffffu, mx1, 1));
        mx1 = fmaxf(mx1, __shfl_xor_sync(0xffffffffu, mx1, 2));

        const float mn0 = fmaxf(m0r, mx0), mn1 = fmaxf(m1r, mx1);
        const float al0 = __expf(m0r - mn0), al1 = __expf(m1r - mn1);
        m0r = mn0; m1r = mn1;

        float s0 = 0.0f, s1 = 0.0f;
#pragma unroll
        for (int nt = 0; nt < 8; nt++) {
            float p0 = __expf(sfr[nt][0] - mn0);
            float p1 = __expf(sfr[nt][1] - mn0);
            float p2 = __expf(sfr[nt][2] - mn1);
            float p3 = __expf(sfr[nt][3] - mn1);
            sfr[nt][0] = p0; sfr[nt][1] = p1; sfr[nt][2] = p2; sfr[nt][3] = p3;
            s0 += p0 + p1; s1 += p2 + p3;
        }
        s0 += __shfl_xor_sync(0xffffffffu, s0, 1);
        s0 += __shfl_xor_sync(0xffffffffu, s0, 2);
        s1 += __shfl_xor_sync(0xffffffffu, s1, 1);
        s1 += __shfl_xor_sync(0xffffffffu, s1, 2);
        l0r = l0r * al0 + s0;
        l1r = l1r * al1 + s1;

#pragma unroll
        for (int nt = 0; nt < 8; nt++) {
            o[nt][0] *= al0; o[nt][1] *= al0;
            o[nt][2] *= al1; o[nt][3] *= al1;
        }

        // ---- O += P @ V ----
#pragma unroll
        for (int ks = 0; ks < 4; ks++) {
            uint32_t af[4];
            af[0] = pack2h(sfr[2 * ks][0],     sfr[2 * ks][1]);
            af[1] = pack2h(sfr[2 * ks][2],     sfr[2 * ks][3]);
            af[2] = pack2h(sfr[2 * ks + 1][0], sfr[2 * ks + 1][1]);
            af[3] = pack2h(sfr[2 * ks + 1][2], sfr[2 * ks + 1][3]);
#pragma unroll
            for (int p = 0; p < 4; p++) {
                uint32_t bv4[4];
                ldsm4t(bv4, vbB + (ks * 16 * FB_LD2 + p * 8) * 4);
                mma16(o[2 * p],     af, &bv4[0]);
                mma16(o[2 * p + 1], af, &bv4[2]);
            }
        }
    }

    // ---- epilogue ----
    const float i0 = 1.0f / l0r, i1 = 1.0f / l1r;
    const long r1 = (long)b * SEQ + m0 + warp * 16 + g;
    const long r2 = r1 + 8;
#pragma unroll
    for (int nt = 0; nt < 8; nt++) {
        const int col = h * D_HEADD + nt * 8 + 2 * tig;
        *(uint32_t*)&O[r1 * D_EMBED + col] = pack2h(o[nt][0] * i0, o[nt][1] * i0);
        *(uint32_t*)&O[r2 * D_EMBED + col] = pack2h(o[nt][2] * i1, o[nt][3] * i1);
    }
}

// ================= fused kc/vc SGEMM (fp32 SIMT, double-buffered) =================
__global__ void __launch_bounds__(256)
sgemm_kv(const float* __restrict__ Y,
         const float* __restrict__ Wk, const float* __restrict__ bk, __half* __restrict__ Ck,
         const float* __restrict__ Wv, const float* __restrict__ bv, __half* __restrict__ Cv)
{
    const bool isv = blockIdx.x >= 4;
    const float* B    = isv ? Wv : Wk;
    const float* bias = isv ? bv : bk;
    __half* C         = isv ? Cv : Ck;
    const int n0 = (blockIdx.x & 3) * 128;
    const int m0 = blockIdx.y * 128;
    const int M = Y_ROWS, N = 512, K = D_CROSS;

    __shared__ float As[2][8][128];
    __shared__ float Bs[2][8][128];
    const int tid = threadIdx.x;
    const int tx = tid & 15;
    const int ty = tid >> 4;

    float acc[8][8];
#pragma unroll
    for (int i = 0; i < 8; i++)
#pragma unroll
        for (int j = 0; j < 8; j++) acc[i][j] = 0.0f;

    const int a_row = tid >> 1;
    const int a_col = (tid & 1) * 4;
    const int b_row = tid >> 5;
    const int b_col = (tid & 31) * 4;
    const bool a_valid = (m0 + a_row) < M;
    const float* Aptr = Y + (long)(m0 + a_row) * K + a_col;
    const float* Bptr = B + (long)b_row * N + n0 + b_col;

    float4 av = a_valid ? *(const float4*)Aptr : make_float4(0.f, 0.f, 0.f, 0.f);
    float4 bv4 = *(const float4*)Bptr;

    const int NIT = K >> 3;
    for (int it = 0; it < NIT; it++) {
        const int buf = it & 1;
        As[buf][a_col + 0][a_row] = av.x;
        As[buf][a_col + 1][a_row] = av.y;
        As[buf][a_col + 2][a_row] = av.z;
        As[buf][a_col + 3][a_row] = av.w;
        *(float4*)&Bs[buf][b_row][b_col] = bv4;

        if (it + 1 < NIT) {
            const int k0 = (it + 1) * 8;
            av = a_valid ? *(const float4*)(Aptr + k0) : make_float4(0.f, 0.f, 0.f, 0.f);
            bv4 = *(const float4*)(Bptr + (long)k0 * N);
        }
        __syncthreads();

#pragma unroll
        for (int kk = 0; kk < 8; kk++) {
            float ra[8], rb[8];
            *(float4*)&ra[0] = *(const float4*)&As[buf][kk][ty * 8];
            *(float4*)&ra[4] = *(const float4*)&As[buf][kk][ty * 8 + 4];
            *(float4*)&rb[0] = *(const float4*)&Bs[buf][kk][tx * 8];
            *(float4*)&rb[4] = *(const float4*)&Bs[buf][kk][tx * 8 + 4];
#pragma unroll
            for (int i = 0; i < 8; i++)
#pragma unroll
                for (int j = 0; j < 8; j++)
                    acc[i][j] += ra[i] * rb[j];
        }
    }

    float bvv[8];
#pragma unroll
    for (int j = 0; j < 8; j++) bvv[j] = bias[n0 + tx * 8 + j];
#pragma unroll
    for (int i = 0; i < 8; i++) {
        int row = m0 + ty * 8 + i;
        if (row < M) {
            __half* Cp = C + (long)row * N + n0 + tx * 8;
#pragma unroll
            for (int j = 0; j < 4; j++)
                *(uint32_t*)&Cp[2 * j] = pack2h(acc[i][2 * j] + bvv[2 * j],
                                                acc[i][2 * j + 1] + bvv[2 * j + 1]);
        }
    }
}

// ================= fused residual add + LayerNorm (dual fp32/fp16 output) =========
__global__ void __launch_bounds__(128)
add_ln(const float* __restrict__ A, const float* __restrict__ R,
       const float* __restrict__ g, const float* __restrict__ beta,
       float* __restrict__ out, __half* __restrict__ out16)
{
    const long row = blockIdx.x;
    const int tid = threadIdx.x;
    const float4 a = *(const float4*)(A + row * D_EMBED + tid * 4);
    const float4 r = *(const float4*)(R + row * D_EMBED + tid * 4);
    float v[4] = {a.x + r.x, a.y + r.y, a.z + r.z, a.w + r.w};

    float s = v[0] + v[1] + v[2] + v[3];
    float ss = v[0]*v[0] + v[1]*v[1] + v[2]*v[2] + v[3]*v[3];
#pragma unroll
    for (int off = 16; off >= 1; off >>= 1) {
        s  += __shfl_xor_sync(0xffffffffu, s,  off);
        ss += __shfl_xor_sync(0xffffffffu, ss, off);
    }
    __shared__ float sred[8];
    const int warp = tid >> 5, lane = tid & 31;
    if (lane == 0) { sred[warp] = s; sred[warp + 4] = ss; }
    __syncthreads();
    s  = sred[0] + sred[1] + sred[2] + sred[3];
    ss = sred[4] + sred[5] + sred[6] + sred[7];

    const float mean = s * (1.0f / D_EMBED);
    const float var  = ss * (1.0f / D_EMBED) - mean * mean;
    const float rstd = rsqrtf(var + 1e-5f);

    const float4 gg = *(const float4*)(g + tid * 4);
    const float4 bb = *(const float4*)(beta + tid * 4);
    float4 o;
    o.x = (v[0] - mean) * rstd * gg.x + bb.x;
    o.y = (v[1] - mean) * rstd * gg.y + bb.y;
    o.z = (v[2] - mean) * rstd * gg.z + bb.z;
    o.w = (v[3] - mean) * rstd * gg.w + bb.w;
    *(float4*)(out + row * D_EMBED + tid * 4) = o;
    if (out16) {
        uint2 h;
        h.x = pack2h(o.x, o.y);
        h.y = pack2h(o.z, o.w);
        *(uint2*)(out16 + row * D_EMBED + tid * 4) = h;
    }
}

// ================= host =================
extern "C" void kernel_launch(void* const* d_in, const int* in_sizes, int n_in,
                              void* d_out, int out_size)
{
    const float* x        = (const float*)d_in[0];
    const float* y        = (const float*)d_in[1];
    const float* sa_in_w  = (const float*)d_in[2];
    const float* sa_in_b  = (const float*)d_in[3];
    const float* sa_out_w = (const float*)d_in[4];
    const float* sa_out_b = (const float*)d_in[5];
    const float* ca_q_w   = (const float*)d_in[6];
    const float* ca_q_b   = (const float*)d_in[7];
    const float* ca_k_w   = (const float*)d_in[8];
    const float* ca_k_b   = (const float*)d_in[9];
    const float* ca_v_w   = (const float*)d_in[10];
    const float* ca_v_b   = (const float*)d_in[11];
    const float* ca_out_w = (const float*)d_in[12];
    const float* ca_out_b = (const float*)d_in[13];
    const float* ff_w1    = (const float*)d_in[14];
    const float* ff_b1    = (const float*)d_in[15];
    const float* ff_w2    = (const float*)d_in[16];
    const float* ff_b2    = (const float*)d_in[17];
    const float* ln1_g    = (const float*)d_in[18];
    const float* ln1_b    = (const float*)d_in[19];
    const float* ln2_g    = (const float*)d_in[20];
    const float* ln2_b    = (const float*)d_in[21];
    const float* ln3_g    = (const float*)d_in[22];
    const float* ln3_b    = (const float*)d_in[23];
    float* out = (float*)d_out;

    __half *qkvh, *attnh, *qch, *ffh, *kch, *vch, *w16, *xh, *x1h, *x2qh;
    float *proj, *x1, *x2q;
    cudaGetSymbolAddress((void**)&qkvh,  g_qkvh);
    cudaGetSymbolAddress((void**)&attnh, g_attnh);
    cudaGetSymbolAddress((void**)&qch,   g_qch);
    cudaGetSymbolAddress((void**)&ffh,   g_ffh);
    cudaGetSymbolAddress((void**)&kch,   g_kch);
    cudaGetSymbolAddress((void**)&vch,   g_vch);
    cudaGetSymbolAddress((void**)&w16,   g_w16);
    cudaGetSymbolAddress((void**)&xh,    g_xh);
    cudaGetSymbolAddress((void**)&x1h,   g_x1h);
    cudaGetSymbolAddress((void**)&x2qh,  g_x2qh);
    cudaGetSymbolAddress((void**)&proj,  g_proj);
    cudaGetSymbolAddress((void**)&x1,    g_x1);
    cudaGetSymbolAddress((void**)&x2q,   g_x2q);

    cudaFuncSetAttribute(flash_h, cudaFuncAttributeMaxDynamicSharedMemorySize, FLASH_SMEM);

    // 0a. x -> fp16
    f2h<<<(M_ROWS * D_EMBED / 8 + 255) / 256, 256>>>(x, xh, M_ROWS * D_EMBED / 8);
    // 0b. weight transposes (1 launch)
    TPack tp;
    tp.W[0] = sa_in_w;  tp.Wt[0] = w16 + WOFF_SAIN;  tp.K[0] = 512;  tp.N[0] = 1536;
    tp.W[1] = sa_out_w; tp.Wt[1] = w16 + WOFF_SAOUT; tp.K[1] = 512;  tp.N[1] = 512;
    tp.W[2] = ca_q_w;   tp.Wt[2] = w16 + WOFF_CAQ;   tp.K[2] = 512;  tp.N[2] = 512;
    tp.W[3] = ca_out_w; tp.Wt[3] = w16 + WOFF_CAOUT; tp.K[3] = 512;  tp.N[3] = 512;
    tp.W[4] = ff_w1;    tp.Wt[4] = w16 + WOFF_FF1;   tp.K[4] = 512;  tp.N[4] = 2048;
    tp.W[5] = ff_w2;    tp.Wt[5] = w16 + WOFF_FF2;   tp.K[5] = 2048; tp.N[5] = 512;
    transpose_all<<<dim3(64, 64, 6), 256>>>(tp);

    // cross-attn K/V projections
    sgemm_kv<<<dim3(8, 2), 256>>>(y, ca_k_w, ca_k_b, kch, ca_v_w, ca_v_b, vch);

    // 1. QKV projection
    gemm_h<false, true><<<dim3(1536/128, M_ROWS/128), 256>>>(
        xh, w16 + WOFF_SAIN, sa_in_b, qkvh, M_ROWS, 3*D_EMBED, D_EMBED);
    // 2. self-attention
    flash_h<<<dim3(SEQ/128, N_HEADS, BATCH), 256, FLASH_SMEM>>>(
        qkvh, qkvh + D_EMBED, qkvh + 2*D_EMBED, attnh,
        3*D_EMBED, (long)SEQ * 3*D_EMBED,
        3*D_EMBED, (long)SEQ * 3*D_EMBED,
        3*D_EMBED, (long)SEQ * 3*D_EMBED,
        SEQ, 0.125f);
    // 3. self-attn output projection
    gemm_h<false, false><<<dim3(4, M_ROWS/128), 256>>>(
        attnh, w16 + WOFF_SAOUT, sa_out_b, proj, M_ROWS, D_EMBED, D_EMBED);
    // 4. x1 = LN(x + proj)  (+ fp16 copy)
    add_ln<<<M_ROWS, 128>>>(x, proj, ln1_g, ln1_b, x1, x1h);

    // 5. cross-attn Q projection
    gemm_h<false, true><<<dim3(4, M_ROWS/128), 256>>>(
        x1h, w16 + WOFF_CAQ, ca_q_b, qch, M_ROWS, D_EMBED, D_EMBED);
    // 7. cross-attention
    flash_h<<<dim3(SEQ/128, N_HEADS, BATCH), 256, FLASH_SMEM>>>(
        qch, kch, vch, attnh,
        D_EMBED, (long)SEQ * D_EMBED,
        D_EMBED, (long)SKV_C * D_EMBED,
        D_EMBED, (long)SKV_C * D_EMBED,
        SKV_C, 0.125f);
    // 8. cross-attn output projection
    gemm_h<false, false><<<dim3(4, M_ROWS/128), 256>>>(
        attnh, w16 + WOFF_CAOUT, ca_out_b, proj, M_ROWS, D_EMBED, D_EMBED);
    // 9. x2 = LN(x1 + proj)  (+ fp16 copy)
    add_ln<<<M_ROWS, 128>>>(x1, proj, ln2_g, ln2_b, x2q, x2qh);

    // 10. FF1 + GELU
    gemm_h<true, true><<<dim3(FF_DIM/128, M_ROWS/128), 256>>>(
        x2qh, w16 + WOFF_FF1, ff_b1, ffh, M_ROWS, FF_DIM, D_EMBED);
    // 11. FF2
    gemm_h<false, false><<<dim3(4, M_ROWS/128), 256>>>(
        ffh, w16 + WOFF_FF2, ff_b2, proj, M_ROWS, D_EMBED, FF_DIM);
    // 12. out = LN(x2 + proj)
    add_ln<<<M_ROWS, 128>>>(x2q, proj, ln3_g, ln3_b, out, (__half*)0);
}